// round 9
// baseline (speedup 1.0000x reference)
#include <cuda_runtime.h>
#include <cuda_bf16.h>
#include <cstdint>

// ---------------- problem constants ----------------
#define BB 2
#define LL 2048
#define NK 64
#define DM 512
#define DI 1024
#define NH 8
#define PP 128
#define NZ 2058
#define CC 1026
#define BLT (BB*LL)

typedef unsigned long long ull;

// ---------------- scratch ----------------
__device__ float g_zx   [(size_t)BB*LL*NZ];
__device__ float g_convf[(size_t)BB*LL*CC];
__device__ float g_convb[(size_t)BB*LL*CC];
__device__ float g_dA   [(size_t)BB*NH*LL*NK];
__device__ float g_uf   [(size_t)BB*NH*LL*NK];
__device__ float g_ub   [(size_t)BB*NH*LL*NK];
__device__ float g_Cf   [(size_t)BB*LL*NK];
__device__ float g_Cb2  [(size_t)BB*LL*NK];
__device__ float g_h0   [(size_t)BB*NK*DI];
__device__ float g_yf   [(size_t)BB*LL*DI];
__device__ float g_yb   [(size_t)BB*LL*DI];
__device__ float g_hf   [(size_t)BB*NH*PP*NK];
__device__ float g_hb   [(size_t)BB*NH*PP*NK];
__device__ float g_xg   [(size_t)BB*LL*DI];
__device__ float g_qn   [(size_t)BB*NK*DI];
// tf32-rounded copies of GEMM inputs
__device__ float g_rA1 [(size_t)BLT*DM];
__device__ float g_rW1 [(size_t)NZ*DM];
__device__ float g_rWo [(size_t)DM*DI];
__device__ float g_rWoq[(size_t)DM*DI];

// ---------------- helpers ----------------
__device__ __forceinline__ unsigned smem_u32(const void* p) {
    return (unsigned)__cvta_generic_to_shared(p);
}
__device__ __forceinline__ void cpasync16(unsigned s, const void* g) {
    asm volatile("cp.async.cg.shared.global [%0],[%1],16;\n" ::"r"(s), "l"(g));
}
__device__ __forceinline__ void cpasync16z(unsigned s, const void* g, unsigned srcsz) {
    asm volatile("cp.async.cg.shared.global [%0],[%1],16,%2;\n" ::"r"(s), "l"(g), "r"(srcsz));
}
__device__ __forceinline__ void cpasync8(unsigned s, const void* g) {
    asm volatile("cp.async.ca.shared.global [%0],[%1],8;\n" ::"r"(s), "l"(g));
}
__device__ __forceinline__ float to_tf32(float x) {
    float r; asm("cvt.rna.tf32.f32 %0,%1;" : "=f"(r) : "f"(x)); return r;
}
__device__ __forceinline__ void mma_tf32(float* c, const uint32_t* a, uint32_t b0, uint32_t b1) {
    asm volatile(
        "mma.sync.aligned.m16n8k8.row.col.f32.tf32.tf32.f32 "
        "{%0,%1,%2,%3}, {%4,%5,%6,%7}, {%8,%9}, {%0,%1,%2,%3};"
        : "+f"(c[0]), "+f"(c[1]), "+f"(c[2]), "+f"(c[3])
        : "r"(a[0]), "r"(a[1]), "r"(a[2]), "r"(a[3]), "r"(b0), "r"(b1));
}
// packed f32x2 (Blackwell, sm_100+)
__device__ __forceinline__ ull mul2(ull a, ull b) {
    ull d; asm("mul.rn.f32x2 %0,%1,%2;" : "=l"(d) : "l"(a), "l"(b)); return d;
}
__device__ __forceinline__ ull fma2(ull a, ull b, ull c) {
    ull d; asm("fma.rn.f32x2 %0,%1,%2,%3;" : "=l"(d) : "l"(a), "l"(b), "l"(c)); return d;
}
__device__ __forceinline__ ull pack2(float x, float y) {
    ull d; asm("mov.b64 %0,{%1,%2};" : "=l"(d) : "f"(x), "f"(y)); return d;
}
__device__ __forceinline__ void unpack2(ull v, float& x, float& y) {
    asm("mov.b64 {%0,%1},%2;" : "=f"(x), "=f"(y) : "l"(v));
}

// ---------------- #1: preround A1/W1/Wo/Woq + zero outq ----------------
__global__ __launch_bounds__(256) void prep_kernel(
    const float* __restrict__ a1, const float* __restrict__ w1,
    const float* __restrict__ wo, const float* __restrict__ woq,
    float* __restrict__ outq)
{
    const size_t n1 = (size_t)BLT * DM / 4;
    const size_t n2 = n1 + (size_t)NZ * DM / 4;
    const size_t n3 = n2 + (size_t)DM * DI / 4;
    const size_t n4 = n3 + (size_t)DM * DI / 4;
    const size_t n5 = n4 + (size_t)BB * NK * DM / 4;
    size_t i = (size_t)blockIdx.x * 256 + threadIdx.x;
    if (i >= n5) return;
    if (i >= n4) {
        ((float4*)outq)[i - n4] = make_float4(0.f, 0.f, 0.f, 0.f);
        return;
    }
    const float* src; float* dst; size_t off;
    if      (i < n1) { src = a1;  dst = g_rA1;  off = i; }
    else if (i < n2) { src = w1;  dst = g_rW1;  off = i - n1; }
    else if (i < n3) { src = wo;  dst = g_rWo;  off = i - n2; }
    else             { src = woq; dst = g_rWoq; off = i - n3; }
    float4 v = ((const float4*)src)[off];
    v.x = to_tf32(v.x); v.y = to_tf32(v.y); v.z = to_tf32(v.z); v.w = to_tf32(v.w);
    ((float4*)dst)[off] = v;
}

// ---------------- tensor-core tf32 GEMM: 4 warps, 64x64 warp tile, 3-stage ----------------
#define KC 16
#define PADK 20
#define STAGE_B (128*PADK*4)           // 10240 B
#define CHUNK_B (2*STAGE_B)            // 20480 B
#define DSMEM_G (3*CHUNK_B)            // 61440 B

__global__ __launch_bounds__(128, 2) void gemm_mma(const float* __restrict__ A,
                                                   const float* __restrict__ W,
                                                   float* __restrict__ C,
                                                   int M, int N, int K)
{
    extern __shared__ __align__(16) char dsm[];
    const int tid = threadIdx.x;
    const int lid = tid & 31, wrp = tid >> 5;
    const int wm = wrp & 1, wn = wrp >> 1;
    const int gid = lid >> 2, tig = lid & 3;
    const int m0 = blockIdx.y * 128, n0 = blockIdx.x * 128;
    const unsigned sbase = smem_u32(dsm);

    const int totCh = K >> 4;
    const int per = totCh / gridDim.z;
    const int cbase = blockIdx.z * per;
    const bool split = gridDim.z > 1;

    auto load_chunk = [&](int st, int ch) {
        const float* Ap = A + (size_t)m0 * K + ch * KC;
        const float* Wp = W + (size_t)n0 * K + ch * KC;
        unsigned ao = (unsigned)st * CHUNK_B;
        unsigned bo = ao + STAGE_B;
#pragma unroll
        for (int i = 0; i < 4; i++) {
            int idx = tid + i * 128;
            int row = idx >> 2, kg = idx & 3;
            unsigned so = (unsigned)(row * PADK * 4 + kg * 16);
            cpasync16(sbase + ao + so, Ap + (size_t)row * K + kg * 4);
            int nrow = n0 + row;
            int cl = (nrow < N) ? nrow : (N - 1);
            cpasync16z(sbase + bo + so, Wp + (size_t)(cl - n0) * K + kg * 4,
                       (nrow < N) ? 16u : 0u);
        }
        asm volatile("cp.async.commit_group;\n" ::: "memory");
    };

    float acc[4][8][4];
#pragma unroll
    for (int mf = 0; mf < 4; mf++)
#pragma unroll
        for (int nf = 0; nf < 8; nf++)
#pragma unroll
            for (int i = 0; i < 4; i++) acc[mf][nf][i] = 0.f;

    load_chunk(0, cbase);
    if (per > 1) load_chunk(1, cbase + 1);

    int st = 0;
    for (int c = 0; c < per; c++) {
        if (c + 1 < per) asm volatile("cp.async.wait_group 1;\n" ::: "memory");
        else             asm volatile("cp.async.wait_group 0;\n" ::: "memory");
        __syncthreads();
        if (c + 2 < per) {
            int st2 = st + 2; if (st2 >= 3) st2 -= 3;
            load_chunk(st2, cbase + c + 2);
        }
        const float* as = (const float*)(dsm + st * CHUNK_B);
        const float* bs = (const float*)(dsm + st * CHUNK_B + STAGE_B);
#pragma unroll
        for (int ks = 0; ks < 2; ks++) {
            int k0 = ks * 8;
            uint32_t af[4][4];
#pragma unroll
            for (int mf = 0; mf < 4; mf++) {
                int r = wm * 64 + mf * 16 + gid;
                af[mf][0] = __float_as_uint(as[r * PADK + k0 + tig]);
                af[mf][1] = __float_as_uint(as[(r + 8) * PADK + k0 + tig]);
                af[mf][2] = __float_as_uint(as[r * PADK + k0 + tig + 4]);
                af[mf][3] = __float_as_uint(as[(r + 8) * PADK + k0 + tig + 4]);
            }
#pragma unroll
            for (int nf = 0; nf < 8; nf++) {
                int nr = wn * 64 + nf * 8 + gid;
                uint32_t b0 = __float_as_uint(bs[nr * PADK + k0 + tig]);
                uint32_t b1 = __float_as_uint(bs[nr * PADK + k0 + tig + 4]);
#pragma unroll
                for (int mf = 0; mf < 4; mf++)
                    mma_tf32(acc[mf][nf], af[mf], b0, b1);
            }
        }
        if (++st >= 3) st = 0;
    }

#pragma unroll
    for (int mf = 0; mf < 4; mf++) {
        int r0 = m0 + wm * 64 + mf * 16 + gid;
#pragma unroll
        for (int nf = 0; nf < 8; nf++) {
            int col = n0 + wn * 64 + nf * 8 + tig * 2;
            if (col < N) {
                float* p0 = &C[(size_t)r0 * N + col];
                float* p1 = &C[(size_t)(r0 + 8) * N + col];
                if (!split) {
                    *(float2*)p0 = make_float2(acc[mf][nf][0], acc[mf][nf][1]);
                    *(float2*)p1 = make_float2(acc[mf][nf][2], acc[mf][nf][3]);
                } else {
                    atomicAdd(p0,     acc[mf][nf][0]);
                    atomicAdd(p0 + 1, acc[mf][nf][1]);
                    atomicAdd(p1,     acc[mf][nf][2]);
                    atomicAdd(p1 + 1, acc[mf][nf][3]);
                }
            }
        }
    }
}

// ---------------- #3: megaprep = h0 SIMT gemm + conv + dtbc in one launch ----------------
#define MEGA_H0   16
#define MEGA_CONV 1026
#define MEGA_DTBC 256

__global__ __launch_bounds__(1024) void megaprep_kernel(
    const float* __restrict__ in_query, const float* __restrict__ wq,
    const float* __restrict__ cw_f, const float* __restrict__ cb_f,
    const float* __restrict__ cw_b, const float* __restrict__ cb_b,
    const float* __restrict__ dist, const float* __restrict__ bcw,
    const float* __restrict__ dtw, const float* __restrict__ dt_bias,
    const float* __restrict__ A_log)
{
    __shared__ float sA[128 * 33];
    __shared__ float sW[32 * 66];
    int bid = blockIdx.x;
    int tid = threadIdx.x;

    if (bid < MEGA_H0) {
        // ---- h0 = in_query @ wq^T, fp32 SIMT, tile 128m x 64n ----
        int n0 = bid * 64;
        int tx = tid & 31, ty = tid >> 5;
        float acc[4][2];
#pragma unroll
        for (int i = 0; i < 4; i++) { acc[i][0] = 0.f; acc[i][1] = 0.f; }
        for (int k0 = 0; k0 < DM; k0 += 32) {
#pragma unroll
            for (int i = 0; i < 4; i++) {
                int e = tid + i * 1024;
                int m = e >> 5, kk = e & 31;
                sA[m * 33 + kk] = in_query[(size_t)m * DM + k0 + kk];
            }
#pragma unroll
            for (int i = 0; i < 2; i++) {
                int e = tid + i * 1024;
                int kk = e >> 6, n = e & 63;
                sW[kk * 66 + n] = wq[(size_t)(n0 + n) * DM + k0 + kk];
            }
            __syncthreads();
#pragma unroll 8
            for (int kk = 0; kk < 32; kk++) {
                float2 w2 = *(const float2*)&sW[kk * 66 + tx * 2];
#pragma unroll
                for (int i = 0; i < 4; i++) {
                    float a = sA[(ty * 4 + i) * 33 + kk];
                    acc[i][0] = fmaf(a, w2.x, acc[i][0]);
                    acc[i][1] = fmaf(a, w2.y, acc[i][1]);
                }
            }
            __syncthreads();
        }
#pragma unroll
        for (int i = 0; i < 4; i++)
            *(float2*)&g_h0[(size_t)(ty * 4 + i) * DI + n0 + tx * 2] =
                make_float2(acc[i][0], acc[i][1]);
        return;
    }

    if (bid < MEGA_H0 + MEGA_CONV) {
        // ---- depthwise conv7 + silu, sliding window (8 l per thread) ----
        size_t e = (size_t)(bid - MEGA_H0) * 1024 + tid;
        const size_t totc = (size_t)CC * 256 * 4;
        if (e >= totc) return;
        int c = (int)(e % CC);
        int r = (int)(e / CC);
        int l0 = (r & 255) * 8;
        int db = r >> 8;
        int dir = db >> 1, b = db & 1;

        const float* wsrc = (dir ? cw_b : cw_f) + c * 7;
        float wr[7];
#pragma unroll
        for (int t = 0; t < 7; t++) wr[t] = wsrc[t];
        float bias = (dir ? cb_b : cb_f)[c];

        const float* src = g_zx + (size_t)b * LL * NZ + DI + c;
        float win[14];
#pragma unroll
        for (int i = 0; i < 14; i++) {
            int l = l0 - 3 + i;
            win[i] = (0 <= l && l < LL) ? src[(size_t)l * NZ] : 0.f;
        }
        float* dst = (dir ? g_convb : g_convf) + ((size_t)b * LL + l0) * CC + c;
#pragma unroll
        for (int j = 0; j < 8; j++) {
            float acc = bias;
#pragma unroll
            for (int t = 0; t < 7; t++) acc = fmaf(wr[t], win[j + t], acc);
            float sig = 1.f / (1.f + __expf(-acc));
            dst[(size_t)j * CC] = acc * sig;
        }
        return;
    }

    {
        // ---- dtbc: dt, dA, u_f/u_b, C_f/C_b (computes own bias-channel convs) ----
        int local = bid - (MEGA_H0 + MEGA_CONV);
        int bl = local * 16 + (tid >> 6);
        int b = bl / LL, l = bl % LL;
        int k = tid & 63;

        // inline 7-tap conv for channels 1024/1025, both directions
        float resf[2], resb[2];
        const float* zsrc = g_zx + (size_t)b * LL * NZ + 2 * DI;
#pragma unroll
        for (int ch = 0; ch < 2; ch++) {
            float af = cb_f[1024 + ch], ab = cb_b[1024 + ch];
#pragma unroll
            for (int t = 0; t < 7; t++) {
                int l2 = l + t - 3;
                if (0 <= l2 && l2 < LL) {
                    float v = zsrc[(size_t)l2 * NZ + ch];
                    af = fmaf(cw_f[(1024 + ch) * 7 + t], v, af);
                    ab = fmaf(cw_b[(1024 + ch) * 7 + t], v, ab);
                }
            }
            resf[ch] = af * (1.f / (1.f + __expf(-af)));
            resb[ch] = ab * (1.f / (1.f + __expf(-ab)));
        }
        float bbf = resf[0], cbfv = resf[1], bbb = resb[0], cbbv = resb[1];

        float4 d4 = *(const float4*)&dist[((size_t)bl * NK + k) * 4];
        float bb = d4.x * bcw[0] + d4.y * bcw[1] + d4.z * bcw[2] + d4.w * bcw[3];
        float cb = d4.x * bcw[4] + d4.y * bcw[5] + d4.z * bcw[6] + d4.w * bcw[7];
        g_Cf [(size_t)bl * NK + k] = cb + cbfv;
        g_Cb2[(size_t)bl * NK + k] = cb + cbbv;
        float Bf = bb + bbf, Bbk = bb + bbb;
        size_t zoff = (size_t)bl * NZ + 2 * DI + 2;
#pragma unroll
        for (int h = 0; h < NH; h++) {
            float pre = d4.x * dtw[h * 4 + 0] + d4.y * dtw[h * 4 + 1]
                      + d4.z * dtw[h * 4 + 2] + d4.w * dtw[h * 4 + 3]
                      + g_zx[zoff + h] + dt_bias[h];
            float dt = (pre > 20.f) ? pre : log1pf(__expf(pre));
            float Ah = -__expf(A_log[h]);
            float dA = __expf(dt * Ah);
            size_t o = (((size_t)(b * NH + h) * LL) + l) * NK + k;
            g_dA[o] = dA;
            g_uf[o] = dt * Bf;
            g_ub[o] = dt * Bbk;
        }
    }
}

// ---------------- #4 (profiled): scan, 256 threads, 2 p per thread, f32x2 ----------------
#define SCAN_T 16
#define SC_DA 0
#define SC_U  2048
#define SC_C  4096
#define SC_X  6144
#define SC_Y  7168
#define DSMEM_S ((7168 + 8192) * 4)     // 61440 B

__global__ __launch_bounds__(256) void scan_kernel()
{
    extern __shared__ __align__(16) float sm[];
    int bid = blockIdx.x;
    int ps  = bid & 3;
    int bh  = (bid >> 2) & 15;
    int dir = bid >> 6;
    int b = bh >> 3, h = bh & 7;
    int tid = threadIdx.x;
    int q = tid & 15, pl = tid >> 4;
    int p0 = ps * 32 + pl * 2;

    const float* gdA = g_dA + (size_t)bh * LL * NK;
    const float* gu  = (dir ? g_ub : g_uf) + (size_t)bh * LL * NK;
    const float* gC  = (dir ? g_Cb2 : g_Cf) + (size_t)b * LL * NK;
    const float* gx  = (dir ? g_convb : g_convf) + (size_t)b * LL * CC + h * PP + ps * 32;
    float* gyr = (dir ? g_yb : g_yf) + (size_t)b * LL * DI + h * PP + ps * 32;

    ull hA01, hA23, hB01, hB23;
    {
        const float* hp = g_h0 + (size_t)b * NK * DI + h * PP;
        hA01 = pack2(hp[(size_t)(4 * q + 0) * DI + p0], hp[(size_t)(4 * q + 1) * DI + p0]);
        hA23 = pack2(hp[(size_t)(4 * q + 2) * DI + p0], hp[(size_t)(4 * q + 3) * DI + p0]);
        hB01 = pack2(hp[(size_t)(4 * q + 0) * DI + p0 + 1], hp[(size_t)(4 * q + 1) * DI + p0 + 1]);
        hB23 = pack2(hp[(size_t)(4 * q + 2) * DI + p0 + 1], hp[(size_t)(4 * q + 3) * DI + p0 + 1]);
    }

    const int NC = LL / SCAN_T;

    auto load_chunk = [&](int buf, int c) {
        size_t t0 = (size_t)c * SCAN_T;
        cpasync16(smem_u32(&sm[SC_DA + buf * 1024 + tid * 4]), gdA + t0 * NK + tid * 4);
        cpasync16(smem_u32(&sm[SC_U  + buf * 1024 + tid * 4]), gu  + t0 * NK + tid * 4);
        cpasync16(smem_u32(&sm[SC_C  + buf * 1024 + tid * 4]), gC  + t0 * NK + tid * 4);
        int tl = tid >> 4, px = (tid & 15) * 2;
        cpasync8(smem_u32(&sm[SC_X + buf * 512 + tl * 32 + px]), gx + (t0 + tl) * CC + px);
        asm volatile("cp.async.commit_group;\n");
    };

    load_chunk(0, dir ? NC - 1 : 0);
    for (int cc = 0; cc < NC; cc++) {
        int cnext = cc + 1;
        if (cnext < NC) {
            load_chunk(cnext & 1, dir ? NC - 1 - cnext : cnext);
            asm volatile("cp.async.wait_group 1;\n");
        } else {
            asm volatile("cp.async.wait_group 0;\n");
        }
        __syncthreads();
        int buf = cc & 1;
        int c = dir ? NC - 1 - cc : cc;
#pragma unroll 4
        for (int j = 0; j < SCAN_T; j++) {
            int tt = dir ? (SCAN_T - 1 - j) : j;
            ulonglong2 a2 = *(const ulonglong2*)&sm[SC_DA + buf * 1024 + tt * 64 + 4 * q];
            ulonglong2 u2 = *(const ulonglong2*)&sm[SC_U  + buf * 1024 + tt * 64 + 4 * q];
            ulonglong2 c2 = *(const ulonglong2*)&sm[SC_C  + buf * 1024 + tt * 64 + 4 * q];
            float2 xv = *(const float2*)&sm[SC_X + buf * 512 + tt * 32 + pl * 2];
            ull xA = pack2(xv.x, xv.x);
            ull xB = pack2(xv.y, xv.y);
            hA01 = fma2(a2.x, hA01, mul2(u2.x, xA));
            hA23 = fma2(a2.y, hA23, mul2(u2.y, xA));
            hB01 = fma2(a2.x, hB01, mul2(u2.x, xB));
            hB23 = fma2(a2.y, hB23, mul2(u2.y, xB));
            ull accA = fma2(c2.y, hA23, mul2(c2.x, hA01));
            ull accB = fma2(c2.y, hB23, mul2(c2.x, hB01));
            float la, ha, lb, hb2;
            unpack2(accA, la, ha);
            unpack2(accB, lb, hb2);
            sm[SC_Y + tt * 512 + (pl * 2 + 0) * 16 + q] = la + ha;
            sm[SC_Y + tt * 512 + (pl * 2 + 1) * 16 + q] = lb + hb2;
        }
        __syncthreads();
#pragma unroll
        for (int r = 0; r < 2; r++) {
            int cell = tid * 2 + r;
            int t_loc = cell >> 5, pr = cell & 31;
            const float4* src = (const float4*)&sm[SC_Y + t_loc * 512 + pr * 16];
            float4 v0 = src[0], v1 = src[1], v2 = src[2], v3 = src[3];
            float s = ((v0.x + v0.y) + (v0.z + v0.w)) + ((v1.x + v1.y) + (v1.z + v1.w))
                    + ((v2.x + v2.y) + (v2.z + v2.w)) + ((v3.x + v3.y) + (v3.z + v3.w));
            int gt = c * SCAN_T + t_loc;
            gyr[(size_t)gt * DI + pr] = s;
        }
    }
    float f0, f1, f2, f3;
    float* gh = (dir ? g_hb : g_hf) + ((size_t)(b * NH + h) * PP + p0) * NK + 4 * q;
    unpack2(hA01, f0, f1); unpack2(hA23, f2, f3);
    gh[0] = f0; gh[1] = f1; gh[2] = f2; gh[3] = f3;
    unpack2(hB01, f0, f1); unpack2(hB23, f2, f3);
    gh[NK + 0] = f0; gh[NK + 1] = f1; gh[NK + 2] = f2; gh[NK + 3] = f3;
}

// ---------------- combine y, gate with silu(z), RMSNorm (tf32 out) ----------------
__global__ __launch_bounds__(256) void gate_norm_key_kernel(const float* __restrict__ Dp,
                                                            const float* __restrict__ normw)
{
    int bl = blockIdx.x;
    int tid = threadIdx.x;
    __shared__ float s_v[DI];
    __shared__ float sred[9];
    float ss = 0.f;
    size_t byDI = (size_t)bl * DI, byCC = (size_t)bl * CC, byNZ = (size_t)bl * NZ;
#pragma unroll
    for (int it = 0; it < 4; it++) {
        int i = tid + it * 256;
        int hh = i >> 7;
        float y = 0.5f * (g_yf[byDI + i] + g_yb[byDI + i])
                + 0.5f * Dp[hh] * (g_convf[byCC + i] + g_convb[byCC + i]);
        float z = g_zx[byNZ + i];
        float xg = y * z * (1.f / (1.f + __expf(-z)));
        s_v[i] = xg;
        ss += xg * xg;
    }
    for (int o = 16; o; o >>= 1) ss += __shfl_xor_sync(0xffffffffu, ss, o);
    if ((tid & 31) == 0) sred[tid >> 5] = ss;
    __syncthreads();
    if (tid == 0) {
        float t = 0.f;
        for (int w = 0; w < 8; w++) t += sred[w];
        sred[8] = rsqrtf(t * (1.f / DI) + 1e-5f);
    }
    __syncthreads();
    float sc = sred[8];
#pragma unroll
    for (int it = 0; it < 4; it++) {
        int i = tid + it * 256;
        g_xg[byDI + i] = to_tf32(s_v[i] * sc * normw[i]);
    }
}

// ---------------- query path: average final states, LayerNorm (tf32 out) ----------------
__global__ __launch_bounds__(256) void qnorm_kernel(const float* __restrict__ w,
                                                    const float* __restrict__ bi)
{
    int bk = blockIdx.x;
    int b = bk >> 6, k = bk & 63;
    int tid = threadIdx.x;
    __shared__ float s_v[DI];
    __shared__ float sred[18];
    float s1 = 0.f, s2 = 0.f;
#pragma unroll
    for (int it = 0; it < 4; it++) {
        int i = tid + it * 256;
        int hh = i >> 7, p = i & 127;
        size_t o = ((size_t)(b * NH + hh) * PP + p) * NK + k;
        float qv = 0.5f * (g_hf[o] + g_hb[o]);
        s_v[i] = qv;
        s1 += qv;
        s2 += qv * qv;
    }
    for (int o = 16; o; o >>= 1) {
        s1 += __shfl_xor_sync(0xffffffffu, s1, o);
        s2 += __shfl_xor_sync(0xffffffffu, s2, o);
    }
    if ((tid & 31) == 0) { sred[tid >> 5] = s1; sred[8 + (tid >> 5)] = s2; }
    __syncthreads();
    if (tid == 0) {
        float t1 = 0.f, t2 = 0.f;
        for (int wv = 0; wv < 8; wv++) { t1 += sred[wv]; t2 += sred[8 + wv]; }
        float mu = t1 * (1.f / DI);
        float var = t2 * (1.f / DI) - mu * mu;
        sred[16] = mu;
        sred[17] = rsqrtf(var + 1e-5f);
    }
    __syncthreads();
    float mu = sred[16], rs = sred[17];
#pragma unroll
    for (int it = 0; it < 4; it++) {
        int i = tid + it * 256;
        g_qn[(size_t)bk * DI + i] = to_tf32((s_v[i] - mu) * rs * w[i] + bi[i]);
    }
}

// ---------------- host launcher ----------------
extern "C" void kernel_launch(void* const* d_in, const int* in_sizes, int n_in,
                              void* d_out, int out_size)
{
    (void)in_sizes; (void)n_in; (void)out_size;
    const float* in_key      = (const float*)d_in[0];
    const float* in_query    = (const float*)d_in[1];
    const float* dist        = (const float*)d_in[2];
    const float* key_proj_w  = (const float*)d_in[4];
    const float* key_conv_w  = (const float*)d_in[5];
    const float* key_conv_b  = (const float*)d_in[6];
    const float* key_conv_bw = (const float*)d_in[7];
    const float* key_conv_bb = (const float*)d_in[8];
    const float* query_proj_w= (const float*)d_in[9];
    const float* bc_proj_w   = (const float*)d_in[10];
    const float* dt_proj_w   = (const float*)d_in[11];
    const float* dt_bias     = (const float*)d_in[12];
    const float* A_log       = (const float*)d_in[13];
    const float* D_param     = (const float*)d_in[14];
    const float* out_key_w   = (const float*)d_in[15];
    const float* out_query_w = (const float*)d_in[16];
    const float* key_norm_w  = (const float*)d_in[17];
    const float* q_ln_w     = (const float*)d_in[18];
    const float* q_ln_b     = (const float*)d_in[19];
    float* out = (float*)d_out;

    void *p_zx, *p_xg, *p_qn, *p_rA1, *p_rW1, *p_rWo, *p_rWoq;
    cudaGetSymbolAddress(&p_zx, g_zx);
    cudaGetSymbolAddress(&p_xg, g_xg);
    cudaGetSymbolAddress(&p_qn, g_qn);
    cudaGetSymbolAddress(&p_rA1, g_rA1);
    cudaGetSymbolAddress(&p_rW1, g_rW1);
    cudaGetSymbolAddress(&p_rWo, g_rWo);
    cudaGetSymbolAddress(&p_rWoq, g_rWoq);

    cudaFuncSetAttribute(gemm_mma, cudaFuncAttributeMaxDynamicSharedMemorySize, DSMEM_G);
    cudaFuncSetAttribute(scan_kernel, cudaFuncAttributeMaxDynamicSharedMemorySize, DSMEM_S);

    // #1: preround + zero outq
    {
        size_t n = ((size_t)BLT * DM + (size_t)NZ * DM + 2ull * DM * DI
                    + (size_t)BB * NK * DM) / 4;
        prep_kernel<<<(int)((n + 255) / 256), 256>>>(in_key, key_proj_w, out_key_w,
                                                     out_query_w, out + (size_t)BLT * DM);
    }
    // #2: zxbcdt = in_key @ key_proj_w^T
    {
        dim3 grid((NZ + 127) / 128, BLT / 128, 1);
        gemm_mma<<<grid, 128, DSMEM_G>>>((const float*)p_rA1, (const float*)p_rW1,
                                         (float*)p_zx, BLT, NZ, DM);
    }
    // #3: megaprep — h0 SIMT + conv + dtbc
    megaprep_kernel<<<MEGA_H0 + MEGA_CONV + MEGA_DTBC, 1024>>>(
        in_query, query_proj_w,
        key_conv_w, key_conv_b, key_conv_bw, key_conv_bb,
        dist, bc_proj_w, dt_proj_w, dt_bias, A_log);
    // #4 (ncu captures this): scans
    scan_kernel<<<128, 256, DSMEM_S>>>();
    // #5: combine + gate + RMSNorm
    gate_norm_key_kernel<<<BLT, 256>>>(D_param, key_norm_w);
    // #6: out_key = key_n @ out_key_w^T
    {
        dim3 grid(DM / 128, BLT / 128, 1);
        gemm_mma<<<grid, 128, DSMEM_G>>>((const float*)p_xg, (const float*)p_rWo,
                                         out, BLT, DM, DI);
    }
    // #7: query layer norm
    qnorm_kernel<<<BB * NK, 256>>>(q_ln_w, q_ln_b);
    // #8: out_query = qn @ out_query_w^T, split-K x8
    {
        dim3 grid(DM / 128, 1, 8);
        gemm_mma<<<grid, 128, DSMEM_G>>>((const float*)p_qn, (const float*)p_rWoq,
                                         out + (size_t)BLT * DM, BB * NK, DM, DI);
    }
}

// round 10
// speedup vs baseline: 1.0148x; 1.0148x over previous
#include <cuda_runtime.h>
#include <cuda_bf16.h>
#include <cstdint>

// ---------------- problem constants ----------------
#define BB 2
#define LL 2048
#define NK 64
#define DM 512
#define DI 1024
#define NH 8
#define PP 128
#define NZ 2058
#define CC 1026
#define BLT (BB*LL)
#define NCH 16          // chunks over L
#define CHL 128         // chunk length

typedef unsigned long long ull;

// ---------------- scratch ----------------
__device__ float g_zx   [(size_t)BB*LL*NZ];
__device__ float g_convf[(size_t)BB*LL*CC];
__device__ float g_convb[(size_t)BB*LL*CC];
__device__ float g_dA   [(size_t)BB*NH*LL*NK];
__device__ float g_uf   [(size_t)BB*NH*LL*NK];
__device__ float g_ub   [(size_t)BB*NH*LL*NK];
__device__ float g_Cf   [(size_t)BB*LL*NK];
__device__ float g_Cb2  [(size_t)BB*LL*NK];
__device__ float g_h0   [(size_t)BB*NK*DI];
__device__ float g_yf   [(size_t)BB*LL*DI];
__device__ float g_yb   [(size_t)BB*LL*DI];
__device__ float g_hf   [(size_t)BB*NH*PP*NK];
__device__ float g_hb   [(size_t)BB*NH*PP*NK];
__device__ float g_xg   [(size_t)BB*LL*DI];
__device__ float g_qn   [(size_t)BB*NK*DI];
// chunked-scan intermediates
__device__ float g_Sf  [(size_t)16*NCH*PP*NK];   // [bh][chunk][p][n]
__device__ float g_Sb  [(size_t)16*NCH*PP*NK];
__device__ float g_P   [(size_t)16*NCH*NK];      // [bh][chunk][n]
__device__ float g_hsf [(size_t)16*NCH*PP*NK];   // entry state per chunk (fwd)
__device__ float g_hsb [(size_t)16*NCH*PP*NK];   // entry state per chunk (bwd)
// tf32-rounded copies of GEMM inputs
__device__ float g_rA1 [(size_t)BLT*DM];
__device__ float g_rW1 [(size_t)NZ*DM];
__device__ float g_rQ  [(size_t)BB*NK*DM];
__device__ float g_rWq [(size_t)DI*DM];
__device__ float g_rWo [(size_t)DM*DI];
__device__ float g_rWoq[(size_t)DM*DI];

// ---------------- helpers ----------------
__device__ __forceinline__ unsigned smem_u32(const void* p) {
    return (unsigned)__cvta_generic_to_shared(p);
}
__device__ __forceinline__ void cpasync16(unsigned s, const void* g) {
    asm volatile("cp.async.cg.shared.global [%0],[%1],16;\n" ::"r"(s), "l"(g));
}
__device__ __forceinline__ void cpasync16z(unsigned s, const void* g, unsigned srcsz) {
    asm volatile("cp.async.cg.shared.global [%0],[%1],16,%2;\n" ::"r"(s), "l"(g), "r"(srcsz));
}
__device__ __forceinline__ void cpasync8(unsigned s, const void* g) {
    asm volatile("cp.async.ca.shared.global [%0],[%1],8;\n" ::"r"(s), "l"(g));
}
__device__ __forceinline__ float to_tf32(float x) {
    float r; asm("cvt.rna.tf32.f32 %0,%1;" : "=f"(r) : "f"(x)); return r;
}
__device__ __forceinline__ void mma_tf32(float* c, const uint32_t* a, uint32_t b0, uint32_t b1) {
    asm volatile(
        "mma.sync.aligned.m16n8k8.row.col.f32.tf32.tf32.f32 "
        "{%0,%1,%2,%3}, {%4,%5,%6,%7}, {%8,%9}, {%0,%1,%2,%3};"
        : "+f"(c[0]), "+f"(c[1]), "+f"(c[2]), "+f"(c[3])
        : "r"(a[0]), "r"(a[1]), "r"(a[2]), "r"(a[3]), "r"(b0), "r"(b1));
}
// packed f32x2 (Blackwell, sm_100+)
__device__ __forceinline__ ull mul2(ull a, ull b) {
    ull d; asm("mul.rn.f32x2 %0,%1,%2;" : "=l"(d) : "l"(a), "l"(b)); return d;
}
__device__ __forceinline__ ull fma2(ull a, ull b, ull c) {
    ull d; asm("fma.rn.f32x2 %0,%1,%2,%3;" : "=l"(d) : "l"(a), "l"(b), "l"(c)); return d;
}
__device__ __forceinline__ ull pack2(float x, float y) {
    ull d; asm("mov.b64 %0,{%1,%2};" : "=l"(d) : "f"(x), "f"(y)); return d;
}
__device__ __forceinline__ void unpack2(ull v, float& x, float& y) {
    asm("mov.b64 {%0,%1},%2;" : "=f"(x), "=f"(y) : "l"(v));
}

// ---------------- preround: weights ----------------
__global__ __launch_bounds__(256) void preround_w_kernel(
    const float* __restrict__ w1, const float* __restrict__ wq,
    const float* __restrict__ wo, const float* __restrict__ woq)
{
    const size_t c1 = (size_t)NZ * DM;
    const size_t c2 = c1 + (size_t)DI * DM;
    const size_t c3 = c2 + (size_t)DM * DI;
    const size_t c4 = c3 + (size_t)DM * DI;
    size_t i = ((size_t)blockIdx.x * 256 + threadIdx.x) * 4;
    if (i >= c4) return;
    const float* src; float* dst; size_t off;
    if      (i < c1) { src = w1;  dst = g_rW1;  off = i; }
    else if (i < c2) { src = wq;  dst = g_rWq;  off = i - c1; }
    else if (i < c3) { src = wo;  dst = g_rWo;  off = i - c2; }
    else             { src = woq; dst = g_rWoq; off = i - c3; }
    float4 v = *(const float4*)(src + off);
    v.x = to_tf32(v.x); v.y = to_tf32(v.y); v.z = to_tf32(v.z); v.w = to_tf32(v.w);
    *(float4*)(dst + off) = v;
}

// ---------------- preround: activations ----------------
__global__ __launch_bounds__(256) void preround_a_kernel(
    const float* __restrict__ a1, const float* __restrict__ q)
{
    const size_t c1 = (size_t)BLT * DM;
    const size_t c2 = c1 + (size_t)BB * NK * DM;
    size_t i = ((size_t)blockIdx.x * 256 + threadIdx.x) * 4;
    if (i >= c2) return;
    const float* src; float* dst; size_t off;
    if (i < c1) { src = a1; dst = g_rA1; off = i; }
    else        { src = q;  dst = g_rQ;  off = i - c1; }
    float4 v = *(const float4*)(src + off);
    v.x = to_tf32(v.x); v.y = to_tf32(v.y); v.z = to_tf32(v.z); v.w = to_tf32(v.w);
    *(float4*)(dst + off) = v;
}

// ---------------- zero split-K accumulators ----------------
__global__ __launch_bounds__(256) void zero_acc_kernel(float* outq) {
    size_t i = (size_t)blockIdx.x * 256 + threadIdx.x;
    const size_t n1 = (size_t)BB * NK * DI;
    const size_t n2 = n1 + (size_t)BB * NK * DM;
    if (i < n1) g_h0[i] = 0.f;
    else if (i < n2) outq[i - n1] = 0.f;
}

// ---------------- tensor-core tf32 GEMM: 4 warps, 64x64 warp tile, 3-stage ----------------
#define KC 16
#define PADK 20
#define STAGE_B (128*PADK*4)
#define CHUNK_B (2*STAGE_B)
#define DSMEM_G (3*CHUNK_B)

__global__ __launch_bounds__(128, 2) void gemm_mma(const float* __restrict__ A,
                                                   const float* __restrict__ W,
                                                   float* __restrict__ C,
                                                   int M, int N, int K)
{
    extern __shared__ __align__(16) char dsm[];
    const int tid = threadIdx.x;
    const int lid = tid & 31, wrp = tid >> 5;
    const int wm = wrp & 1, wn = wrp >> 1;
    const int gid = lid >> 2, tig = lid & 3;
    const int m0 = blockIdx.y * 128, n0 = blockIdx.x * 128;
    const unsigned sbase = smem_u32(dsm);

    const int totCh = K >> 4;
    const int per = totCh / gridDim.z;
    const int cbase = blockIdx.z * per;
    const bool split = gridDim.z > 1;

    auto load_chunk = [&](int st, int ch) {
        const float* Ap = A + (size_t)m0 * K + ch * KC;
        const float* Wp = W + (size_t)n0 * K + ch * KC;
        unsigned ao = (unsigned)st * CHUNK_B;
        unsigned bo = ao + STAGE_B;
#pragma unroll
        for (int i = 0; i < 4; i++) {
            int idx = tid + i * 128;
            int row = idx >> 2, kg = idx & 3;
            unsigned so = (unsigned)(row * PADK * 4 + kg * 16);
            cpasync16(sbase + ao + so, Ap + (size_t)row * K + kg * 4);
            int nrow = n0 + row;
            int cl = (nrow < N) ? nrow : (N - 1);
            cpasync16z(sbase + bo + so, Wp + (size_t)(cl - n0) * K + kg * 4,
                       (nrow < N) ? 16u : 0u);
        }
        asm volatile("cp.async.commit_group;\n" ::: "memory");
    };

    float acc[4][8][4];
#pragma unroll
    for (int mf = 0; mf < 4; mf++)
#pragma unroll
        for (int nf = 0; nf < 8; nf++)
#pragma unroll
            for (int i = 0; i < 4; i++) acc[mf][nf][i] = 0.f;

    load_chunk(0, cbase);
    if (per > 1) load_chunk(1, cbase + 1);

    int st = 0;
    for (int c = 0; c < per; c++) {
        if (c + 1 < per) asm volatile("cp.async.wait_group 1;\n" ::: "memory");
        else             asm volatile("cp.async.wait_group 0;\n" ::: "memory");
        __syncthreads();
        if (c + 2 < per) {
            int st2 = st + 2; if (st2 >= 3) st2 -= 3;
            load_chunk(st2, cbase + c + 2);
        }
        const float* as = (const float*)(dsm + st * CHUNK_B);
        const float* bs = (const float*)(dsm + st * CHUNK_B + STAGE_B);
#pragma unroll
        for (int ks = 0; ks < 2; ks++) {
            int k0 = ks * 8;
            uint32_t af[4][4];
#pragma unroll
            for (int mf = 0; mf < 4; mf++) {
                int r = wm * 64 + mf * 16 + gid;
                af[mf][0] = __float_as_uint(as[r * PADK + k0 + tig]);
                af[mf][1] = __float_as_uint(as[(r + 8) * PADK + k0 + tig]);
                af[mf][2] = __float_as_uint(as[r * PADK + k0 + tig + 4]);
                af[mf][3] = __float_as_uint(as[(r + 8) * PADK + k0 + tig + 4]);
            }
#pragma unroll
            for (int nf = 0; nf < 8; nf++) {
                int nr = wn * 64 + nf * 8 + gid;
                uint32_t b0 = __float_as_uint(bs[nr * PADK + k0 + tig]);
                uint32_t b1 = __float_as_uint(bs[nr * PADK + k0 + tig + 4]);
#pragma unroll
                for (int mf = 0; mf < 4; mf++)
                    mma_tf32(acc[mf][nf], af[mf], b0, b1);
            }
        }
        if (++st >= 3) st = 0;
    }

#pragma unroll
    for (int mf = 0; mf < 4; mf++) {
        int r0 = m0 + wm * 64 + mf * 16 + gid;
#pragma unroll
        for (int nf = 0; nf < 8; nf++) {
            int col = n0 + wn * 64 + nf * 8 + tig * 2;
            if (col < N) {
                float* p0 = &C[(size_t)r0 * N + col];
                float* p1 = &C[(size_t)(r0 + 8) * N + col];
                if (!split) {
                    *(float2*)p0 = make_float2(acc[mf][nf][0], acc[mf][nf][1]);
                    *(float2*)p1 = make_float2(acc[mf][nf][2], acc[mf][nf][3]);
                } else {
                    atomicAdd(p0,     acc[mf][nf][0]);
                    atomicAdd(p0 + 1, acc[mf][nf][1]);
                    atomicAdd(p1,     acc[mf][nf][2]);
                    atomicAdd(p1 + 1, acc[mf][nf][3]);
                }
            }
        }
    }
}

// ---------------- depthwise conv7 + silu, sliding window ----------------
__global__ __launch_bounds__(256) void conv_kernel(const float* __restrict__ cwf,
                                                   const float* __restrict__ cbf,
                                                   const float* __restrict__ cwb,
                                                   const float* __restrict__ cbb)
{
    int c = blockIdx.x * 256 + threadIdx.x;
    if (c >= CC) return;
    int l0 = blockIdx.y * 8;
    int db = blockIdx.z;
    int dir = db >> 1, b = db & 1;

    const float* wsrc = (dir ? cwb : cwf) + c * 7;
    float wr[7];
#pragma unroll
    for (int t = 0; t < 7; t++) wr[t] = wsrc[t];
    float bias = (dir ? cbb : cbf)[c];

    const float* src = g_zx + (size_t)b * LL * NZ + DI + c;
    float win[14];
#pragma unroll
    for (int i = 0; i < 14; i++) {
        int l = l0 - 3 + i;
        win[i] = (0 <= l && l < LL) ? src[(size_t)l * NZ] : 0.f;
    }
    float* dst = (dir ? g_convb : g_convf) + ((size_t)b * LL + l0) * CC + c;
#pragma unroll
    for (int j = 0; j < 8; j++) {
        float acc = bias;
#pragma unroll
        for (int t = 0; t < 7; t++) acc = fmaf(wr[t], win[j + t], acc);
        float sig = 1.f / (1.f + __expf(-acc));
        dst[(size_t)j * CC] = acc * sig;
    }
}

// ---------------- pointwise: dt, dA, u_f/u_b, C_f/C_b ----------------
__global__ __launch_bounds__(256) void dtbc_kernel(const float* __restrict__ dist,
                                                   const float* __restrict__ bcw,
                                                   const float* __restrict__ dtw,
                                                   const float* __restrict__ dt_bias,
                                                   const float* __restrict__ A_log)
{
    int bl = blockIdx.x * 4 + (threadIdx.x >> 6);
    int b = bl / LL, l = bl % LL;
    int k = threadIdx.x & 63;
    float4 d4 = *(const float4*)&dist[((size_t)bl * NK + k) * 4];
    float bb = d4.x * bcw[0] + d4.y * bcw[1] + d4.z * bcw[2] + d4.w * bcw[3];
    float cb = d4.x * bcw[4] + d4.y * bcw[5] + d4.z * bcw[6] + d4.w * bcw[7];
    size_t cbase = (size_t)bl * CC;
    float bbf = g_convf[cbase + 1024], cbf = g_convf[cbase + 1025];
    float bbb = g_convb[cbase + 1024], cbb = g_convb[cbase + 1025];
    g_Cf [(size_t)bl * NK + k] = cb + cbf;
    g_Cb2[(size_t)bl * NK + k] = cb + cbb;
    float Bf = bb + bbf, Bbk = bb + bbb;
    size_t zoff = (size_t)bl * NZ + 2 * DI + 2;
#pragma unroll
    for (int h = 0; h < NH; h++) {
        float pre = d4.x * dtw[h * 4 + 0] + d4.y * dtw[h * 4 + 1]
                  + d4.z * dtw[h * 4 + 2] + d4.w * dtw[h * 4 + 3]
                  + g_zx[zoff + h] + dt_bias[h];
        float dt = (pre > 20.f) ? pre : log1pf(__expf(pre));
        float Ah = -__expf(A_log[h]);
        float dA = __expf(dt * Ah);
        size_t o = (((size_t)(b * NH + h) * LL) + l) * NK + k;
        g_dA[o] = dA;
        g_uf[o] = dt * Bf;
        g_ub[o] = dt * Bbk;
    }
}

// ================= chunked scan =================
// P1: per (bh, ps, chunk): S_fwd, S_bwd (scan from 0 within chunk) and P = prod(dA).
#define P1_DA 0
#define P1_U  2048
#define P1_X  4096     // 1024 floats
__global__ __launch_bounds__(256) void scan_p1()
{
    __shared__ __align__(16) float sm1[5120];
    int bid = blockIdx.x;          // 1024: bh(16) x ps(4) x chunk(16)
    int c   = bid & 15;
    int ps  = (bid >> 4) & 3;
    int bh  = bid >> 6;
    int b = bh >> 3, h = bh & 7;
    int tid = threadIdx.x;
    int q = tid & 15, pl = tid >> 4;
    int p0 = ps * 32 + pl * 2;
    const int base_t = c * CHL;

    const float* gdA = g_dA + (size_t)bh * LL * NK;

    auto load_tile = [&](int buf, int tile, const float* gu, const float* gx) {
        size_t t0 = (size_t)base_t + tile * 16;
        cpasync16(smem_u32(&sm1[P1_DA + buf * 1024 + tid * 4]), gdA + t0 * NK + tid * 4);
        cpasync16(smem_u32(&sm1[P1_U  + buf * 1024 + tid * 4]), gu  + t0 * NK + tid * 4);
        int tl = tid >> 4, px = (tid & 15) * 2;
        cpasync8(smem_u32(&sm1[P1_X + buf * 512 + tl * 32 + px]), gx + (t0 + tl) * CC + px);
        asm volatile("cp.async.commit_group;\n");
    };

    // ---- phase F: S_fwd + P ----
    {
        const float* gu = g_uf + (size_t)bh * LL * NK;
        const float* gx = g_convf + (size_t)b * LL * CC + h * PP + ps * 32;
        ull sA01 = 0, sA23 = 0, sB01 = 0, sB23 = 0;
        ull P01 = pack2(1.f, 1.f), P23 = P01;
        load_tile(0, 0, gu, gx);
        for (int s = 0; s < 8; s++) {
            if (s + 1 < 8) {
                load_tile((s + 1) & 1, s + 1, gu, gx);
                asm volatile("cp.async.wait_group 1;\n");
            } else {
                asm volatile("cp.async.wait_group 0;\n");
            }
            __syncthreads();
            int buf = s & 1;
#pragma unroll 4
            for (int j = 0; j < 16; j++) {
                ulonglong2 a2 = *(const ulonglong2*)&sm1[P1_DA + buf * 1024 + j * 64 + 4 * q];
                ulonglong2 u2 = *(const ulonglong2*)&sm1[P1_U  + buf * 1024 + j * 64 + 4 * q];
                float2 xv = *(const float2*)&sm1[P1_X + buf * 512 + j * 32 + pl * 2];
                ull xA = pack2(xv.x, xv.x), xB = pack2(xv.y, xv.y);
                sA01 = fma2(a2.x, sA01, mul2(u2.x, xA));
                sA23 = fma2(a2.y, sA23, mul2(u2.y, xA));
                sB01 = fma2(a2.x, sB01, mul2(u2.x, xB));
                sB23 = fma2(a2.y, sB23, mul2(u2.y, xB));
                P01 = mul2(P01, a2.x);
                P23 = mul2(P23, a2.y);
            }
            __syncthreads();
        }
        size_t so = (((size_t)bh * NCH + c) * PP + p0) * NK + 4 * q;
        *(ulonglong2*)&g_Sf[so]      = make_ulonglong2(sA01, sA23);
        *(ulonglong2*)&g_Sf[so + NK] = make_ulonglong2(sB01, sB23);
        if (pl == 0)
            *(ulonglong2*)&g_P[((size_t)bh * NCH + c) * NK + 4 * q] = make_ulonglong2(P01, P23);
    }

    // ---- phase B: S_bwd ----
    {
        const float* gu = g_ub + (size_t)bh * LL * NK;
        const float* gx = g_convb + (size_t)b * LL * CC + h * PP + ps * 32;
        ull sA01 = 0, sA23 = 0, sB01 = 0, sB23 = 0;
        load_tile(0, 7, gu, gx);
        for (int s = 0; s < 8; s++) {
            if (s + 1 < 8) {
                load_tile((s + 1) & 1, 6 - s, gu, gx);
                asm volatile("cp.async.wait_group 1;\n");
            } else {
                asm volatile("cp.async.wait_group 0;\n");
            }
            __syncthreads();
            int buf = s & 1;
#pragma unroll 4
            for (int j = 0; j < 16; j++) {
                int tt = 15 - j;
                ulonglong2 a2 = *(const ulonglong2*)&sm1[P1_DA + buf * 1024 + tt * 64 + 4 * q];
                ulonglong2 u2 = *(const ulonglong2*)&sm1[P1_U  + buf * 1024 + tt * 64 + 4 * q];
                float2 xv = *(const float2*)&sm1[P1_X + buf * 512 + tt * 32 + pl * 2];
                ull xA = pack2(xv.x, xv.x), xB = pack2(xv.y, xv.y);
                sA01 = fma2(a2.x, sA01, mul2(u2.x, xA));
                sA23 = fma2(a2.y, sA23, mul2(u2.y, xA));
                sB01 = fma2(a2.x, sB01, mul2(u2.x, xB));
                sB23 = fma2(a2.y, sB23, mul2(u2.y, xB));
            }
            __syncthreads();
        }
        size_t so = (((size_t)bh * NCH + c) * PP + p0) * NK + 4 * q;
        *(ulonglong2*)&g_Sb[so]      = make_ulonglong2(sA01, sA23);
        *(ulonglong2*)&g_Sb[so + NK] = make_ulonglong2(sB01, sB23);
    }
}

// P2: combine chunks serially per (p, n), both directions; emit entry states + finals.
__global__ __launch_bounds__(256) void scan_p2()
{
    int bid = blockIdx.x;          // 128: bh(16) x pblk(8)
    int pblk = bid & 7, bh = bid >> 3;
    int b = bh >> 3, h = bh & 7;
    int tid = threadIdx.x;
    int q = tid & 15, pl = tid >> 4;
    int p = pblk * 16 + pl;

    ull h01, h23;
    {
        const float* hp = g_h0 + (size_t)b * NK * DI + h * PP + p;
        h01 = pack2(hp[(size_t)(4 * q + 0) * DI], hp[(size_t)(4 * q + 1) * DI]);
        h23 = pack2(hp[(size_t)(4 * q + 2) * DI], hp[(size_t)(4 * q + 3) * DI]);
    }
    // forward
    {
        ull a01 = h01, a23 = h23;
        for (int c = 0; c < NCH; c++) {
            size_t ho = (((size_t)bh * NCH + c) * PP + p) * NK + 4 * q;
            *(ulonglong2*)&g_hsf[ho] = make_ulonglong2(a01, a23);
            ulonglong2 P2 = *(const ulonglong2*)&g_P[((size_t)bh * NCH + c) * NK + 4 * q];
            ulonglong2 S2 = *(const ulonglong2*)&g_Sf[ho];
            a01 = fma2(P2.x, a01, S2.x);
            a23 = fma2(P2.y, a23, S2.y);
        }
        float f0, f1, f2, f3;
        unpack2(a01, f0, f1); unpack2(a23, f2, f3);
        float* gh = g_hf + ((size_t)bh * PP + p) * NK + 4 * q;
        gh[0] = f0; gh[1] = f1; gh[2] = f2; gh[3] = f3;
    }
    // backward
    {
        ull a01 = h01, a23 = h23;
        for (int c = NCH - 1; c >= 0; c--) {
            size_t ho = (((size_t)bh * NCH + c) * PP + p) * NK + 4 * q;
            *(ulonglong2*)&g_hsb[ho] = make_ulonglong2(a01, a23);
            ulonglong2 P2 = *(const ulonglong2*)&g_P[((size_t)bh * NCH + c) * NK + 4 * q];
            ulonglong2 S2 = *(const ulonglong2*)&g_Sb[ho];
            a01 = fma2(P2.x, a01, S2.x);
            a23 = fma2(P2.y, a23, S2.y);
        }
        float f0, f1, f2, f3;
        unpack2(a01, f0, f1); unpack2(a23, f2, f3);
        float* gh = g_hb + ((size_t)bh * PP + p) * NK + 4 * q;
        gh[0] = f0; gh[1] = f1; gh[2] = f2; gh[3] = f3;
    }
}

// P3: within-chunk scan with true entry state; emit y.
#define SC_DA 0
#define SC_U  2048
#define SC_C  4096
#define SC_X  6144
#define SC_Y  7168
#define DSMEM_S ((7168 + 8192) * 4)     // 61440 B

__global__ __launch_bounds__(256) void scan_p3()
{
    extern __shared__ __align__(16) float sm[];
    int bid = blockIdx.x;          // 2048: c(16) x ps(4) x bh(16) x dir(2)
    int c   = bid & 15;
    int ps  = (bid >> 4) & 3;
    int bh  = (bid >> 6) & 15;
    int dir = bid >> 10;
    int b = bh >> 3, h = bh & 7;
    int tid = threadIdx.x;
    int q = tid & 15, pl = tid >> 4;
    int p0 = ps * 32 + pl * 2;
    const int base_t = c * CHL;

    const float* gdA = g_dA + (size_t)bh * LL * NK;
    const float* gu  = (dir ? g_ub : g_uf) + (size_t)bh * LL * NK;
    const float* gC  = (dir ? g_Cb2 : g_Cf) + (size_t)b * LL * NK;
    const float* gx  = (dir ? g_convb : g_convf) + (size_t)b * LL * CC + h * PP + ps * 32;
    float* gyr = (dir ? g_yb : g_yf) + (size_t)b * LL * DI + h * PP + ps * 32;

    ull hA01, hA23, hB01, hB23;
    {
        const float* hsp = (dir ? g_hsb : g_hsf)
                         + (((size_t)bh * NCH + c) * PP + p0) * NK + 4 * q;
        ulonglong2 vA = *(const ulonglong2*)&hsp[0];
        ulonglong2 vB = *(const ulonglong2*)&hsp[NK];
        hA01 = vA.x; hA23 = vA.y; hB01 = vB.x; hB23 = vB.y;
    }

    auto load_tile = [&](int buf, int tile) {
        size_t t0 = (size_t)base_t + tile * 16;
        cpasync16(smem_u32(&sm[SC_DA + buf * 1024 + tid * 4]), gdA + t0 * NK + tid * 4);
        cpasync16(smem_u32(&sm[SC_U  + buf * 1024 + tid * 4]), gu  + t0 * NK + tid * 4);
        cpasync16(smem_u32(&sm[SC_C  + buf * 1024 + tid * 4]), gC  + t0 * NK + tid * 4);
        int tl = tid >> 4, px = (tid & 15) * 2;
        cpasync8(smem_u32(&sm[SC_X + buf * 512 + tl * 32 + px]), gx + (t0 + tl) * CC + px);
        asm volatile("cp.async.commit_group;\n");
    };

    load_tile(0, dir ? 7 : 0);
    for (int s = 0; s < 8; s++) {
        if (s + 1 < 8) {
            load_tile((s + 1) & 1, dir ? 6 - s : s + 1);
            asm volatile("cp.async.wait_group 1;\n");
        } else {
            asm volatile("cp.async.wait_group 0;\n");
        }
        __syncthreads();
        int buf = s & 1;
        int tile = dir ? 7 - s : s;
#pragma unroll 4
        for (int j = 0; j < 16; j++) {
            int tt = dir ? (15 - j) : j;
            ulonglong2 a2 = *(const ulonglong2*)&sm[SC_DA + buf * 1024 + tt * 64 + 4 * q];
            ulonglong2 u2 = *(const ulonglong2*)&sm[SC_U  + buf * 1024 + tt * 64 + 4 * q];
            ulonglong2 c2 = *(const ulonglong2*)&sm[SC_C  + buf * 1024 + tt * 64 + 4 * q];
            float2 xv = *(const float2*)&sm[SC_X + buf * 512 + tt * 32 + pl * 2];
            ull xA = pack2(xv.x, xv.x), xB = pack2(xv.y, xv.y);
            hA01 = fma2(a2.x, hA01, mul2(u2.x, xA));
            hA23 = fma2(a2.y, hA23, mul2(u2.y, xA));
            hB01 = fma2(a2.x, hB01, mul2(u2.x, xB));
            hB23 = fma2(a2.y, hB23, mul2(u2.y, xB));
            ull accA = fma2(c2.y, hA23, mul2(c2.x, hA01));
            ull accB = fma2(c2.y, hB23, mul2(c2.x, hB01));
            float la, ha, lb, hb2;
            unpack2(accA, la, ha);
            unpack2(accB, lb, hb2);
            sm[SC_Y + tt * 512 + (pl * 2 + 0) * 16 + q] = la + ha;
            sm[SC_Y + tt * 512 + (pl * 2 + 1) * 16 + q] = lb + hb2;
        }
        __syncthreads();
#pragma unroll
        for (int r = 0; r < 2; r++) {
            int cell = tid * 2 + r;
            int t_loc = cell >> 5, pr = cell & 31;
            const float4* src = (const float4*)&sm[SC_Y + t_loc * 512 + pr * 16];
            float4 v0 = src[0], v1 = src[1], v2 = src[2], v3 = src[3];
            float sum = ((v0.x + v0.y) + (v0.z + v0.w)) + ((v1.x + v1.y) + (v1.z + v1.w))
                      + ((v2.x + v2.y) + (v2.z + v2.w)) + ((v3.x + v3.y) + (v3.z + v3.w));
            int gt = base_t + tile * 16 + t_loc;
            gyr[(size_t)gt * DI + pr] = sum;
        }
    }
}

// ---------------- combine y, gate with silu(z), RMSNorm (tf32 out) ----------------
__global__ __launch_bounds__(256) void gate_norm_key_kernel(const float* __restrict__ Dp,
                                                            const float* __restrict__ normw)
{
    int bl = blockIdx.x;
    int tid = threadIdx.x;
    __shared__ float s_v[DI];
    __shared__ float sred[9];
    float ss = 0.f;
    size_t byDI = (size_t)bl * DI, byCC = (size_t)bl * CC, byNZ = (size_t)bl * NZ;
#pragma unroll
    for (int it = 0; it < 4; it++) {
        int i = tid + it * 256;
        int hh = i >> 7;
        float y = 0.5f * (g_yf[byDI + i] + g_yb[byDI + i])
                + 0.5f * Dp[hh] * (g_convf[byCC + i] + g_convb[byCC + i]);
        float z = g_zx[byNZ + i];
        float xg = y * z * (1.f / (1.f + __expf(-z)));
        s_v[i] = xg;
        ss += xg * xg;
    }
    for (int o = 16; o; o >>= 1) ss += __shfl_xor_sync(0xffffffffu, ss, o);
    if ((tid & 31) == 0) sred[tid >> 5] = ss;
    __syncthreads();
    if (tid == 0) {
        float t = 0.f;
        for (int w = 0; w < 8; w++) t += sred[w];
        sred[8] = rsqrtf(t * (1.f / DI) + 1e-5f);
    }
    __syncthreads();
    float sc = sred[8];
#pragma unroll
    for (int it = 0; it < 4; it++) {
        int i = tid + it * 256;
        g_xg[byDI + i] = to_tf32(s_v[i] * sc * normw[i]);
    }
}

// ---------------- query path: average final states, LayerNorm (tf32 out) ----------------
__global__ __launch_bounds__(256) void qnorm_kernel(const float* __restrict__ w,
                                                    const float* __restrict__ bi)
{
    int bk = blockIdx.x;
    int b = bk >> 6, k = bk & 63;
    int tid = threadIdx.x;
    __shared__ float s_v[DI];
    __shared__ float sred[18];
    float s1 = 0.f, s2 = 0.f;
#pragma unroll
    for (int it = 0; it < 4; it++) {
        int i = tid + it * 256;
        int hh = i >> 7, p = i & 127;
        size_t o = ((size_t)(b * NH + hh) * PP + p) * NK + k;
        float qv = 0.5f * (g_hf[o] + g_hb[o]);
        s_v[i] = qv;
        s1 += qv;
        s2 += qv * qv;
    }
    for (int o = 16; o; o >>= 1) {
        s1 += __shfl_xor_sync(0xffffffffu, s1, o);
        s2 += __shfl_xor_sync(0xffffffffu, s2, o);
    }
    if ((tid & 31) == 0) { sred[tid >> 5] = s1; sred[8 + (tid >> 5)] = s2; }
    __syncthreads();
    if (tid == 0) {
        float t1 = 0.f, t2 = 0.f;
        for (int wv = 0; wv < 8; wv++) { t1 += sred[wv]; t2 += sred[8 + wv]; }
        float mu = t1 * (1.f / DI);
        float var = t2 * (1.f / DI) - mu * mu;
        sred[16] = mu;
        sred[17] = rsqrtf(var + 1e-5f);
    }
    __syncthreads();
    float mu = sred[16], rs = sred[17];
#pragma unroll
    for (int it = 0; it < 4; it++) {
        int i = tid + it * 256;
        g_qn[(size_t)bk * DI + i] = to_tf32((s_v[i] - mu) * rs * w[i] + bi[i]);
    }
}

// ---------------- host launcher ----------------
extern "C" void kernel_launch(void* const* d_in, const int* in_sizes, int n_in,
                              void* d_out, int out_size)
{
    (void)in_sizes; (void)n_in; (void)out_size;
    const float* in_key      = (const float*)d_in[0];
    const float* in_query    = (const float*)d_in[1];
    const float* dist        = (const float*)d_in[2];
    const float* key_proj_w  = (const float*)d_in[4];
    const float* key_conv_w  = (const float*)d_in[5];
    const float* key_conv_b  = (const float*)d_in[6];
    const float* key_conv_bw = (const float*)d_in[7];
    const float* key_conv_bb = (const float*)d_in[8];
    const float* query_proj_w= (const float*)d_in[9];
    const float* bc_proj_w   = (const float*)d_in[10];
    const float* dt_proj_w   = (const float*)d_in[11];
    const float* dt_bias     = (const float*)d_in[12];
    const float* A_log       = (const float*)d_in[13];
    const float* D_param     = (const float*)d_in[14];
    const float* out_key_w   = (const float*)d_in[15];
    const float* out_query_w = (const float*)d_in[16];
    const float* key_norm_w  = (const float*)d_in[17];
    const float* q_ln_w      = (const float*)d_in[18];
    const float* q_ln_b      = (const float*)d_in[19];
    float* out = (float*)d_out;

    void *p_zx, *p_h0, *p_xg, *p_qn;
    void *p_rA1, *p_rW1, *p_rQ, *p_rWq, *p_rWo, *p_rWoq;
    cudaGetSymbolAddress(&p_zx, g_zx);
    cudaGetSymbolAddress(&p_h0, g_h0);
    cudaGetSymbolAddress(&p_xg, g_xg);
    cudaGetSymbolAddress(&p_qn, g_qn);
    cudaGetSymbolAddress(&p_rA1, g_rA1);
    cudaGetSymbolAddress(&p_rW1, g_rW1);
    cudaGetSymbolAddress(&p_rQ, g_rQ);
    cudaGetSymbolAddress(&p_rWq, g_rWq);
    cudaGetSymbolAddress(&p_rWo, g_rWo);
    cudaGetSymbolAddress(&p_rWoq, g_rWoq);

    cudaFuncSetAttribute(gemm_mma, cudaFuncAttributeMaxDynamicSharedMemorySize, DSMEM_G);
    cudaFuncSetAttribute(scan_p3, cudaFuncAttributeMaxDynamicSharedMemorySize, DSMEM_S);

    // #1: round weights
    {
        size_t total = (size_t)NZ * DM + (size_t)DI * DM + 2ull * DM * DI;
        preround_w_kernel<<<(int)((total / 4 + 255) / 256), 256>>>(
            key_proj_w, query_proj_w, out_key_w, out_query_w);
    }
    // #2: round activations
    {
        size_t total = (size_t)BLT * DM + (size_t)BB * NK * DM;
        preround_a_kernel<<<(int)((total / 4 + 255) / 256), 256>>>(in_key, in_query);
    }
    // #3: zero split-K accumulators
    {
        size_t total = (size_t)BB * NK * DI + (size_t)BB * NK * DM;
        zero_acc_kernel<<<(int)((total + 255) / 256), 256>>>(out + (size_t)BLT * DM);
    }
    // #4: zxbcdt = in_key @ key_proj_w^T
    {
        dim3 grid((NZ + 127) / 128, BLT / 128, 1);
        gemm_mma<<<grid, 128, DSMEM_G>>>((const float*)p_rA1, (const float*)p_rW1,
                                         (float*)p_zx, BLT, NZ, DM);
    }
    // #5: h0 = in_query @ query_proj_w^T, split-K x4
    {
        dim3 grid(DI / 128, 1, 4);
        gemm_mma<<<grid, 128, DSMEM_G>>>((const float*)p_rQ, (const float*)p_rWq,
                                         (float*)p_h0, BB * NK, DI, DM);
    }
    // #6: depthwise conv + silu
    {
        dim3 grid((CC + 255) / 256, LL / 8, 2 * BB);
        conv_kernel<<<grid, 256>>>(key_conv_w, key_conv_b, key_conv_bw, key_conv_bb);
    }
    // #7: pointwise dt/dA/u/C
    dtbc_kernel<<<BLT / 4, 256>>>(dist, bc_proj_w, dt_proj_w, dt_bias, A_log);
    // #8-#10: chunked scan
    scan_p1<<<1024, 256>>>();
    scan_p2<<<128, 256>>>();
    scan_p3<<<2048, 256, DSMEM_S>>>();
    // #11: combine + gate + RMSNorm
    gate_norm_key_kernel<<<BLT, 256>>>(D_param, key_norm_w);
    // #12: out_key = key_n @ out_key_w^T
    {
        dim3 grid(DM / 128, BLT / 128, 1);
        gemm_mma<<<grid, 128, DSMEM_G>>>((const float*)p_xg, (const float*)p_rWo,
                                         out, BLT, DM, DI);
    }
    // #13: query layer norm
    qnorm_kernel<<<BB * NK, 256>>>(q_ln_w, q_ln_b);
    // #14: out_query = qn @ out_query_w^T, split-K x8
    {
        dim3 grid(DM / 128, 1, 8);
        gemm_mma<<<grid, 128, DSMEM_G>>>((const float*)p_qn, (const float*)p_rWoq,
                                         out + (size_t)BLT * DM, BB * NK, DM, DI);
    }
}

// round 12
// speedup vs baseline: 1.3235x; 1.3043x over previous
#include <cuda_runtime.h>
#include <cuda_bf16.h>
#include <cstdint>

// ---------------- problem constants ----------------
#define BB 2
#define LL 2048
#define NK 64
#define DM 512
#define DI 1024
#define NH 8
#define PP 128
#define NZ 2058
#define CC 1026
#define BLT (BB*LL)
#define NCH 16          // chunks over L
#define CHL 128         // chunk length

typedef unsigned long long ull;

// ---------------- scratch ----------------
__device__ float g_zx   [(size_t)BB*LL*NZ];
__device__ float g_convf[(size_t)BB*LL*CC];
__device__ float g_convb[(size_t)BB*LL*CC];
__device__ float g_dA   [(size_t)BB*NH*LL*NK];
__device__ float g_uf   [(size_t)BB*NH*LL*NK];
__device__ float g_ub   [(size_t)BB*NH*LL*NK];
__device__ float g_Cf   [(size_t)BB*LL*NK];
__device__ float g_Cb2  [(size_t)BB*LL*NK];
__device__ float g_h0   [(size_t)BB*NK*DI];
__device__ float g_yf   [(size_t)BB*LL*DI];
__device__ float g_yb   [(size_t)BB*LL*DI];
__device__ float g_hf   [(size_t)BB*NH*PP*NK];
__device__ float g_hb   [(size_t)BB*NH*PP*NK];
__device__ float g_xg   [(size_t)BB*LL*DI];
__device__ float g_qn   [(size_t)BB*NK*DI];
// chunked-scan intermediates
__device__ float g_Sf  [(size_t)16*NCH*PP*NK];
__device__ float g_Sb  [(size_t)16*NCH*PP*NK];
__device__ float g_P   [(size_t)16*NCH*NK];
__device__ float g_hsf [(size_t)16*NCH*PP*NK];
__device__ float g_hsb [(size_t)16*NCH*PP*NK];
// tf32-rounded copies of GEMM inputs
__device__ float g_rA1 [(size_t)BLT*DM];
__device__ float g_rW1 [(size_t)NZ*DM];
__device__ float g_rQ  [(size_t)BB*NK*DM];
__device__ float g_rWq [(size_t)DI*DM];
__device__ float g_rWo [(size_t)DM*DI];
__device__ float g_rWoq[(size_t)DM*DI];

// ---------------- helpers ----------------
__device__ __forceinline__ unsigned smem_u32(const void* p) {
    return (unsigned)__cvta_generic_to_shared(p);
}
__device__ __forceinline__ void cpasync16(unsigned s, const void* g) {
    asm volatile("cp.async.cg.shared.global [%0],[%1],16;\n" ::"r"(s), "l"(g));
}
__device__ __forceinline__ void cpasync16z(unsigned s, const void* g, unsigned srcsz) {
    asm volatile("cp.async.cg.shared.global [%0],[%1],16,%2;\n" ::"r"(s), "l"(g), "r"(srcsz));
}
__device__ __forceinline__ void cpasync8(unsigned s, const void* g) {
    asm volatile("cp.async.ca.shared.global [%0],[%1],8;\n" ::"r"(s), "l"(g));
}
__device__ __forceinline__ float to_tf32(float x) {
    float r; asm("cvt.rna.tf32.f32 %0,%1;" : "=f"(r) : "f"(x)); return r;
}
__device__ __forceinline__ void mma_tf32(float* c, const uint32_t* a, uint32_t b0, uint32_t b1) {
    asm volatile(
        "mma.sync.aligned.m16n8k8.row.col.f32.tf32.tf32.f32 "
        "{%0,%1,%2,%3}, {%4,%5,%6,%7}, {%8,%9}, {%0,%1,%2,%3};"
        : "+f"(c[0]), "+f"(c[1]), "+f"(c[2]), "+f"(c[3])
        : "r"(a[0]), "r"(a[1]), "r"(a[2]), "r"(a[3]), "r"(b0), "r"(b1));
}
// packed f32x2 (Blackwell, sm_100+)
__device__ __forceinline__ ull mul2(ull a, ull b) {
    ull d; asm("mul.rn.f32x2 %0,%1,%2;" : "=l"(d) : "l"(a), "l"(b)); return d;
}
__device__ __forceinline__ ull fma2(ull a, ull b, ull c) {
    ull d; asm("fma.rn.f32x2 %0,%1,%2,%3;" : "=l"(d) : "l"(a), "l"(b), "l"(c)); return d;
}
__device__ __forceinline__ ull pack2(float x, float y) {
    ull d; asm("mov.b64 %0,{%1,%2};" : "=l"(d) : "f"(x), "f"(y)); return d;
}
__device__ __forceinline__ void unpack2(ull v, float& x, float& y) {
    asm("mov.b64 {%0,%1},%2;" : "=f"(x), "=f"(y) : "l"(v));
}

// ---------------- preround: weights ----------------
__global__ __launch_bounds__(256) void preround_w_kernel(
    const float* __restrict__ w1, const float* __restrict__ wq,
    const float* __restrict__ wo, const float* __restrict__ woq)
{
    const size_t c1 = (size_t)NZ * DM;
    const size_t c2 = c1 + (size_t)DI * DM;
    const size_t c3 = c2 + (size_t)DM * DI;
    const size_t c4 = c3 + (size_t)DM * DI;
    size_t i = ((size_t)blockIdx.x * 256 + threadIdx.x) * 4;
    if (i >= c4) return;
    const float* src; float* dst; size_t off;
    if      (i < c1) { src = w1;  dst = g_rW1;  off = i; }
    else if (i < c2) { src = wq;  dst = g_rWq;  off = i - c1; }
    else if (i < c3) { src = wo;  dst = g_rWo;  off = i - c2; }
    else             { src = woq; dst = g_rWoq; off = i - c3; }
    float4 v = *(const float4*)(src + off);
    v.x = to_tf32(v.x); v.y = to_tf32(v.y); v.z = to_tf32(v.z); v.w = to_tf32(v.w);
    *(float4*)(dst + off) = v;
}

// ---------------- preround: activations ----------------
__global__ __launch_bounds__(256) void preround_a_kernel(
    const float* __restrict__ a1, const float* __restrict__ q)
{
    const size_t c1 = (size_t)BLT * DM;
    const size_t c2 = c1 + (size_t)BB * NK * DM;
    size_t i = ((size_t)blockIdx.x * 256 + threadIdx.x) * 4;
    if (i >= c2) return;
    const float* src; float* dst; size_t off;
    if (i < c1) { src = a1; dst = g_rA1; off = i; }
    else        { src = q;  dst = g_rQ;  off = i - c1; }
    float4 v = *(const float4*)(src + off);
    v.x = to_tf32(v.x); v.y = to_tf32(v.y); v.z = to_tf32(v.z); v.w = to_tf32(v.w);
    *(float4*)(dst + off) = v;
}

// ---------------- zero split-K accumulators ----------------
__global__ __launch_bounds__(256) void zero_acc_kernel(float* outq) {
    size_t i = (size_t)blockIdx.x * 256 + threadIdx.x;
    const size_t n1 = (size_t)BB * NK * DI;
    const size_t n2 = n1 + (size_t)BB * NK * DM;
    if (i < n1) g_h0[i] = 0.f;
    else if (i < n2) outq[i - n1] = 0.f;
}

// ---------------- tensor-core tf32 GEMM: 4 warps, 64x64 warp tile, 3-stage ----------------
#define KC 16
#define PADK 20
#define STAGE_B (128*PADK*4)
#define CHUNK_B (2*STAGE_B)
#define DSMEM_G (3*CHUNK_B)

__global__ __launch_bounds__(128, 2) void gemm_mma(const float* __restrict__ A,
                                                   const float* __restrict__ W,
                                                   float* __restrict__ C,
                                                   int M, int N, int K)
{
    extern __shared__ __align__(16) char dsm[];
    const int tid = threadIdx.x;
    const int lid = tid & 31, wrp = tid >> 5;
    const int wm = wrp & 1, wn = wrp >> 1;
    const int gid = lid >> 2, tig = lid & 3;
    const int m0 = blockIdx.y * 128, n0 = blockIdx.x * 128;
    const unsigned sbase = smem_u32(dsm);

    const int totCh = K >> 4;
    const int per = totCh / gridDim.z;
    const int cbase = blockIdx.z * per;
    const bool split = gridDim.z > 1;

    auto load_chunk = [&](int st, int ch) {
        const float* Ap = A + (size_t)m0 * K + ch * KC;
        const float* Wp = W + (size_t)n0 * K + ch * KC;
        unsigned ao = (unsigned)st * CHUNK_B;
        unsigned bo = ao + STAGE_B;
#pragma unroll
        for (int i = 0; i < 4; i++) {
            int idx = tid + i * 128;
            int row = idx >> 2, kg = idx & 3;
            unsigned so = (unsigned)(row * PADK * 4 + kg * 16);
            cpasync16(sbase + ao + so, Ap + (size_t)row * K + kg * 4);
            int nrow = n0 + row;
            int cl = (nrow < N) ? nrow : (N - 1);
            cpasync16z(sbase + bo + so, Wp + (size_t)(cl - n0) * K + kg * 4,
                       (nrow < N) ? 16u : 0u);
        }
        asm volatile("cp.async.commit_group;\n" ::: "memory");
    };

    float acc[4][8][4];
#pragma unroll
    for (int mf = 0; mf < 4; mf++)
#pragma unroll
        for (int nf = 0; nf < 8; nf++)
#pragma unroll
            for (int i = 0; i < 4; i++) acc[mf][nf][i] = 0.f;

    load_chunk(0, cbase);
    if (per > 1) load_chunk(1, cbase + 1);

    int st = 0;
    for (int c = 0; c < per; c++) {
        if (c + 1 < per) asm volatile("cp.async.wait_group 1;\n" ::: "memory");
        else             asm volatile("cp.async.wait_group 0;\n" ::: "memory");
        __syncthreads();
        if (c + 2 < per) {
            int st2 = st + 2; if (st2 >= 3) st2 -= 3;
            load_chunk(st2, cbase + c + 2);
        }
        const float* as = (const float*)(dsm + st * CHUNK_B);
        const float* bs = (const float*)(dsm + st * CHUNK_B + STAGE_B);
#pragma unroll
        for (int ks = 0; ks < 2; ks++) {
            int k0 = ks * 8;
            uint32_t af[4][4];
#pragma unroll
            for (int mf = 0; mf < 4; mf++) {
                int r = wm * 64 + mf * 16 + gid;
                af[mf][0] = __float_as_uint(as[r * PADK + k0 + tig]);
                af[mf][1] = __float_as_uint(as[(r + 8) * PADK + k0 + tig]);
                af[mf][2] = __float_as_uint(as[r * PADK + k0 + tig + 4]);
                af[mf][3] = __float_as_uint(as[(r + 8) * PADK + k0 + tig + 4]);
            }
#pragma unroll
            for (int nf = 0; nf < 8; nf++) {
                int nr = wn * 64 + nf * 8 + gid;
                uint32_t b0 = __float_as_uint(bs[nr * PADK + k0 + tig]);
                uint32_t b1 = __float_as_uint(bs[nr * PADK + k0 + tig + 4]);
#pragma unroll
                for (int mf = 0; mf < 4; mf++)
                    mma_tf32(acc[mf][nf], af[mf], b0, b1);
            }
        }
        if (++st >= 3) st = 0;
    }

#pragma unroll
    for (int mf = 0; mf < 4; mf++) {
        int r0 = m0 + wm * 64 + mf * 16 + gid;
#pragma unroll
        for (int nf = 0; nf < 8; nf++) {
            int col = n0 + wn * 64 + nf * 8 + tig * 2;
            if (col < N) {
                float* p0 = &C[(size_t)r0 * N + col];
                float* p1 = &C[(size_t)(r0 + 8) * N + col];
                if (!split) {
                    *(float2*)p0 = make_float2(acc[mf][nf][0], acc[mf][nf][1]);
                    *(float2*)p1 = make_float2(acc[mf][nf][2], acc[mf][nf][3]);
                } else {
                    atomicAdd(p0,     acc[mf][nf][0]);
                    atomicAdd(p0 + 1, acc[mf][nf][1]);
                    atomicAdd(p1,     acc[mf][nf][2]);
                    atomicAdd(p1 + 1, acc[mf][nf][3]);
                }
            }
        }
    }
}

// ---------------- depthwise conv7 + silu, sliding window ----------------
__global__ __launch_bounds__(256) void conv_kernel(const float* __restrict__ cwf,
                                                   const float* __restrict__ cbf,
                                                   const float* __restrict__ cwb,
                                                   const float* __restrict__ cbb)
{
    int c = blockIdx.x * 256 + threadIdx.x;
    if (c >= CC) return;
    int l0 = blockIdx.y * 8;
    int db = blockIdx.z;
    int dir = db >> 1, b = db & 1;

    const float* wsrc = (dir ? cwb : cwf) + c * 7;
    float wr[7];
#pragma unroll
    for (int t = 0; t < 7; t++) wr[t] = wsrc[t];
    float bias = (dir ? cbb : cbf)[c];

    const float* src = g_zx + (size_t)b * LL * NZ + DI + c;
    float win[14];
#pragma unroll
    for (int i = 0; i < 14; i++) {
        int l = l0 - 3 + i;
        win[i] = (0 <= l && l < LL) ? src[(size_t)l * NZ] : 0.f;
    }
    float* dst = (dir ? g_convb : g_convf) + ((size_t)b * LL + l0) * CC + c;
#pragma unroll
    for (int j = 0; j < 8; j++) {
        float acc = bias;
#pragma unroll
        for (int t = 0; t < 7; t++) acc = fmaf(wr[t], win[j + t], acc);
        float sig = 1.f / (1.f + __expf(-acc));
        dst[(size_t)j * CC] = acc * sig;
    }
}

// ---------------- pointwise: dt, dA, u_f/u_b, C_f/C_b ----------------
__global__ __launch_bounds__(256) void dtbc_kernel(const float* __restrict__ dist,
                                                   const float* __restrict__ bcw,
                                                   const float* __restrict__ dtw,
                                                   const float* __restrict__ dt_bias,
                                                   const float* __restrict__ A_log)
{
    int bl = blockIdx.x * 4 + (threadIdx.x >> 6);
    int b = bl / LL, l = bl % LL;
    int k = threadIdx.x & 63;
    float4 d4 = *(const float4*)&dist[((size_t)bl * NK + k) * 4];
    float bb = d4.x * bcw[0] + d4.y * bcw[1] + d4.z * bcw[2] + d4.w * bcw[3];
    float cb = d4.x * bcw[4] + d4.y * bcw[5] + d4.z * bcw[6] + d4.w * bcw[7];
    size_t cbase = (size_t)bl * CC;
    float bbf = g_convf[cbase + 1024], cbf = g_convf[cbase + 1025];
    float bbb = g_convb[cbase + 1024], cbb = g_convb[cbase + 1025];
    g_Cf [(size_t)bl * NK + k] = cb + cbf;
    g_Cb2[(size_t)bl * NK + k] = cb + cbb;
    float Bf = bb + bbf, Bbk = bb + bbb;
    size_t zoff = (size_t)bl * NZ + 2 * DI + 2;
#pragma unroll
    for (int h = 0; h < NH; h++) {
        float pre = d4.x * dtw[h * 4 + 0] + d4.y * dtw[h * 4 + 1]
                  + d4.z * dtw[h * 4 + 2] + d4.w * dtw[h * 4 + 3]
                  + g_zx[zoff + h] + dt_bias[h];
        float dt = (pre > 20.f) ? pre : log1pf(__expf(pre));
        float Ah = -__expf(A_log[h]);
        float dA = __expf(dt * Ah);
        size_t o = (((size_t)(b * NH + h) * LL) + l) * NK + k;
        g_dA[o] = dA;
        g_uf[o] = dt * Bf;
        g_ub[o] = dt * Bbk;
    }
}

// ================= chunked scan, n-major register layout =================
// P1: per (chunk, bh, dir): S = within-chunk scan from 0 (all 64 n in regs);
//     dir==0 blocks also compute P = prod(dA).
#define T1_DA 0
#define T1_U  2048
#define T1_X  4096     // 2 bufs x 2048
__global__ __launch_bounds__(128, 3) void scan_p1()
{
    __shared__ __align__(16) float sm1[8192];   // 32 KB
    int bid = blockIdx.x;            // c(16) x bh(16) x dir(2)
    int c   = bid & 15;
    int bh  = (bid >> 4) & 15;
    int dir = bid >> 8;
    int b = bh >> 3, h = bh & 7;
    int tid = threadIdx.x;           // = p

    const float* gdA = g_dA + ((size_t)bh * LL + (size_t)c * CHL) * NK;
    const float* gu  = (dir ? g_ub : g_uf) + ((size_t)bh * LL + (size_t)c * CHL) * NK;
    const float* gx  = (dir ? g_convb : g_convf)
                     + ((size_t)b * LL + (size_t)c * CHL) * CC + h * PP;

    ull hh[32];
#pragma unroll
    for (int i = 0; i < 32; i++) hh[i] = 0;
    ull Pa = pack2(1.f, 1.f), Pb = pack2(1.f, 1.f);

    auto load_tile = [&](int buf, int tile) {
        const float* da = gdA + (size_t)tile * 16 * NK;
        const float* uu = gu + (size_t)tile * 16 * NK;
        cpasync16(smem_u32(&sm1[T1_DA + buf * 1024 + tid * 8]),     da + tid * 8);
        cpasync16(smem_u32(&sm1[T1_DA + buf * 1024 + tid * 8 + 4]), da + tid * 8 + 4);
        cpasync16(smem_u32(&sm1[T1_U  + buf * 1024 + tid * 8]),     uu + tid * 8);
        cpasync16(smem_u32(&sm1[T1_U  + buf * 1024 + tid * 8 + 4]), uu + tid * 8 + 4);
        // x rows have stride CC=1026 floats (only 8B-aligned) -> 8-byte cp.async
#pragma unroll
        for (int i = 0; i < 4; i++) {
            int idx = tid + i * 128;
            int row = idx >> 5, c4 = idx & 31;
            const float* xs = gx + (size_t)(tile * 16 + row) * CC + c4 * 4;
            unsigned sd = smem_u32(&sm1[T1_X + buf * 2048 + row * 128 + c4 * 4]);
            cpasync8(sd, xs);
            cpasync8(sd + 8, xs + 2);
        }
        asm volatile("cp.async.commit_group;\n");
    };

    load_tile(0, dir ? 7 : 0);
    for (int s = 0; s < 8; s++) {
        if (s + 1 < 8) {
            load_tile((s + 1) & 1, dir ? 6 - s : s + 1);
            asm volatile("cp.async.wait_group 1;\n");
        } else {
            asm volatile("cp.async.wait_group 0;\n");
        }
        __syncthreads();
        int buf = s & 1;
#pragma unroll 2
        for (int j = 0; j < 16; j++) {
            int tt = dir ? (15 - j) : j;
            float xp = sm1[T1_X + buf * 2048 + tt * 128 + tid];
            ull xx = pack2(xp, xp);
            const float* da = &sm1[T1_DA + buf * 1024 + tt * 64];
            const float* uu = &sm1[T1_U  + buf * 1024 + tt * 64];
#pragma unroll
            for (int i = 0; i < 16; i++) {
                ulonglong2 av = *(const ulonglong2*)&da[i * 4];
                ulonglong2 uv = *(const ulonglong2*)&uu[i * 4];
                hh[2 * i]     = fma2(av.x, hh[2 * i],     mul2(uv.x, xx));
                hh[2 * i + 1] = fma2(av.y, hh[2 * i + 1], mul2(uv.y, xx));
            }
            if (dir == 0 && tid < 16) {
                ulonglong2 av = *(const ulonglong2*)&da[tid * 4];
                Pa = mul2(Pa, av.x);
                Pb = mul2(Pb, av.y);
            }
        }
        __syncthreads();
    }
    float* S = (dir ? g_Sb : g_Sf) + (((size_t)bh * NCH + c) * PP + tid) * NK;
#pragma unroll
    for (int i = 0; i < 16; i++)
        *(ulonglong2*)&S[i * 4] = make_ulonglong2(hh[2 * i], hh[2 * i + 1]);
    if (dir == 0 && tid < 16)
        *(ulonglong2*)&g_P[((size_t)bh * NCH + c) * NK + tid * 4] =
            make_ulonglong2(Pa, Pb);
}

// P2: combine chunks serially per (p, n), both directions (validated in R10).
__global__ __launch_bounds__(256) void scan_p2()
{
    int bid = blockIdx.x;          // 128: bh(16) x pblk(8)
    int pblk = bid & 7, bh = bid >> 3;
    int b = bh >> 3, h = bh & 7;
    int tid = threadIdx.x;
    int q = tid & 15, pl = tid >> 4;
    int p = pblk * 16 + pl;

    ull h01, h23;
    {
        const float* hp = g_h0 + (size_t)b * NK * DI + h * PP + p;
        h01 = pack2(hp[(size_t)(4 * q + 0) * DI], hp[(size_t)(4 * q + 1) * DI]);
        h23 = pack2(hp[(size_t)(4 * q + 2) * DI], hp[(size_t)(4 * q + 3) * DI]);
    }
    {
        ull a01 = h01, a23 = h23;
        for (int c = 0; c < NCH; c++) {
            size_t ho = (((size_t)bh * NCH + c) * PP + p) * NK + 4 * q;
            *(ulonglong2*)&g_hsf[ho] = make_ulonglong2(a01, a23);
            ulonglong2 P2 = *(const ulonglong2*)&g_P[((size_t)bh * NCH + c) * NK + 4 * q];
            ulonglong2 S2 = *(const ulonglong2*)&g_Sf[ho];
            a01 = fma2(P2.x, a01, S2.x);
            a23 = fma2(P2.y, a23, S2.y);
        }
        float f0, f1, f2, f3;
        unpack2(a01, f0, f1); unpack2(a23, f2, f3);
        float* gh = g_hf + ((size_t)bh * PP + p) * NK + 4 * q;
        gh[0] = f0; gh[1] = f1; gh[2] = f2; gh[3] = f3;
    }
    {
        ull a01 = h01, a23 = h23;
        for (int c = NCH - 1; c >= 0; c--) {
            size_t ho = (((size_t)bh * NCH + c) * PP + p) * NK + 4 * q;
            *(ulonglong2*)&g_hsb[ho] = make_ulonglong2(a01, a23);
            ulonglong2 P2 = *(const ulonglong2*)&g_P[((size_t)bh * NCH + c) * NK + 4 * q];
            ulonglong2 S2 = *(const ulonglong2*)&g_Sb[ho];
            a01 = fma2(P2.x, a01, S2.x);
            a23 = fma2(P2.y, a23, S2.y);
        }
        float f0, f1, f2, f3;
        unpack2(a01, f0, f1); unpack2(a23, f2, f3);
        float* gh = g_hb + ((size_t)bh * PP + p) * NK + 4 * q;
        gh[0] = f0; gh[1] = f1; gh[2] = f2; gh[3] = f3;
    }
}

// P3: within-chunk scan with true entry state, full n in regs, y emitted directly.
#define T3_DA 0
#define T3_U  2048
#define T3_C  4096
#define T3_X  6144     // 2 bufs x 2048
__global__ __launch_bounds__(128, 3) void scan_p3()
{
    __shared__ __align__(16) float sm3[10240];  // 40 KB
    int bid = blockIdx.x;            // c(16) x bh(16) x dir(2)
    int c   = bid & 15;
    int bh  = (bid >> 4) & 15;
    int dir = bid >> 8;
    int b = bh >> 3, h = bh & 7;
    int tid = threadIdx.x;           // = p

    const float* gdA = g_dA + ((size_t)bh * LL + (size_t)c * CHL) * NK;
    const float* gu  = (dir ? g_ub : g_uf) + ((size_t)bh * LL + (size_t)c * CHL) * NK;
    const float* gC  = (dir ? g_Cb2 : g_Cf) + ((size_t)b * LL + (size_t)c * CHL) * NK;
    const float* gx  = (dir ? g_convb : g_convf)
                     + ((size_t)b * LL + (size_t)c * CHL) * CC + h * PP;
    float* gy = (dir ? g_yb : g_yf)
              + ((size_t)b * LL + (size_t)c * CHL) * DI + h * PP + tid;

    ull hh[32];
    {
        const float* hs = (dir ? g_hsb : g_hsf)
                        + (((size_t)bh * NCH + c) * PP + tid) * NK;
#pragma unroll
        for (int i = 0; i < 16; i++) {
            ulonglong2 v = *(const ulonglong2*)&hs[i * 4];
            hh[2 * i] = v.x; hh[2 * i + 1] = v.y;
        }
    }

    auto load_tile = [&](int buf, int tile) {
        const float* da = gdA + (size_t)tile * 16 * NK;
        const float* uu = gu + (size_t)tile * 16 * NK;
        const float* cc = gC + (size_t)tile * 16 * NK;
        cpasync16(smem_u32(&sm3[T3_DA + buf * 1024 + tid * 8]),     da + tid * 8);
        cpasync16(smem_u32(&sm3[T3_DA + buf * 1024 + tid * 8 + 4]), da + tid * 8 + 4);
        cpasync16(smem_u32(&sm3[T3_U  + buf * 1024 + tid * 8]),     uu + tid * 8);
        cpasync16(smem_u32(&sm3[T3_U  + buf * 1024 + tid * 8 + 4]), uu + tid * 8 + 4);
        cpasync16(smem_u32(&sm3[T3_C  + buf * 1024 + tid * 8]),     cc + tid * 8);
        cpasync16(smem_u32(&sm3[T3_C  + buf * 1024 + tid * 8 + 4]), cc + tid * 8 + 4);
        // x rows have stride CC=1026 floats (only 8B-aligned) -> 8-byte cp.async
#pragma unroll
        for (int i = 0; i < 4; i++) {
            int idx = tid + i * 128;
            int row = idx >> 5, c4 = idx & 31;
            const float* xs = gx + (size_t)(tile * 16 + row) * CC + c4 * 4;
            unsigned sd = smem_u32(&sm3[T3_X + buf * 2048 + row * 128 + c4 * 4]);
            cpasync8(sd, xs);
            cpasync8(sd + 8, xs + 2);
        }
        asm volatile("cp.async.commit_group;\n");
    };

    load_tile(0, dir ? 7 : 0);
    for (int s = 0; s < 8; s++) {
        if (s + 1 < 8) {
            load_tile((s + 1) & 1, dir ? 6 - s : s + 1);
            asm volatile("cp.async.wait_group 1;\n");
        } else {
            asm volatile("cp.async.wait_group 0;\n");
        }
        __syncthreads();
        int buf = s & 1;
        int tile = dir ? 7 - s : s;
#pragma unroll 2
        for (int j = 0; j < 16; j++) {
            int tt = dir ? (15 - j) : j;
            float xp = sm3[T3_X + buf * 2048 + tt * 128 + tid];
            ull xx = pack2(xp, xp);
            const float* da = &sm3[T3_DA + buf * 1024 + tt * 64];
            const float* uu = &sm3[T3_U  + buf * 1024 + tt * 64];
            const float* cv = &sm3[T3_C  + buf * 1024 + tt * 64];
            ull acc0 = 0, acc1 = 0, acc2 = 0, acc3 = 0;
#pragma unroll
            for (int i = 0; i < 16; i++) {
                ulonglong2 av = *(const ulonglong2*)&da[i * 4];
                ulonglong2 uv = *(const ulonglong2*)&uu[i * 4];
                ulonglong2 c2 = *(const ulonglong2*)&cv[i * 4];
                hh[2 * i]     = fma2(av.x, hh[2 * i],     mul2(uv.x, xx));
                hh[2 * i + 1] = fma2(av.y, hh[2 * i + 1], mul2(uv.y, xx));
                if (i & 1) {
                    acc2 = fma2(c2.x, hh[2 * i], acc2);
                    acc3 = fma2(c2.y, hh[2 * i + 1], acc3);
                } else {
                    acc0 = fma2(c2.x, hh[2 * i], acc0);
                    acc1 = fma2(c2.y, hh[2 * i + 1], acc1);
                }
            }
            float a, bq, cq, d, e, f, g2, h2;
            unpack2(acc0, a, bq); unpack2(acc1, cq, d);
            unpack2(acc2, e, f);  unpack2(acc3, g2, h2);
            float y = ((a + bq) + (cq + d)) + ((e + f) + (g2 + h2));
            gy[(size_t)(tile * 16 + tt) * DI] = y;
        }
        __syncthreads();
    }
}

// ---------------- combine y, gate with silu(z), RMSNorm (tf32 out) ----------------
__global__ __launch_bounds__(256) void gate_norm_key_kernel(const float* __restrict__ Dp,
                                                            const float* __restrict__ normw)
{
    int bl = blockIdx.x;
    int tid = threadIdx.x;
    __shared__ float s_v[DI];
    __shared__ float sred[9];
    float ss = 0.f;
    size_t byDI = (size_t)bl * DI, byCC = (size_t)bl * CC, byNZ = (size_t)bl * NZ;
#pragma unroll
    for (int it = 0; it < 4; it++) {
        int i = tid + it * 256;
        int hh = i >> 7;
        float y = 0.5f * (g_yf[byDI + i] + g_yb[byDI + i])
                + 0.5f * Dp[hh] * (g_convf[byCC + i] + g_convb[byCC + i]);
        float z = g_zx[byNZ + i];
        float xg = y * z * (1.f / (1.f + __expf(-z)));
        s_v[i] = xg;
        ss += xg * xg;
    }
    for (int o = 16; o; o >>= 1) ss += __shfl_xor_sync(0xffffffffu, ss, o);
    if ((tid & 31) == 0) sred[tid >> 5] = ss;
    __syncthreads();
    if (tid == 0) {
        float t = 0.f;
        for (int w = 0; w < 8; w++) t += sred[w];
        sred[8] = rsqrtf(t * (1.f / DI) + 1e-5f);
    }
    __syncthreads();
    float sc = sred[8];
#pragma unroll
    for (int it = 0; it < 4; it++) {
        int i = tid + it * 256;
        g_xg[byDI + i] = to_tf32(s_v[i] * sc * normw[i]);
    }
}

// ---------------- query path: average final states, LayerNorm (tf32 out) ----------------
__global__ __launch_bounds__(256) void qnorm_kernel(const float* __restrict__ w,
                                                    const float* __restrict__ bi)
{
    int bk = blockIdx.x;
    int b = bk >> 6, k = bk & 63;
    int tid = threadIdx.x;
    __shared__ float s_v[DI];
    __shared__ float sred[18];
    float s1 = 0.f, s2 = 0.f;
#pragma unroll
    for (int it = 0; it < 4; it++) {
        int i = tid + it * 256;
        int hh = i >> 7, p = i & 127;
        size_t o = ((size_t)(b * NH + hh) * PP + p) * NK + k;
        float qv = 0.5f * (g_hf[o] + g_hb[o]);
        s_v[i] = qv;
        s1 += qv;
        s2 += qv * qv;
    }
    for (int o = 16; o; o >>= 1) {
        s1 += __shfl_xor_sync(0xffffffffu, s1, o);
        s2 += __shfl_xor_sync(0xffffffffu, s2, o);
    }
    if ((tid & 31) == 0) { sred[tid >> 5] = s1; sred[8 + (tid >> 5)] = s2; }
    __syncthreads();
    if (tid == 0) {
        float t1 = 0.f, t2 = 0.f;
        for (int wv = 0; wv < 8; wv++) { t1 += sred[wv]; t2 += sred[8 + wv]; }
        float mu = t1 * (1.f / DI);
        float var = t2 * (1.f / DI) - mu * mu;
        sred[16] = mu;
        sred[17] = rsqrtf(var + 1e-5f);
    }
    __syncthreads();
    float mu = sred[16], rs = sred[17];
#pragma unroll
    for (int it = 0; it < 4; it++) {
        int i = tid + it * 256;
        g_qn[(size_t)bk * DI + i] = to_tf32((s_v[i] - mu) * rs * w[i] + bi[i]);
    }
}

// ---------------- host launcher ----------------
extern "C" void kernel_launch(void* const* d_in, const int* in_sizes, int n_in,
                              void* d_out, int out_size)
{
    (void)in_sizes; (void)n_in; (void)out_size;
    const float* in_key      = (const float*)d_in[0];
    const float* in_query    = (const float*)d_in[1];
    const float* dist        = (const float*)d_in[2];
    const float* key_proj_w  = (const float*)d_in[4];
    const float* key_conv_w  = (const float*)d_in[5];
    const float* key_conv_b  = (const float*)d_in[6];
    const float* key_conv_bw = (const float*)d_in[7];
    const float* key_conv_bb = (const float*)d_in[8];
    const float* query_proj_w= (const float*)d_in[9];
    const float* bc_proj_w   = (const float*)d_in[10];
    const float* dt_proj_w   = (const float*)d_in[11];
    const float* dt_bias     = (const float*)d_in[12];
    const float* A_log       = (const float*)d_in[13];
    const float* D_param     = (const float*)d_in[14];
    const float* out_key_w   = (const float*)d_in[15];
    const float* out_query_w = (const float*)d_in[16];
    const float* key_norm_w  = (const float*)d_in[17];
    const float* q_ln_w      = (const float*)d_in[18];
    const float* q_ln_b      = (const float*)d_in[19];
    float* out = (float*)d_out;

    void *p_zx, *p_h0, *p_xg, *p_qn;
    void *p_rA1, *p_rW1, *p_rQ, *p_rWq, *p_rWo, *p_rWoq;
    cudaGetSymbolAddress(&p_zx, g_zx);
    cudaGetSymbolAddress(&p_h0, g_h0);
    cudaGetSymbolAddress(&p_xg, g_xg);
    cudaGetSymbolAddress(&p_qn, g_qn);
    cudaGetSymbolAddress(&p_rA1, g_rA1);
    cudaGetSymbolAddress(&p_rW1, g_rW1);
    cudaGetSymbolAddress(&p_rQ, g_rQ);
    cudaGetSymbolAddress(&p_rWq, g_rWq);
    cudaGetSymbolAddress(&p_rWo, g_rWo);
    cudaGetSymbolAddress(&p_rWoq, g_rWoq);

    cudaFuncSetAttribute(gemm_mma, cudaFuncAttributeMaxDynamicSharedMemorySize, DSMEM_G);

    // #1: round weights
    {
        size_t total = (size_t)NZ * DM + (size_t)DI * DM + 2ull * DM * DI;
        preround_w_kernel<<<(int)((total / 4 + 255) / 256), 256>>>(
            key_proj_w, query_proj_w, out_key_w, out_query_w);
    }
    // #2: round activations
    {
        size_t total = (size_t)BLT * DM + (size_t)BB * NK * DM;
        preround_a_kernel<<<(int)((total / 4 + 255) / 256), 256>>>(in_key, in_query);
    }
    // #3: zero split-K accumulators
    {
        size_t total = (size_t)BB * NK * DI + (size_t)BB * NK * DM;
        zero_acc_kernel<<<(int)((total + 255) / 256), 256>>>(out + (size_t)BLT * DM);
    }
    // #4: zxbcdt = in_key @ key_proj_w^T
    {
        dim3 grid((NZ + 127) / 128, BLT / 128, 1);
        gemm_mma<<<grid, 128, DSMEM_G>>>((const float*)p_rA1, (const float*)p_rW1,
                                         (float*)p_zx, BLT, NZ, DM);
    }
    // #5: h0 = in_query @ query_proj_w^T, split-K x4
    {
        dim3 grid(DI / 128, 1, 4);
        gemm_mma<<<grid, 128, DSMEM_G>>>((const float*)p_rQ, (const float*)p_rWq,
                                         (float*)p_h0, BB * NK, DI, DM);
    }
    // #6: depthwise conv + silu
    {
        dim3 grid((CC + 255) / 256, LL / 8, 2 * BB);
        conv_kernel<<<grid, 256>>>(key_conv_w, key_conv_b, key_conv_bw, key_conv_bb);
    }
    // #7: pointwise dt/dA/u/C
    dtbc_kernel<<<BLT / 4, 256>>>(dist, bc_proj_w, dt_proj_w, dt_bias, A_log);
    // #8-#10: chunked scan (n-major register layout)
    scan_p1<<<512, 128>>>();
    scan_p2<<<128, 256>>>();
    scan_p3<<<512, 128>>>();
    // #11: combine + gate + RMSNorm
    gate_norm_key_kernel<<<BLT, 256>>>(D_param, key_norm_w);
    // #12: out_key = key_n @ out_key_w^T
    {
        dim3 grid(DM / 128, BLT / 128, 1);
        gemm_mma<<<grid, 128, DSMEM_G>>>((const float*)p_xg, (const float*)p_rWo,
                                         out, BLT, DM, DI);
    }
    // #13: query layer norm
    qnorm_kernel<<<BB * NK, 256>>>(q_ln_w, q_ln_b);
    // #14: out_query = qn @ out_query_w^T, split-K x8
    {
        dim3 grid(DM / 128, 1, 8);
        gemm_mma<<<grid, 128, DSMEM_G>>>((const float*)p_qn, (const float*)p_rWoq,
                                         out + (size_t)BLT * DM, BB * NK, DM, DI);
    }
}

// round 13
// speedup vs baseline: 1.3619x; 1.0290x over previous
#include <cuda_runtime.h>
#include <cuda_bf16.h>
#include <cstdint>

// ---------------- problem constants ----------------
#define BB 2
#define LL 2048
#define NK 64
#define DM 512
#define DI 1024
#define NH 8
#define PP 128
#define NZ 2058
#define CC 1026
#define BLT (BB*LL)
#define NCH 16          // chunks over L
#define CHL 128         // chunk length

typedef unsigned long long ull;

// ---------------- scratch ----------------
__device__ float g_zx   [(size_t)BB*LL*NZ];
__device__ float g_convf[(size_t)BB*LL*CC];
__device__ float g_convb[(size_t)BB*LL*CC];
__device__ float g_dA   [(size_t)BB*NH*LL*NK];
__device__ float g_uf   [(size_t)BB*NH*LL*NK];
__device__ float g_ub   [(size_t)BB*NH*LL*NK];
__device__ float g_Cf   [(size_t)BB*LL*NK];
__device__ float g_Cb2  [(size_t)BB*LL*NK];
__device__ float g_h0   [(size_t)BB*NK*DI];
__device__ float g_yf   [(size_t)BB*LL*DI];
__device__ float g_yb   [(size_t)BB*LL*DI];
__device__ float g_hf   [(size_t)BB*NH*PP*NK];
__device__ float g_hb   [(size_t)BB*NH*PP*NK];
__device__ float g_xg   [(size_t)BB*LL*DI];
__device__ float g_qn   [(size_t)BB*NK*DI];
// chunked-scan intermediates
__device__ float g_Sf  [(size_t)16*NCH*PP*NK];
__device__ float g_Sb  [(size_t)16*NCH*PP*NK];
__device__ float g_P   [(size_t)16*NCH*NK];
__device__ float g_hsf [(size_t)16*NCH*PP*NK];
__device__ float g_hsb [(size_t)16*NCH*PP*NK];
// tf32-rounded copies of GEMM inputs
__device__ float g_rA1 [(size_t)BLT*DM];
__device__ float g_rW1 [(size_t)NZ*DM];
__device__ float g_rQ  [(size_t)BB*NK*DM];
__device__ float g_rWq [(size_t)DI*DM];
__device__ float g_rWo [(size_t)DM*DI];
__device__ float g_rWoq[(size_t)DM*DI];

// ---------------- helpers ----------------
__device__ __forceinline__ unsigned smem_u32(const void* p) {
    return (unsigned)__cvta_generic_to_shared(p);
}
__device__ __forceinline__ void cpasync16(unsigned s, const void* g) {
    asm volatile("cp.async.cg.shared.global [%0],[%1],16;\n" ::"r"(s), "l"(g));
}
__device__ __forceinline__ void cpasync16z(unsigned s, const void* g, unsigned srcsz) {
    asm volatile("cp.async.cg.shared.global [%0],[%1],16,%2;\n" ::"r"(s), "l"(g), "r"(srcsz));
}
__device__ __forceinline__ void cpasync8(unsigned s, const void* g) {
    asm volatile("cp.async.ca.shared.global [%0],[%1],8;\n" ::"r"(s), "l"(g));
}
__device__ __forceinline__ float to_tf32(float x) {
    float r; asm("cvt.rna.tf32.f32 %0,%1;" : "=f"(r) : "f"(x)); return r;
}
__device__ __forceinline__ void mma_tf32(float* c, const uint32_t* a, uint32_t b0, uint32_t b1) {
    asm volatile(
        "mma.sync.aligned.m16n8k8.row.col.f32.tf32.tf32.f32 "
        "{%0,%1,%2,%3}, {%4,%5,%6,%7}, {%8,%9}, {%0,%1,%2,%3};"
        : "+f"(c[0]), "+f"(c[1]), "+f"(c[2]), "+f"(c[3])
        : "r"(a[0]), "r"(a[1]), "r"(a[2]), "r"(a[3]), "r"(b0), "r"(b1));
}
// packed f32x2 (Blackwell, sm_100+)
__device__ __forceinline__ ull mul2(ull a, ull b) {
    ull d; asm("mul.rn.f32x2 %0,%1,%2;" : "=l"(d) : "l"(a), "l"(b)); return d;
}
__device__ __forceinline__ ull fma2(ull a, ull b, ull c) {
    ull d; asm("fma.rn.f32x2 %0,%1,%2,%3;" : "=l"(d) : "l"(a), "l"(b), "l"(c)); return d;
}
__device__ __forceinline__ ull pack2(float x, float y) {
    ull d; asm("mov.b64 %0,{%1,%2};" : "=l"(d) : "f"(x), "f"(y)); return d;
}
__device__ __forceinline__ void unpack2(ull v, float& x, float& y) {
    asm("mov.b64 {%0,%1},%2;" : "=f"(x), "=f"(y) : "l"(v));
}

// ---------------- #1: fused prerounds + zero accumulators ----------------
__global__ __launch_bounds__(256) void prep_all_kernel(
    const float* __restrict__ a1, const float* __restrict__ w1,
    const float* __restrict__ q,  const float* __restrict__ wq,
    const float* __restrict__ wo, const float* __restrict__ woq,
    float* __restrict__ outq)
{
    const size_t n1 = (size_t)BLT * DM / 4;
    const size_t n2 = n1 + (size_t)NZ * DM / 4;
    const size_t n3 = n2 + (size_t)BB * NK * DM / 4;
    const size_t n4 = n3 + (size_t)DI * DM / 4;
    const size_t n5 = n4 + (size_t)DM * DI / 4;
    const size_t n6 = n5 + (size_t)DM * DI / 4;
    const size_t n7 = n6 + (size_t)BB * NK * DI / 4;
    const size_t n8 = n7 + (size_t)BB * NK * DM / 4;
    size_t i = (size_t)blockIdx.x * 256 + threadIdx.x;
    if (i >= n8) return;
    if (i >= n6) {
        float4 z = make_float4(0.f, 0.f, 0.f, 0.f);
        if (i < n7) ((float4*)g_h0)[i - n6] = z;
        else        ((float4*)outq)[i - n7] = z;
        return;
    }
    const float* src; float* dst; size_t off;
    if      (i < n1) { src = a1;  dst = g_rA1;  off = i; }
    else if (i < n2) { src = w1;  dst = g_rW1;  off = i - n1; }
    else if (i < n3) { src = q;   dst = g_rQ;   off = i - n2; }
    else if (i < n4) { src = wq;  dst = g_rWq;  off = i - n3; }
    else if (i < n5) { src = wo;  dst = g_rWo;  off = i - n4; }
    else             { src = woq; dst = g_rWoq; off = i - n5; }
    float4 v = ((const float4*)src)[off];
    v.x = to_tf32(v.x); v.y = to_tf32(v.y); v.z = to_tf32(v.z); v.w = to_tf32(v.w);
    ((float4*)dst)[off] = v;
}

// ---------------- tensor-core tf32 GEMM: 4 warps, 64x64 warp tile, 3-stage ----------------
#define KC 16
#define PADK 20
#define STAGE_B (128*PADK*4)
#define CHUNK_B (2*STAGE_B)
#define DSMEM_G (3*CHUNK_B)

__global__ __launch_bounds__(128, 2) void gemm_mma(const float* __restrict__ A,
                                                   const float* __restrict__ W,
                                                   float* __restrict__ C,
                                                   int M, int N, int K)
{
    extern __shared__ __align__(16) char dsm[];
    const int tid = threadIdx.x;
    const int lid = tid & 31, wrp = tid >> 5;
    const int wm = wrp & 1, wn = wrp >> 1;
    const int gid = lid >> 2, tig = lid & 3;
    const int m0 = blockIdx.y * 128, n0 = blockIdx.x * 128;
    const unsigned sbase = smem_u32(dsm);

    const int totCh = K >> 4;
    const int per = totCh / gridDim.z;
    const int cbase = blockIdx.z * per;
    const bool split = gridDim.z > 1;

    auto load_chunk = [&](int st, int ch) {
        const float* Ap = A + (size_t)m0 * K + ch * KC;
        const float* Wp = W + (size_t)n0 * K + ch * KC;
        unsigned ao = (unsigned)st * CHUNK_B;
        unsigned bo = ao + STAGE_B;
#pragma unroll
        for (int i = 0; i < 4; i++) {
            int idx = tid + i * 128;
            int row = idx >> 2, kg = idx & 3;
            unsigned so = (unsigned)(row * PADK * 4 + kg * 16);
            cpasync16(sbase + ao + so, Ap + (size_t)row * K + kg * 4);
            int nrow = n0 + row;
            int cl = (nrow < N) ? nrow : (N - 1);
            cpasync16z(sbase + bo + so, Wp + (size_t)(cl - n0) * K + kg * 4,
                       (nrow < N) ? 16u : 0u);
        }
        asm volatile("cp.async.commit_group;\n" ::: "memory");
    };

    float acc[4][8][4];
#pragma unroll
    for (int mf = 0; mf < 4; mf++)
#pragma unroll
        for (int nf = 0; nf < 8; nf++)
#pragma unroll
            for (int i = 0; i < 4; i++) acc[mf][nf][i] = 0.f;

    load_chunk(0, cbase);
    if (per > 1) load_chunk(1, cbase + 1);

    int st = 0;
    for (int c = 0; c < per; c++) {
        if (c + 1 < per) asm volatile("cp.async.wait_group 1;\n" ::: "memory");
        else             asm volatile("cp.async.wait_group 0;\n" ::: "memory");
        __syncthreads();
        if (c + 2 < per) {
            int st2 = st + 2; if (st2 >= 3) st2 -= 3;
            load_chunk(st2, cbase + c + 2);
        }
        const float* as = (const float*)(dsm + st * CHUNK_B);
        const float* bs = (const float*)(dsm + st * CHUNK_B + STAGE_B);
#pragma unroll
        for (int ks = 0; ks < 2; ks++) {
            int k0 = ks * 8;
            uint32_t af[4][4];
#pragma unroll
            for (int mf = 0; mf < 4; mf++) {
                int r = wm * 64 + mf * 16 + gid;
                af[mf][0] = __float_as_uint(as[r * PADK + k0 + tig]);
                af[mf][1] = __float_as_uint(as[(r + 8) * PADK + k0 + tig]);
                af[mf][2] = __float_as_uint(as[r * PADK + k0 + tig + 4]);
                af[mf][3] = __float_as_uint(as[(r + 8) * PADK + k0 + tig + 4]);
            }
#pragma unroll
            for (int nf = 0; nf < 8; nf++) {
                int nr = wn * 64 + nf * 8 + gid;
                uint32_t b0 = __float_as_uint(bs[nr * PADK + k0 + tig]);
                uint32_t b1 = __float_as_uint(bs[nr * PADK + k0 + tig + 4]);
#pragma unroll
                for (int mf = 0; mf < 4; mf++)
                    mma_tf32(acc[mf][nf], af[mf], b0, b1);
            }
        }
        if (++st >= 3) st = 0;
    }

#pragma unroll
    for (int mf = 0; mf < 4; mf++) {
        int r0 = m0 + wm * 64 + mf * 16 + gid;
#pragma unroll
        for (int nf = 0; nf < 8; nf++) {
            int col = n0 + wn * 64 + nf * 8 + tig * 2;
            if (col < N) {
                float* p0 = &C[(size_t)r0 * N + col];
                float* p1 = &C[(size_t)(r0 + 8) * N + col];
                if (!split) {
                    *(float2*)p0 = make_float2(acc[mf][nf][0], acc[mf][nf][1]);
                    *(float2*)p1 = make_float2(acc[mf][nf][2], acc[mf][nf][3]);
                } else {
                    atomicAdd(p0,     acc[mf][nf][0]);
                    atomicAdd(p0 + 1, acc[mf][nf][1]);
                    atomicAdd(p1,     acc[mf][nf][2]);
                    atomicAdd(p1 + 1, acc[mf][nf][3]);
                }
            }
        }
    }
}

// ---------------- #3: fused conv + dtbc (both depend only on g_zx) ----------------
#define CONV_BLKS (((CC + 255) / 256) * (LL / 8) * (2 * BB))   // 5 * 256 * 4 = 5120
#define DTBC_BLKS (BLT / 4)                                     // 1024

__global__ __launch_bounds__(256) void convdtbc_kernel(
    const float* __restrict__ cwf, const float* __restrict__ cbf,
    const float* __restrict__ cwb, const float* __restrict__ cbb,
    const float* __restrict__ dist, const float* __restrict__ bcw,
    const float* __restrict__ dtw, const float* __restrict__ dt_bias,
    const float* __restrict__ A_log)
{
    int bid = blockIdx.x;
    int tid = threadIdx.x;
    if (bid < CONV_BLKS) {
        // ---- depthwise conv7 + silu, sliding window ----
        int cblk = bid % 5;
        int rest = bid / 5;
        int l0 = (rest & 255) * 8;
        int db = rest >> 8;
        int dir = db >> 1, b = db & 1;
        int c = cblk * 256 + tid;
        if (c >= CC) return;

        const float* wsrc = (dir ? cwb : cwf) + c * 7;
        float wr[7];
#pragma unroll
        for (int t = 0; t < 7; t++) wr[t] = wsrc[t];
        float bias = (dir ? cbb : cbf)[c];

        const float* src = g_zx + (size_t)b * LL * NZ + DI + c;
        float win[14];
#pragma unroll
        for (int i = 0; i < 14; i++) {
            int l = l0 - 3 + i;
            win[i] = (0 <= l && l < LL) ? src[(size_t)l * NZ] : 0.f;
        }
        float* dst = (dir ? g_convb : g_convf) + ((size_t)b * LL + l0) * CC + c;
#pragma unroll
        for (int j = 0; j < 8; j++) {
            float acc = bias;
#pragma unroll
            for (int t = 0; t < 7; t++) acc = fmaf(wr[t], win[j + t], acc);
            float sig = 1.f / (1.f + __expf(-acc));
            dst[(size_t)j * CC] = acc * sig;
        }
        return;
    }
    {
        // ---- dtbc (computes own bias-channel convs inline; validated R9) ----
        int bl = (bid - CONV_BLKS) * 4 + (tid >> 6);
        int b = bl / LL, l = bl % LL;
        int k = tid & 63;

        float resf[2], resb[2];
        const float* zsrc = g_zx + (size_t)b * LL * NZ + 2 * DI;
#pragma unroll
        for (int ch = 0; ch < 2; ch++) {
            float af = cbf[1024 + ch], ab = cbb[1024 + ch];
#pragma unroll
            for (int t = 0; t < 7; t++) {
                int l2 = l + t - 3;
                if (0 <= l2 && l2 < LL) {
                    float v = zsrc[(size_t)l2 * NZ + ch];
                    af = fmaf(cwf[(1024 + ch) * 7 + t], v, af);
                    ab = fmaf(cwb[(1024 + ch) * 7 + t], v, ab);
                }
            }
            resf[ch] = af * (1.f / (1.f + __expf(-af)));
            resb[ch] = ab * (1.f / (1.f + __expf(-ab)));
        }
        float bbf = resf[0], cbfv = resf[1], bbb = resb[0], cbbv = resb[1];

        float4 d4 = *(const float4*)&dist[((size_t)bl * NK + k) * 4];
        float bb = d4.x * bcw[0] + d4.y * bcw[1] + d4.z * bcw[2] + d4.w * bcw[3];
        float cb = d4.x * bcw[4] + d4.y * bcw[5] + d4.z * bcw[6] + d4.w * bcw[7];
        g_Cf [(size_t)bl * NK + k] = cb + cbfv;
        g_Cb2[(size_t)bl * NK + k] = cb + cbbv;
        float Bf = bb + bbf, Bbk = bb + bbb;
        size_t zoff = (size_t)bl * NZ + 2 * DI + 2;
#pragma unroll
        for (int h = 0; h < NH; h++) {
            float pre = d4.x * dtw[h * 4 + 0] + d4.y * dtw[h * 4 + 1]
                      + d4.z * dtw[h * 4 + 2] + d4.w * dtw[h * 4 + 3]
                      + g_zx[zoff + h] + dt_bias[h];
            float dt = (pre > 20.f) ? pre : log1pf(__expf(pre));
            float Ah = -__expf(A_log[h]);
            float dA = __expf(dt * Ah);
            size_t o = (((size_t)(b * NH + h) * LL) + l) * NK + k;
            g_dA[o] = dA;
            g_uf[o] = dt * Bf;
            g_ub[o] = dt * Bbk;
        }
    }
}

// ================= chunked scan, n-major register layout =================
// P1 (#4, profiled): per (chunk, bh, dir): S = within-chunk scan from 0;
//     dir==0 blocks also compute P = prod(dA).
#define T1_DA 0
#define T1_U  2048
#define T1_X  4096     // 2 bufs x 2048
__global__ __launch_bounds__(128, 4) void scan_p1()
{
    __shared__ __align__(16) float sm1[8192];   // 32 KB
    int bid = blockIdx.x;            // c(16) x bh(16) x dir(2)
    int c   = bid & 15;
    int bh  = (bid >> 4) & 15;
    int dir = bid >> 8;
    int b = bh >> 3, h = bh & 7;
    int tid = threadIdx.x;           // = p

    const float* gdA = g_dA + ((size_t)bh * LL + (size_t)c * CHL) * NK;
    const float* gu  = (dir ? g_ub : g_uf) + ((size_t)bh * LL + (size_t)c * CHL) * NK;
    const float* gx  = (dir ? g_convb : g_convf)
                     + ((size_t)b * LL + (size_t)c * CHL) * CC + h * PP;

    ull hh[32];
#pragma unroll
    for (int i = 0; i < 32; i++) hh[i] = 0;
    ull Pa = pack2(1.f, 1.f), Pb = pack2(1.f, 1.f);

    auto load_tile = [&](int buf, int tile) {
        const float* da = gdA + (size_t)tile * 16 * NK;
        const float* uu = gu + (size_t)tile * 16 * NK;
        cpasync16(smem_u32(&sm1[T1_DA + buf * 1024 + tid * 8]),     da + tid * 8);
        cpasync16(smem_u32(&sm1[T1_DA + buf * 1024 + tid * 8 + 4]), da + tid * 8 + 4);
        cpasync16(smem_u32(&sm1[T1_U  + buf * 1024 + tid * 8]),     uu + tid * 8);
        cpasync16(smem_u32(&sm1[T1_U  + buf * 1024 + tid * 8 + 4]), uu + tid * 8 + 4);
        // x rows: stride CC=1026 floats (8B-aligned only) -> 8-byte cp.async
#pragma unroll
        for (int i = 0; i < 4; i++) {
            int idx = tid + i * 128;
            int row = idx >> 5, c4 = idx & 31;
            const float* xs = gx + (size_t)(tile * 16 + row) * CC + c4 * 4;
            unsigned sd = smem_u32(&sm1[T1_X + buf * 2048 + row * 128 + c4 * 4]);
            cpasync8(sd, xs);
            cpasync8(sd + 8, xs + 2);
        }
        asm volatile("cp.async.commit_group;\n");
    };

    load_tile(0, dir ? 7 : 0);
    for (int s = 0; s < 8; s++) {
        if (s + 1 < 8) {
            load_tile((s + 1) & 1, dir ? 6 - s : s + 1);
            asm volatile("cp.async.wait_group 1;\n");
        } else {
            asm volatile("cp.async.wait_group 0;\n");
        }
        __syncthreads();
        int buf = s & 1;
#pragma unroll 2
        for (int j = 0; j < 16; j++) {
            int tt = dir ? (15 - j) : j;
            float xp = sm1[T1_X + buf * 2048 + tt * 128 + tid];
            ull xx = pack2(xp, xp);
            const float* da = &sm1[T1_DA + buf * 1024 + tt * 64];
            const float* uu = &sm1[T1_U  + buf * 1024 + tt * 64];
#pragma unroll
            for (int i = 0; i < 16; i++) {
                ulonglong2 av = *(const ulonglong2*)&da[i * 4];
                ulonglong2 uv = *(const ulonglong2*)&uu[i * 4];
                hh[2 * i]     = fma2(av.x, hh[2 * i],     mul2(uv.x, xx));
                hh[2 * i + 1] = fma2(av.y, hh[2 * i + 1], mul2(uv.y, xx));
            }
            if (dir == 0 && tid < 16) {
                ulonglong2 av = *(const ulonglong2*)&da[tid * 4];
                Pa = mul2(Pa, av.x);
                Pb = mul2(Pb, av.y);
            }
        }
        __syncthreads();
    }
    float* S = (dir ? g_Sb : g_Sf) + (((size_t)bh * NCH + c) * PP + tid) * NK;
#pragma unroll
    for (int i = 0; i < 16; i++)
        *(ulonglong2*)&S[i * 4] = make_ulonglong2(hh[2 * i], hh[2 * i + 1]);
    if (dir == 0 && tid < 16)
        *(ulonglong2*)&g_P[((size_t)bh * NCH + c) * NK + tid * 4] =
            make_ulonglong2(Pa, Pb);
}

// P2: combine chunks serially per (p, n), both directions.
__global__ __launch_bounds__(256) void scan_p2()
{
    int bid = blockIdx.x;          // 128: bh(16) x pblk(8)
    int pblk = bid & 7, bh = bid >> 3;
    int b = bh >> 3, h = bh & 7;
    int tid = threadIdx.x;
    int q = tid & 15, pl = tid >> 4;
    int p = pblk * 16 + pl;

    ull h01, h23;
    {
        const float* hp = g_h0 + (size_t)b * NK * DI + h * PP + p;
        h01 = pack2(hp[(size_t)(4 * q + 0) * DI], hp[(size_t)(4 * q + 1) * DI]);
        h23 = pack2(hp[(size_t)(4 * q + 2) * DI], hp[(size_t)(4 * q + 3) * DI]);
    }
    {
        ull a01 = h01, a23 = h23;
        for (int c = 0; c < NCH; c++) {
            size_t ho = (((size_t)bh * NCH + c) * PP + p) * NK + 4 * q;
            *(ulonglong2*)&g_hsf[ho] = make_ulonglong2(a01, a23);
            ulonglong2 P2 = *(const ulonglong2*)&g_P[((size_t)bh * NCH + c) * NK + 4 * q];
            ulonglong2 S2 = *(const ulonglong2*)&g_Sf[ho];
            a01 = fma2(P2.x, a01, S2.x);
            a23 = fma2(P2.y, a23, S2.y);
        }
        float f0, f1, f2, f3;
        unpack2(a01, f0, f1); unpack2(a23, f2, f3);
        float* gh = g_hf + ((size_t)bh * PP + p) * NK + 4 * q;
        gh[0] = f0; gh[1] = f1; gh[2] = f2; gh[3] = f3;
    }
    {
        ull a01 = h01, a23 = h23;
        for (int c = NCH - 1; c >= 0; c--) {
            size_t ho = (((size_t)bh * NCH + c) * PP + p) * NK + 4 * q;
            *(ulonglong2*)&g_hsb[ho] = make_ulonglong2(a01, a23);
            ulonglong2 P2 = *(const ulonglong2*)&g_P[((size_t)bh * NCH + c) * NK + 4 * q];
            ulonglong2 S2 = *(const ulonglong2*)&g_Sb[ho];
            a01 = fma2(P2.x, a01, S2.x);
            a23 = fma2(P2.y, a23, S2.y);
        }
        float f0, f1, f2, f3;
        unpack2(a01, f0, f1); unpack2(a23, f2, f3);
        float* gh = g_hb + ((size_t)bh * PP + p) * NK + 4 * q;
        gh[0] = f0; gh[1] = f1; gh[2] = f2; gh[3] = f3;
    }
}

// P3: within-chunk scan with true entry state, full n in regs, y emitted directly.
#define T3_DA 0
#define T3_U  2048
#define T3_C  4096
#define T3_X  6144     // 2 bufs x 2048
__global__ __launch_bounds__(128, 4) void scan_p3()
{
    __shared__ __align__(16) float sm3[10240];  // 40 KB
    int bid = blockIdx.x;            // c(16) x bh(16) x dir(2)
    int c   = bid & 15;
    int bh  = (bid >> 4) & 15;
    int dir = bid >> 8;
    int b = bh >> 3, h = bh & 7;
    int tid = threadIdx.x;           // = p

    const float* gdA = g_dA + ((size_t)bh * LL + (size_t)c * CHL) * NK;
    const float* gu  = (dir ? g_ub : g_uf) + ((size_t)bh * LL + (size_t)c * CHL) * NK;
    const float* gC  = (dir ? g_Cb2 : g_Cf) + ((size_t)b * LL + (size_t)c * CHL) * NK;
    const float* gx  = (dir ? g_convb : g_convf)
                     + ((size_t)b * LL + (size_t)c * CHL) * CC + h * PP;
    float* gy = (dir ? g_yb : g_yf)
              + ((size_t)b * LL + (size_t)c * CHL) * DI + h * PP + tid;

    ull hh[32];
    {
        const float* hs = (dir ? g_hsb : g_hsf)
                        + (((size_t)bh * NCH + c) * PP + tid) * NK;
#pragma unroll
        for (int i = 0; i < 16; i++) {
            ulonglong2 v = *(const ulonglong2*)&hs[i * 4];
            hh[2 * i] = v.x; hh[2 * i + 1] = v.y;
        }
    }

    auto load_tile = [&](int buf, int tile) {
        const float* da = gdA + (size_t)tile * 16 * NK;
        const float* uu = gu + (size_t)tile * 16 * NK;
        const float* cc = gC + (size_t)tile * 16 * NK;
        cpasync16(smem_u32(&sm3[T3_DA + buf * 1024 + tid * 8]),     da + tid * 8);
        cpasync16(smem_u32(&sm3[T3_DA + buf * 1024 + tid * 8 + 4]), da + tid * 8 + 4);
        cpasync16(smem_u32(&sm3[T3_U  + buf * 1024 + tid * 8]),     uu + tid * 8);
        cpasync16(smem_u32(&sm3[T3_U  + buf * 1024 + tid * 8 + 4]), uu + tid * 8 + 4);
        cpasync16(smem_u32(&sm3[T3_C  + buf * 1024 + tid * 8]),     cc + tid * 8);
        cpasync16(smem_u32(&sm3[T3_C  + buf * 1024 + tid * 8 + 4]), cc + tid * 8 + 4);
        // x rows: stride CC=1026 floats (8B-aligned only) -> 8-byte cp.async
#pragma unroll
        for (int i = 0; i < 4; i++) {
            int idx = tid + i * 128;
            int row = idx >> 5, c4 = idx & 31;
            const float* xs = gx + (size_t)(tile * 16 + row) * CC + c4 * 4;
            unsigned sd = smem_u32(&sm3[T3_X + buf * 2048 + row * 128 + c4 * 4]);
            cpasync8(sd, xs);
            cpasync8(sd + 8, xs + 2);
        }
        asm volatile("cp.async.commit_group;\n");
    };

    load_tile(0, dir ? 7 : 0);
    for (int s = 0; s < 8; s++) {
        if (s + 1 < 8) {
            load_tile((s + 1) & 1, dir ? 6 - s : s + 1);
            asm volatile("cp.async.wait_group 1;\n");
        } else {
            asm volatile("cp.async.wait_group 0;\n");
        }
        __syncthreads();
        int buf = s & 1;
        int tile = dir ? 7 - s : s;
#pragma unroll 2
        for (int j = 0; j < 16; j++) {
            int tt = dir ? (15 - j) : j;
            float xp = sm3[T3_X + buf * 2048 + tt * 128 + tid];
            ull xx = pack2(xp, xp);
            const float* da = &sm3[T3_DA + buf * 1024 + tt * 64];
            const float* uu = &sm3[T3_U  + buf * 1024 + tt * 64];
            const float* cv = &sm3[T3_C  + buf * 1024 + tt * 64];
            ull acc0 = 0, acc1 = 0, acc2 = 0, acc3 = 0;
#pragma unroll
            for (int i = 0; i < 16; i++) {
                ulonglong2 av = *(const ulonglong2*)&da[i * 4];
                ulonglong2 uv = *(const ulonglong2*)&uu[i * 4];
                ulonglong2 c2 = *(const ulonglong2*)&cv[i * 4];
                hh[2 * i]     = fma2(av.x, hh[2 * i],     mul2(uv.x, xx));
                hh[2 * i + 1] = fma2(av.y, hh[2 * i + 1], mul2(uv.y, xx));
                if (i & 1) {
                    acc2 = fma2(c2.x, hh[2 * i], acc2);
                    acc3 = fma2(c2.y, hh[2 * i + 1], acc3);
                } else {
                    acc0 = fma2(c2.x, hh[2 * i], acc0);
                    acc1 = fma2(c2.y, hh[2 * i + 1], acc1);
                }
            }
            float a, bq, cq, d, e, f, g2, h2;
            unpack2(acc0, a, bq); unpack2(acc1, cq, d);
            unpack2(acc2, e, f);  unpack2(acc3, g2, h2);
            float y = ((a + bq) + (cq + d)) + ((e + f) + (g2 + h2));
            gy[(size_t)(tile * 16 + tt) * DI] = y;
        }
        __syncthreads();
    }
}

// ---------------- combine y, gate with silu(z), RMSNorm (tf32 out) ----------------
__global__ __launch_bounds__(256) void gate_norm_key_kernel(const float* __restrict__ Dp,
                                                            const float* __restrict__ normw)
{
    int bl = blockIdx.x;
    int tid = threadIdx.x;
    __shared__ float s_v[DI];
    __shared__ float sred[9];
    float ss = 0.f;
    size_t byDI = (size_t)bl * DI, byCC = (size_t)bl * CC, byNZ = (size_t)bl * NZ;
#pragma unroll
    for (int it = 0; it < 4; it++) {
        int i = tid + it * 256;
        int hh = i >> 7;
        float y = 0.5f * (g_yf[byDI + i] + g_yb[byDI + i])
                + 0.5f * Dp[hh] * (g_convf[byCC + i] + g_convb[byCC + i]);
        float z = g_zx[byNZ + i];
        float xg = y * z * (1.f / (1.f + __expf(-z)));
        s_v[i] = xg;
        ss += xg * xg;
    }
    for (int o = 16; o; o >>= 1) ss += __shfl_xor_sync(0xffffffffu, ss, o);
    if ((tid & 31) == 0) sred[tid >> 5] = ss;
    __syncthreads();
    if (tid == 0) {
        float t = 0.f;
        for (int w = 0; w < 8; w++) t += sred[w];
        sred[8] = rsqrtf(t * (1.f / DI) + 1e-5f);
    }
    __syncthreads();
    float sc = sred[8];
#pragma unroll
    for (int it = 0; it < 4; it++) {
        int i = tid + it * 256;
        g_xg[byDI + i] = to_tf32(s_v[i] * sc * normw[i]);
    }
}

// ---------------- query path: average final states, LayerNorm (tf32 out) ----------------
__global__ __launch_bounds__(256) void qnorm_kernel(const float* __restrict__ w,
                                                    const float* __restrict__ bi)
{
    int bk = blockIdx.x;
    int b = bk >> 6, k = bk & 63;
    int tid = threadIdx.x;
    __shared__ float s_v[DI];
    __shared__ float sred[18];
    float s1 = 0.f, s2 = 0.f;
#pragma unroll
    for (int it = 0; it < 4; it++) {
        int i = tid + it * 256;
        int hh = i >> 7, p = i & 127;
        size_t o = ((size_t)(b * NH + hh) * PP + p) * NK + k;
        float qv = 0.5f * (g_hf[o] + g_hb[o]);
        s_v[i] = qv;
        s1 += qv;
        s2 += qv * qv;
    }
    for (int o = 16; o; o >>= 1) {
        s1 += __shfl_xor_sync(0xffffffffu, s1, o);
        s2 += __shfl_xor_sync(0xffffffffu, s2, o);
    }
    if ((tid & 31) == 0) { sred[tid >> 5] = s1; sred[8 + (tid >> 5)] = s2; }
    __syncthreads();
    if (tid == 0) {
        float t1 = 0.f, t2 = 0.f;
        for (int wv = 0; wv < 8; wv++) { t1 += sred[wv]; t2 += sred[8 + wv]; }
        float mu = t1 * (1.f / DI);
        float var = t2 * (1.f / DI) - mu * mu;
        sred[16] = mu;
        sred[17] = rsqrtf(var + 1e-5f);
    }
    __syncthreads();
    float mu = sred[16], rs = sred[17];
#pragma unroll
    for (int it = 0; it < 4; it++) {
        int i = tid + it * 256;
        g_qn[(size_t)bk * DI + i] = to_tf32((s_v[i] - mu) * rs * w[i] + bi[i]);
    }
}

// ---------------- host launcher ----------------
extern "C" void kernel_launch(void* const* d_in, const int* in_sizes, int n_in,
                              void* d_out, int out_size)
{
    (void)in_sizes; (void)n_in; (void)out_size;
    const float* in_key      = (const float*)d_in[0];
    const float* in_query    = (const float*)d_in[1];
    const float* dist        = (const float*)d_in[2];
    const float* key_proj_w  = (const float*)d_in[4];
    const float* key_conv_w  = (const float*)d_in[5];
    const float* key_conv_b  = (const float*)d_in[6];
    const float* key_conv_bw = (const float*)d_in[7];
    const float* key_conv_bb = (const float*)d_in[8];
    const float* query_proj_w= (const float*)d_in[9];
    const float* bc_proj_w   = (const float*)d_in[10];
    const float* dt_proj_w   = (const float*)d_in[11];
    const float* dt_bias     = (const float*)d_in[12];
    const float* A_log       = (const float*)d_in[13];
    const float* D_param     = (const float*)d_in[14];
    const float* out_key_w   = (const float*)d_in[15];
    const float* out_query_w = (const float*)d_in[16];
    const float* key_norm_w  = (const float*)d_in[17];
    const float* q_ln_w      = (const float*)d_in[18];
    const float* q_ln_b      = (const float*)d_in[19];
    float* out = (float*)d_out;

    void *p_zx, *p_h0, *p_xg, *p_qn;
    void *p_rA1, *p_rW1, *p_rQ, *p_rWq, *p_rWo, *p_rWoq;
    cudaGetSymbolAddress(&p_zx, g_zx);
    cudaGetSymbolAddress(&p_h0, g_h0);
    cudaGetSymbolAddress(&p_xg, g_xg);
    cudaGetSymbolAddress(&p_qn, g_qn);
    cudaGetSymbolAddress(&p_rA1, g_rA1);
    cudaGetSymbolAddress(&p_rW1, g_rW1);
    cudaGetSymbolAddress(&p_rQ, g_rQ);
    cudaGetSymbolAddress(&p_rWq, g_rWq);
    cudaGetSymbolAddress(&p_rWo, g_rWo);
    cudaGetSymbolAddress(&p_rWoq, g_rWoq);

    cudaFuncSetAttribute(gemm_mma, cudaFuncAttributeMaxDynamicSharedMemorySize, DSMEM_G);

    // #1: fused prerounds + zeros
    {
        size_t n = ((size_t)BLT * DM + (size_t)NZ * DM + (size_t)BB * NK * DM
                    + (size_t)DI * DM + 2ull * DM * DI
                    + (size_t)BB * NK * DI + (size_t)BB * NK * DM) / 4;
        prep_all_kernel<<<(int)((n + 255) / 256), 256>>>(
            in_key, key_proj_w, in_query, query_proj_w, out_key_w, out_query_w,
            out + (size_t)BLT * DM);
    }
    // #2: zxbcdt = in_key @ key_proj_w^T
    {
        dim3 grid((NZ + 127) / 128, BLT / 128, 1);
        gemm_mma<<<grid, 128, DSMEM_G>>>((const float*)p_rA1, (const float*)p_rW1,
                                         (float*)p_zx, BLT, NZ, DM);
    }
    // #3: fused conv + dtbc
    convdtbc_kernel<<<CONV_BLKS + DTBC_BLKS, 256>>>(
        key_conv_w, key_conv_b, key_conv_bw, key_conv_bb,
        dist, bc_proj_w, dt_proj_w, dt_bias, A_log);
    // #4 (ncu captures this): scan P1
    scan_p1<<<512, 128>>>();
    // #5: h0 = in_query @ query_proj_w^T, split-K x4 (needed by P2)
    {
        dim3 grid(DI / 128, 1, 4);
        gemm_mma<<<grid, 128, DSMEM_G>>>((const float*)p_rQ, (const float*)p_rWq,
                                         (float*)p_h0, BB * NK, DI, DM);
    }
    // #6: scan P2
    scan_p2<<<128, 256>>>();
    // #7: scan P3
    scan_p3<<<512, 128>>>();
    // #8: combine + gate + RMSNorm
    gate_norm_key_kernel<<<BLT, 256>>>(D_param, key_norm_w);
    // #9: out_key = key_n @ out_key_w^T
    {
        dim3 grid(DM / 128, BLT / 128, 1);
        gemm_mma<<<grid, 128, DSMEM_G>>>((const float*)p_xg, (const float*)p_rWo,
                                         out, BLT, DM, DI);
    }
    // #10: query layer norm
    qnorm_kernel<<<BB * NK, 256>>>(q_ln_w, q_ln_b);
    // #11: out_query = qn @ out_query_w^T, split-K x8
    {
        dim3 grid(DM / 128, 1, 8);
        gemm_mma<<<grid, 128, DSMEM_G>>>((const float*)p_qn, (const float*)p_rWoq,
                                         out + (size_t)BLT * DM, BB * NK, DM, DI);
    }
}

// round 14
// speedup vs baseline: 1.4884x; 1.0929x over previous
#include <cuda_runtime.h>
#include <cuda_bf16.h>
#include <cstdint>

// ---------------- problem constants ----------------
#define BB 2
#define LL 2048
#define NK 64
#define DM 512
#define DI 1024
#define NH 8
#define PP 128
#define NZ 2058
#define CC 1026
#define BLT (BB*LL)
#define NCH 16
#define CHL 128

typedef unsigned long long ull;

// ---------------- scratch ----------------
__device__ float g_zx   [(size_t)BB*LL*NZ];
__device__ float g_convf[(size_t)BB*LL*CC];
__device__ float g_convb[(size_t)BB*LL*CC];
__device__ float g_dA   [(size_t)BB*NH*LL*NK];
__device__ float g_uf   [(size_t)BB*NH*LL*NK];
__device__ float g_ub   [(size_t)BB*NH*LL*NK];
__device__ float g_Cf   [(size_t)BB*LL*NK];
__device__ float g_Cb2  [(size_t)BB*LL*NK];
__device__ float g_h0   [(size_t)BB*NK*DI];
__device__ float g_yf   [(size_t)BB*LL*DI];
__device__ float g_yb   [(size_t)BB*LL*DI];
__device__ float g_hf   [(size_t)BB*NH*PP*NK];
__device__ float g_hb   [(size_t)BB*NH*PP*NK];
__device__ float g_xg   [(size_t)BB*LL*DI];
__device__ float g_qn   [(size_t)BB*NK*DI];
// chunked-scan intermediates
__device__ float g_Sf  [(size_t)16*NCH*NK*PP];   // [bh][c][n][p]
__device__ float g_Sb  [(size_t)16*NCH*NK*PP];
__device__ float g_P   [(size_t)16*NCH*NK];
__device__ float g_hsf [(size_t)16*NCH*PP*NK];   // [bh][c][p][n]
__device__ float g_hsb [(size_t)16*NCH*PP*NK];
__device__ float g_wf  [(size_t)16*NCH*NK*CHL];  // [bh][c][n][t], tf32
__device__ float g_wb  [(size_t)16*NCH*NK*CHL];
__device__ float g_xTf [(size_t)16*PP*LL];       // [bh][p][t], tf32
__device__ float g_xTb [(size_t)16*PP*LL];
// tf32-rounded copies of GEMM inputs
__device__ float g_rA1 [(size_t)BLT*DM];
__device__ float g_rW1 [(size_t)NZ*DM];
__device__ float g_rQ  [(size_t)BB*NK*DM];
__device__ float g_rWq [(size_t)DI*DM];
__device__ float g_rWo [(size_t)DM*DI];
__device__ float g_rWoq[(size_t)DM*DI];

// ---------------- helpers ----------------
__device__ __forceinline__ unsigned smem_u32(const void* p) {
    return (unsigned)__cvta_generic_to_shared(p);
}
__device__ __forceinline__ void cpasync16(unsigned s, const void* g) {
    asm volatile("cp.async.cg.shared.global [%0],[%1],16;\n" ::"r"(s), "l"(g));
}
__device__ __forceinline__ void cpasync16z(unsigned s, const void* g, unsigned srcsz) {
    asm volatile("cp.async.cg.shared.global [%0],[%1],16,%2;\n" ::"r"(s), "l"(g), "r"(srcsz));
}
__device__ __forceinline__ void cpasync8(unsigned s, const void* g) {
    asm volatile("cp.async.ca.shared.global [%0],[%1],8;\n" ::"r"(s), "l"(g));
}
__device__ __forceinline__ float to_tf32(float x) {
    float r; asm("cvt.rna.tf32.f32 %0,%1;" : "=f"(r) : "f"(x)); return r;
}
__device__ __forceinline__ void mma_tf32(float* c, const uint32_t* a, uint32_t b0, uint32_t b1) {
    asm volatile(
        "mma.sync.aligned.m16n8k8.row.col.f32.tf32.tf32.f32 "
        "{%0,%1,%2,%3}, {%4,%5,%6,%7}, {%8,%9}, {%0,%1,%2,%3};"
        : "+f"(c[0]), "+f"(c[1]), "+f"(c[2]), "+f"(c[3])
        : "r"(a[0]), "r"(a[1]), "r"(a[2]), "r"(a[3]), "r"(b0), "r"(b1));
}
__device__ __forceinline__ ull mul2(ull a, ull b) {
    ull d; asm("mul.rn.f32x2 %0,%1,%2;" : "=l"(d) : "l"(a), "l"(b)); return d;
}
__device__ __forceinline__ ull fma2(ull a, ull b, ull c) {
    ull d; asm("fma.rn.f32x2 %0,%1,%2,%3;" : "=l"(d) : "l"(a), "l"(b), "l"(c)); return d;
}
__device__ __forceinline__ ull pack2(float x, float y) {
    ull d; asm("mov.b64 %0,{%1,%2};" : "=l"(d) : "f"(x), "f"(y)); return d;
}
__device__ __forceinline__ void unpack2(ull v, float& x, float& y) {
    asm("mov.b64 {%0,%1},%2;" : "=f"(x), "=f"(y) : "l"(v));
}

// ---------------- #1: fused prerounds + zero accumulators ----------------
__global__ __launch_bounds__(256) void prep_all_kernel(
    const float* __restrict__ a1, const float* __restrict__ w1,
    const float* __restrict__ q,  const float* __restrict__ wq,
    const float* __restrict__ wo, const float* __restrict__ woq,
    float* __restrict__ outq)
{
    const size_t n1 = (size_t)BLT * DM / 4;
    const size_t n2 = n1 + (size_t)NZ * DM / 4;
    const size_t n3 = n2 + (size_t)BB * NK * DM / 4;
    const size_t n4 = n3 + (size_t)DI * DM / 4;
    const size_t n5 = n4 + (size_t)DM * DI / 4;
    const size_t n6 = n5 + (size_t)DM * DI / 4;
    const size_t n7 = n6 + (size_t)BB * NK * DI / 4;
    const size_t n8 = n7 + (size_t)BB * NK * DM / 4;
    size_t i = (size_t)blockIdx.x * 256 + threadIdx.x;
    if (i >= n8) return;
    if (i >= n6) {
        float4 z = make_float4(0.f, 0.f, 0.f, 0.f);
        if (i < n7) ((float4*)g_h0)[i - n6] = z;
        else        ((float4*)outq)[i - n7] = z;
        return;
    }
    const float* src; float* dst; size_t off;
    if      (i < n1) { src = a1;  dst = g_rA1;  off = i; }
    else if (i < n2) { src = w1;  dst = g_rW1;  off = i - n1; }
    else if (i < n3) { src = q;   dst = g_rQ;   off = i - n2; }
    else if (i < n4) { src = wq;  dst = g_rWq;  off = i - n3; }
    else if (i < n5) { src = wo;  dst = g_rWo;  off = i - n4; }
    else             { src = woq; dst = g_rWoq; off = i - n5; }
    float4 v = ((const float4*)src)[off];
    v.x = to_tf32(v.x); v.y = to_tf32(v.y); v.z = to_tf32(v.z); v.w = to_tf32(v.w);
    ((float4*)dst)[off] = v;
}

// ---------------- tensor-core tf32 GEMM (unchanged, 4 warps, 3-stage) ----------------
#define KC 16
#define PADK 20
#define STAGE_B (128*PADK*4)
#define CHUNK_B (2*STAGE_B)
#define DSMEM_G (3*CHUNK_B)

__global__ __launch_bounds__(128, 2) void gemm_mma(const float* __restrict__ A,
                                                   const float* __restrict__ W,
                                                   float* __restrict__ C,
                                                   int M, int N, int K)
{
    extern __shared__ __align__(16) char dsm[];
    const int tid = threadIdx.x;
    const int lid = tid & 31, wrp = tid >> 5;
    const int wm = wrp & 1, wn = wrp >> 1;
    const int gid = lid >> 2, tig = lid & 3;
    const int m0 = blockIdx.y * 128, n0 = blockIdx.x * 128;
    const unsigned sbase = smem_u32(dsm);

    const int totCh = K >> 4;
    const int per = totCh / gridDim.z;
    const int cbase = blockIdx.z * per;
    const bool split = gridDim.z > 1;

    auto load_chunk = [&](int st, int ch) {
        const float* Ap = A + (size_t)m0 * K + ch * KC;
        const float* Wp = W + (size_t)n0 * K + ch * KC;
        unsigned ao = (unsigned)st * CHUNK_B;
        unsigned bo = ao + STAGE_B;
#pragma unroll
        for (int i = 0; i < 4; i++) {
            int idx = tid + i * 128;
            int row = idx >> 2, kg = idx & 3;
            unsigned so = (unsigned)(row * PADK * 4 + kg * 16);
            cpasync16(sbase + ao + so, Ap + (size_t)row * K + kg * 4);
            int nrow = n0 + row;
            int cl = (nrow < N) ? nrow : (N - 1);
            cpasync16z(sbase + bo + so, Wp + (size_t)(cl - n0) * K + kg * 4,
                       (nrow < N) ? 16u : 0u);
        }
        asm volatile("cp.async.commit_group;\n" ::: "memory");
    };

    float acc[4][8][4];
#pragma unroll
    for (int mf = 0; mf < 4; mf++)
#pragma unroll
        for (int nf = 0; nf < 8; nf++)
#pragma unroll
            for (int i = 0; i < 4; i++) acc[mf][nf][i] = 0.f;

    load_chunk(0, cbase);
    if (per > 1) load_chunk(1, cbase + 1);

    int st = 0;
    for (int c = 0; c < per; c++) {
        if (c + 1 < per) asm volatile("cp.async.wait_group 1;\n" ::: "memory");
        else             asm volatile("cp.async.wait_group 0;\n" ::: "memory");
        __syncthreads();
        if (c + 2 < per) {
            int st2 = st + 2; if (st2 >= 3) st2 -= 3;
            load_chunk(st2, cbase + c + 2);
        }
        const float* as = (const float*)(dsm + st * CHUNK_B);
        const float* bs = (const float*)(dsm + st * CHUNK_B + STAGE_B);
#pragma unroll
        for (int ks = 0; ks < 2; ks++) {
            int k0 = ks * 8;
            uint32_t af[4][4];
#pragma unroll
            for (int mf = 0; mf < 4; mf++) {
                int r = wm * 64 + mf * 16 + gid;
                af[mf][0] = __float_as_uint(as[r * PADK + k0 + tig]);
                af[mf][1] = __float_as_uint(as[(r + 8) * PADK + k0 + tig]);
                af[mf][2] = __float_as_uint(as[r * PADK + k0 + tig + 4]);
                af[mf][3] = __float_as_uint(as[(r + 8) * PADK + k0 + tig + 4]);
            }
#pragma unroll
            for (int nf = 0; nf < 8; nf++) {
                int nr = wn * 64 + nf * 8 + gid;
                uint32_t b0 = __float_as_uint(bs[nr * PADK + k0 + tig]);
                uint32_t b1 = __float_as_uint(bs[nr * PADK + k0 + tig + 4]);
#pragma unroll
                for (int mf = 0; mf < 4; mf++)
                    mma_tf32(acc[mf][nf], af[mf], b0, b1);
            }
        }
        if (++st >= 3) st = 0;
    }

#pragma unroll
    for (int mf = 0; mf < 4; mf++) {
        int r0 = m0 + wm * 64 + mf * 16 + gid;
#pragma unroll
        for (int nf = 0; nf < 8; nf++) {
            int col = n0 + wn * 64 + nf * 8 + tig * 2;
            if (col < N) {
                float* p0 = &C[(size_t)r0 * N + col];
                float* p1 = &C[(size_t)(r0 + 8) * N + col];
                if (!split) {
                    *(float2*)p0 = make_float2(acc[mf][nf][0], acc[mf][nf][1]);
                    *(float2*)p1 = make_float2(acc[mf][nf][2], acc[mf][nf][3]);
                } else {
                    atomicAdd(p0,     acc[mf][nf][0]);
                    atomicAdd(p0 + 1, acc[mf][nf][1]);
                    atomicAdd(p1,     acc[mf][nf][2]);
                    atomicAdd(p1 + 1, acc[mf][nf][3]);
                }
            }
        }
    }
}

// ---------------- #3: fused conv + dtbc ----------------
#define CONV_BLKS (((CC + 255) / 256) * (LL / 8) * (2 * BB))
#define DTBC_BLKS (BLT / 4)

__global__ __launch_bounds__(256) void convdtbc_kernel(
    const float* __restrict__ cwf, const float* __restrict__ cbf,
    const float* __restrict__ cwb, const float* __restrict__ cbb,
    const float* __restrict__ dist, const float* __restrict__ bcw,
    const float* __restrict__ dtw, const float* __restrict__ dt_bias,
    const float* __restrict__ A_log)
{
    int bid = blockIdx.x;
    int tid = threadIdx.x;
    if (bid < CONV_BLKS) {
        int cblk = bid % 5;
        int rest = bid / 5;
        int l0 = (rest & 255) * 8;
        int db = rest >> 8;
        int dir = db >> 1, b = db & 1;
        int c = cblk * 256 + tid;
        if (c >= CC) return;

        const float* wsrc = (dir ? cwb : cwf) + c * 7;
        float wr[7];
#pragma unroll
        for (int t = 0; t < 7; t++) wr[t] = wsrc[t];
        float bias = (dir ? cbb : cbf)[c];

        const float* src = g_zx + (size_t)b * LL * NZ + DI + c;
        float win[14];
#pragma unroll
        for (int i = 0; i < 14; i++) {
            int l = l0 - 3 + i;
            win[i] = (0 <= l && l < LL) ? src[(size_t)l * NZ] : 0.f;
        }
        float* dst = (dir ? g_convb : g_convf) + ((size_t)b * LL + l0) * CC + c;
#pragma unroll
        for (int j = 0; j < 8; j++) {
            float acc = bias;
#pragma unroll
            for (int t = 0; t < 7; t++) acc = fmaf(wr[t], win[j + t], acc);
            float sig = 1.f / (1.f + __expf(-acc));
            dst[(size_t)j * CC] = acc * sig;
        }
        return;
    }
    {
        int bl = (bid - CONV_BLKS) * 4 + (tid >> 6);
        int b = bl / LL, l = bl % LL;
        int k = tid & 63;

        float resf[2], resb[2];
        const float* zsrc = g_zx + (size_t)b * LL * NZ + 2 * DI;
#pragma unroll
        for (int ch = 0; ch < 2; ch++) {
            float af = cbf[1024 + ch], ab = cbb[1024 + ch];
#pragma unroll
            for (int t = 0; t < 7; t++) {
                int l2 = l + t - 3;
                if (0 <= l2 && l2 < LL) {
                    float v = zsrc[(size_t)l2 * NZ + ch];
                    af = fmaf(cwf[(1024 + ch) * 7 + t], v, af);
                    ab = fmaf(cwb[(1024 + ch) * 7 + t], v, ab);
                }
            }
            resf[ch] = af * (1.f / (1.f + __expf(-af)));
            resb[ch] = ab * (1.f / (1.f + __expf(-ab)));
        }
        float bbf = resf[0], cbfv = resf[1], bbb = resb[0], cbbv = resb[1];

        float4 d4 = *(const float4*)&dist[((size_t)bl * NK + k) * 4];
        float bb = d4.x * bcw[0] + d4.y * bcw[1] + d4.z * bcw[2] + d4.w * bcw[3];
        float cb = d4.x * bcw[4] + d4.y * bcw[5] + d4.z * bcw[6] + d4.w * bcw[7];
        g_Cf [(size_t)bl * NK + k] = cb + cbfv;
        g_Cb2[(size_t)bl * NK + k] = cb + cbbv;
        float Bf = bb + bbf, Bbk = bb + bbb;
        size_t zoff = (size_t)bl * NZ + 2 * DI + 2;
#pragma unroll
        for (int h = 0; h < NH; h++) {
            float pre = d4.x * dtw[h * 4 + 0] + d4.y * dtw[h * 4 + 1]
                      + d4.z * dtw[h * 4 + 2] + d4.w * dtw[h * 4 + 3]
                      + g_zx[zoff + h] + dt_bias[h];
            float dt = (pre > 20.f) ? pre : log1pf(__expf(pre));
            float Ah = -__expf(A_log[h]);
            float dA = __expf(dt * Ah);
            size_t o = (((size_t)(b * NH + h) * LL) + l) * NK + k;
            g_dA[o] = dA;
            g_uf[o] = dt * Bf;
            g_ub[o] = dt * Bbk;
        }
    }
}

// ---------------- #4 (profiled): w-prep — running dA products x u, plus P ----------------
// 512 blocks: bh(16) x c(16) x dir(2), 64 threads = n lanes.
__global__ __launch_bounds__(64) void wprep_kernel()
{
    int bid = blockIdx.x;
    int dir = bid & 1;
    int c   = (bid >> 1) & 15;
    int bh  = bid >> 5;
    int n = threadIdx.x;
    const float* dA = g_dA + ((size_t)bh * LL + (size_t)c * CHL) * NK + n;
    if (dir == 0) {
        // forward: suffix-exclusive product; also P
        const float* uf = g_uf + ((size_t)bh * LL + (size_t)c * CHL) * NK + n;
        float* wf = g_wf + (((size_t)bh * NCH + c) * NK + n) * CHL;
        float run = 1.f;
        float buf[4];
        for (int t = CHL - 1; t >= 0; t--) {
            buf[t & 3] = to_tf32(run * uf[(size_t)t * NK]);
            run *= dA[(size_t)t * NK];
            if ((t & 3) == 0)
                *(float4*)&wf[t] = make_float4(buf[0], buf[1], buf[2], buf[3]);
        }
        g_P[((size_t)bh * NCH + c) * NK + n] = run;
    } else {
        // backward: prefix-exclusive product
        const float* ub = g_ub + ((size_t)bh * LL + (size_t)c * CHL) * NK + n;
        float* wb = g_wb + (((size_t)bh * NCH + c) * NK + n) * CHL;
        float run = 1.f;
        float buf[4];
        for (int t = 0; t < CHL; t++) {
            buf[t & 3] = to_tf32(run * ub[(size_t)t * NK]);
            run *= dA[(size_t)t * NK];
            if ((t & 3) == 3)
                *(float4*)&wb[t - 3] = make_float4(buf[0], buf[1], buf[2], buf[3]);
        }
    }
}

// ---------------- #5: transpose x (channels < 1024) to [bh][p][t], tf32 ----------------
__global__ __launch_bounds__(256) void xpose_kernel()
{
    __shared__ float tile[32][33];
    int db = blockIdx.z;
    int dir = db >> 1, b = db & 1;
    const float* src = (dir ? g_convb : g_convf) + (size_t)b * LL * CC;
    float* dst = dir ? g_xTb : g_xTf;
    int c0 = blockIdx.x * 32, l0 = blockIdx.y * 32;
    int tx = threadIdx.x & 31, ty = threadIdx.x >> 5;
#pragma unroll
    for (int i = 0; i < 4; i++) {
        int l = l0 + ty + i * 8;
        tile[ty + i * 8][tx] = src[(size_t)l * CC + c0 + tx];
    }
    __syncthreads();
#pragma unroll
    for (int i = 0; i < 4; i++) {
        int cc = c0 + ty + i * 8;
        int bh = b * 8 + (cc >> 7), p = cc & 127;
        dst[((size_t)bh * PP + p) * LL + l0 + tx] = to_tf32(tile[tx][ty + i * 8]);
    }
}

// ---------------- #6: S[n][p] = sum_t w[n][t] * xT[p][t] (tensor cores) ----------------
#define PADT 36
#define SGW_F (64*PADT)      // floats
#define SGX_F (128*PADT)
#define SGSTG_F (SGW_F + SGX_F)  // 6912 floats
#define DSMEM_SG (2*SGSTG_F*4)   // 55296 B

__global__ __launch_bounds__(128, 4) void sgemm_s_kernel()
{
    extern __shared__ __align__(16) float sms[];
    int bid = blockIdx.x;            // c(16) x bh(16) x dir(2)
    int c   = bid & 15;
    int bh  = (bid >> 4) & 15;
    int dir = bid >> 8;
    int tid = threadIdx.x, lid = tid & 31, wp = tid >> 5;
    int gid = lid >> 2, tig = lid & 3;

    const float* wsrc = (dir ? g_wb : g_wf) + ((size_t)bh * NCH + c) * NK * CHL;
    const float* xT   = (dir ? g_xTb : g_xTf) + (size_t)bh * PP * LL + (size_t)c * CHL;
    float* S = (dir ? g_Sb : g_Sf) + ((size_t)bh * NCH + c) * NK * PP;

    auto load = [&](int st, int kt) {
        float* dw = sms + st * SGSTG_F;
        float* dx = dw + SGW_F;
#pragma unroll
        for (int i = 0; i < 4; i++) {          // w: 64 rows x 8 float4 = 512
            int idx = tid + i * 128;
            int row = idx >> 3, kg = idx & 7;
            cpasync16(smem_u32(&dw[row * PADT + kg * 4]),
                      wsrc + (size_t)row * CHL + kt * 32 + kg * 4);
        }
#pragma unroll
        for (int i = 0; i < 8; i++) {          // x: 128 rows x 8 float4 = 1024
            int idx = tid + i * 128;
            int row = idx >> 3, kg = idx & 7;
            cpasync16(smem_u32(&dx[row * PADT + kg * 4]),
                      xT + (size_t)row * LL + kt * 32 + kg * 4);
        }
        asm volatile("cp.async.commit_group;\n" ::: "memory");
    };
    // NOTE: kt*32 covers only 32 t per stage but rows are 8 float4 = 32 floats ✓

    float acc[4][4][4];
#pragma unroll
    for (int mf = 0; mf < 4; mf++)
#pragma unroll
        for (int nf = 0; nf < 4; nf++)
#pragma unroll
            for (int i = 0; i < 4; i++) acc[mf][nf][i] = 0.f;

    load(0, 0);
    load(1, 1);
    for (int kt = 0; kt < 4; kt++) {
        if (kt + 1 < 4) asm volatile("cp.async.wait_group 1;\n" ::: "memory");
        else            asm volatile("cp.async.wait_group 0;\n" ::: "memory");
        __syncthreads();
        const float* dw = sms + (kt & 1) * SGSTG_F;
        const float* dx = dw + SGW_F;
#pragma unroll
        for (int kf = 0; kf < 4; kf++) {
            int k0 = kf * 8;
            uint32_t af[4][4];
#pragma unroll
            for (int mf = 0; mf < 4; mf++) {
                int r = mf * 16 + gid;
                af[mf][0] = __float_as_uint(dw[r * PADT + k0 + tig]);
                af[mf][1] = __float_as_uint(dw[(r + 8) * PADT + k0 + tig]);
                af[mf][2] = __float_as_uint(dw[r * PADT + k0 + tig + 4]);
                af[mf][3] = __float_as_uint(dw[(r + 8) * PADT + k0 + tig + 4]);
            }
#pragma unroll
            for (int nf = 0; nf < 4; nf++) {
                int pr = wp * 32 + nf * 8 + gid;
                uint32_t b0 = __float_as_uint(dx[pr * PADT + k0 + tig]);
                uint32_t b1 = __float_as_uint(dx[pr * PADT + k0 + tig + 4]);
#pragma unroll
                for (int mf = 0; mf < 4; mf++)
                    mma_tf32(acc[mf][nf], af[mf], b0, b1);
            }
        }
        __syncthreads();
        if (kt + 2 < 4) load(kt & 1, kt + 2);
    }

#pragma unroll
    for (int mf = 0; mf < 4; mf++) {
        int r0 = mf * 16 + gid;
#pragma unroll
        for (int nf = 0; nf < 4; nf++) {
            int col = wp * 32 + nf * 8 + tig * 2;
            *(float2*)&S[(size_t)r0 * PP + col] =
                make_float2(acc[mf][nf][0], acc[mf][nf][1]);
            *(float2*)&S[(size_t)(r0 + 8) * PP + col] =
                make_float2(acc[mf][nf][2], acc[mf][nf][3]);
        }
    }
}

// ---------------- P2: chunk combine (S now [n][p]) ----------------
__global__ __launch_bounds__(256) void scan_p2()
{
    int bid = blockIdx.x;
    int pblk = bid & 7, bh = bid >> 3;
    int b = bh >> 3, h = bh & 7;
    int tid = threadIdx.x;
    int q = tid & 15, pl = tid >> 4;
    int p = pblk * 16 + pl;

    ull h01, h23;
    {
        const float* hp = g_h0 + (size_t)b * NK * DI + h * PP + p;
        h01 = pack2(hp[(size_t)(4 * q + 0) * DI], hp[(size_t)(4 * q + 1) * DI]);
        h23 = pack2(hp[(size_t)(4 * q + 2) * DI], hp[(size_t)(4 * q + 3) * DI]);
    }
    {
        ull a01 = h01, a23 = h23;
        for (int c = 0; c < NCH; c++) {
            size_t ho = (((size_t)bh * NCH + c) * PP + p) * NK + 4 * q;
            *(ulonglong2*)&g_hsf[ho] = make_ulonglong2(a01, a23);
            ulonglong2 P2 = *(const ulonglong2*)&g_P[((size_t)bh * NCH + c) * NK + 4 * q];
            size_t sb = (((size_t)bh * NCH + c) * NK + 4 * q) * PP + p;
            ull S01 = pack2(g_Sf[sb], g_Sf[sb + PP]);
            ull S23 = pack2(g_Sf[sb + 2 * PP], g_Sf[sb + 3 * PP]);
            a01 = fma2(P2.x, a01, S01);
            a23 = fma2(P2.y, a23, S23);
        }
        float f0, f1, f2, f3;
        unpack2(a01, f0, f1); unpack2(a23, f2, f3);
        float* gh = g_hf + ((size_t)bh * PP + p) * NK + 4 * q;
        gh[0] = f0; gh[1] = f1; gh[2] = f2; gh[3] = f3;
    }
    {
        ull a01 = h01, a23 = h23;
        for (int c = NCH - 1; c >= 0; c--) {
            size_t ho = (((size_t)bh * NCH + c) * PP + p) * NK + 4 * q;
            *(ulonglong2*)&g_hsb[ho] = make_ulonglong2(a01, a23);
            ulonglong2 P2 = *(const ulonglong2*)&g_P[((size_t)bh * NCH + c) * NK + 4 * q];
            size_t sb = (((size_t)bh * NCH + c) * NK + 4 * q) * PP + p;
            ull S01 = pack2(g_Sb[sb], g_Sb[sb + PP]);
            ull S23 = pack2(g_Sb[sb + 2 * PP], g_Sb[sb + 3 * PP]);
            a01 = fma2(P2.x, a01, S01);
            a23 = fma2(P2.y, a23, S23);
        }
        float f0, f1, f2, f3;
        unpack2(a01, f0, f1); unpack2(a23, f2, f3);
        float* gh = g_hb + ((size_t)bh * PP + p) * NK + 4 * q;
        gh[0] = f0; gh[1] = f1; gh[2] = f2; gh[3] = f3;
    }
}

// ---------------- P3: within-chunk scan + y (unchanged) ----------------
#define T3_DA 0
#define T3_U  2048
#define T3_C  4096
#define T3_X  6144
__global__ __launch_bounds__(128, 4) void scan_p3()
{
    __shared__ __align__(16) float sm3[10240];
    int bid = blockIdx.x;
    int c   = bid & 15;
    int bh  = (bid >> 4) & 15;
    int dir = bid >> 8;
    int b = bh >> 3, h = bh & 7;
    int tid = threadIdx.x;

    const float* gdA = g_dA + ((size_t)bh * LL + (size_t)c * CHL) * NK;
    const float* gu  = (dir ? g_ub : g_uf) + ((size_t)bh * LL + (size_t)c * CHL) * NK;
    const float* gC  = (dir ? g_Cb2 : g_Cf) + ((size_t)b * LL + (size_t)c * CHL) * NK;
    const float* gx  = (dir ? g_convb : g_convf)
                     + ((size_t)b * LL + (size_t)c * CHL) * CC + h * PP;
    float* gy = (dir ? g_yb : g_yf)
              + ((size_t)b * LL + (size_t)c * CHL) * DI + h * PP + tid;

    ull hh[32];
    {
        const float* hs = (dir ? g_hsb : g_hsf)
                        + (((size_t)bh * NCH + c) * PP + tid) * NK;
#pragma unroll
        for (int i = 0; i < 16; i++) {
            ulonglong2 v = *(const ulonglong2*)&hs[i * 4];
            hh[2 * i] = v.x; hh[2 * i + 1] = v.y;
        }
    }

    auto load_tile = [&](int buf, int tile) {
        const float* da = gdA + (size_t)tile * 16 * NK;
        const float* uu = gu + (size_t)tile * 16 * NK;
        const float* cc = gC + (size_t)tile * 16 * NK;
        cpasync16(smem_u32(&sm3[T3_DA + buf * 1024 + tid * 8]),     da + tid * 8);
        cpasync16(smem_u32(&sm3[T3_DA + buf * 1024 + tid * 8 + 4]), da + tid * 8 + 4);
        cpasync16(smem_u32(&sm3[T3_U  + buf * 1024 + tid * 8]),     uu + tid * 8);
        cpasync16(smem_u32(&sm3[T3_U  + buf * 1024 + tid * 8 + 4]), uu + tid * 8 + 4);
        cpasync16(smem_u32(&sm3[T3_C  + buf * 1024 + tid * 8]),     cc + tid * 8);
        cpasync16(smem_u32(&sm3[T3_C  + buf * 1024 + tid * 8 + 4]), cc + tid * 8 + 4);
#pragma unroll
        for (int i = 0; i < 4; i++) {
            int idx = tid + i * 128;
            int row = idx >> 5, c4 = idx & 31;
            const float* xs = gx + (size_t)(tile * 16 + row) * CC + c4 * 4;
            unsigned sd = smem_u32(&sm3[T3_X + buf * 2048 + row * 128 + c4 * 4]);
            cpasync8(sd, xs);
            cpasync8(sd + 8, xs + 2);
        }
        asm volatile("cp.async.commit_group;\n");
    };

    load_tile(0, dir ? 7 : 0);
    for (int s = 0; s < 8; s++) {
        if (s + 1 < 8) {
            load_tile((s + 1) & 1, dir ? 6 - s : s + 1);
            asm volatile("cp.async.wait_group 1;\n");
        } else {
            asm volatile("cp.async.wait_group 0;\n");
        }
        __syncthreads();
        int buf = s & 1;
        int tile = dir ? 7 - s : s;
#pragma unroll 2
        for (int j = 0; j < 16; j++) {
            int tt = dir ? (15 - j) : j;
            float xp = sm3[T3_X + buf * 2048 + tt * 128 + tid];
            ull xx = pack2(xp, xp);
            const float* da = &sm3[T3_DA + buf * 1024 + tt * 64];
            const float* uu = &sm3[T3_U  + buf * 1024 + tt * 64];
            const float* cv = &sm3[T3_C  + buf * 1024 + tt * 64];
            ull acc0 = 0, acc1 = 0, acc2 = 0, acc3 = 0;
#pragma unroll
            for (int i = 0; i < 16; i++) {
                ulonglong2 av = *(const ulonglong2*)&da[i * 4];
                ulonglong2 uv = *(const ulonglong2*)&uu[i * 4];
                ulonglong2 c2 = *(const ulonglong2*)&cv[i * 4];
                hh[2 * i]     = fma2(av.x, hh[2 * i],     mul2(uv.x, xx));
                hh[2 * i + 1] = fma2(av.y, hh[2 * i + 1], mul2(uv.y, xx));
                if (i & 1) {
                    acc2 = fma2(c2.x, hh[2 * i], acc2);
                    acc3 = fma2(c2.y, hh[2 * i + 1], acc3);
                } else {
                    acc0 = fma2(c2.x, hh[2 * i], acc0);
                    acc1 = fma2(c2.y, hh[2 * i + 1], acc1);
                }
            }
            float a, bq, cq, d, e, f, g2, h2;
            unpack2(acc0, a, bq); unpack2(acc1, cq, d);
            unpack2(acc2, e, f);  unpack2(acc3, g2, h2);
            float y = ((a + bq) + (cq + d)) + ((e + f) + (g2 + h2));
            gy[(size_t)(tile * 16 + tt) * DI] = y;
        }
        __syncthreads();
    }
}

// ---------------- combine y, gate with silu(z), RMSNorm (tf32 out) ----------------
__global__ __launch_bounds__(256) void gate_norm_key_kernel(const float* __restrict__ Dp,
                                                            const float* __restrict__ normw)
{
    int bl = blockIdx.x;
    int tid = threadIdx.x;
    __shared__ float s_v[DI];
    __shared__ float sred[9];
    float ss = 0.f;
    size_t byDI = (size_t)bl * DI, byCC = (size_t)bl * CC, byNZ = (size_t)bl * NZ;
#pragma unroll
    for (int it = 0; it < 4; it++) {
        int i = tid + it * 256;
        int hh = i >> 7;
        float y = 0.5f * (g_yf[byDI + i] + g_yb[byDI + i])
                + 0.5f * Dp[hh] * (g_convf[byCC + i] + g_convb[byCC + i]);
        float z = g_zx[byNZ + i];
        float xg = y * z * (1.f / (1.f + __expf(-z)));
        s_v[i] = xg;
        ss += xg * xg;
    }
    for (int o = 16; o; o >>= 1) ss += __shfl_xor_sync(0xffffffffu, ss, o);
    if ((tid & 31) == 0) sred[tid >> 5] = ss;
    __syncthreads();
    if (tid == 0) {
        float t = 0.f;
        for (int w = 0; w < 8; w++) t += sred[w];
        sred[8] = rsqrtf(t * (1.f / DI) + 1e-5f);
    }
    __syncthreads();
    float sc = sred[8];
#pragma unroll
    for (int it = 0; it < 4; it++) {
        int i = tid + it * 256;
        g_xg[byDI + i] = to_tf32(s_v[i] * sc * normw[i]);
    }
}

// ---------------- query path: LayerNorm (tf32 out) ----------------
__global__ __launch_bounds__(256) void qnorm_kernel(const float* __restrict__ w,
                                                    const float* __restrict__ bi)
{
    int bk = blockIdx.x;
    int b = bk >> 6, k = bk & 63;
    int tid = threadIdx.x;
    __shared__ float s_v[DI];
    __shared__ float sred[18];
    float s1 = 0.f, s2 = 0.f;
#pragma unroll
    for (int it = 0; it < 4; it++) {
        int i = tid + it * 256;
        int hh = i >> 7, p = i & 127;
        size_t o = ((size_t)(b * NH + hh) * PP + p) * NK + k;
        float qv = 0.5f * (g_hf[o] + g_hb[o]);
        s_v[i] = qv;
        s1 += qv;
        s2 += qv * qv;
    }
    for (int o = 16; o; o >>= 1) {
        s1 += __shfl_xor_sync(0xffffffffu, s1, o);
        s2 += __shfl_xor_sync(0xffffffffu, s2, o);
    }
    if ((tid & 31) == 0) { sred[tid >> 5] = s1; sred[8 + (tid >> 5)] = s2; }
    __syncthreads();
    if (tid == 0) {
        float t1 = 0.f, t2 = 0.f;
        for (int wv = 0; wv < 8; wv++) { t1 += sred[wv]; t2 += sred[8 + wv]; }
        float mu = t1 * (1.f / DI);
        float var = t2 * (1.f / DI) - mu * mu;
        sred[16] = mu;
        sred[17] = rsqrtf(var + 1e-5f);
    }
    __syncthreads();
    float mu = sred[16], rs = sred[17];
#pragma unroll
    for (int it = 0; it < 4; it++) {
        int i = tid + it * 256;
        g_qn[(size_t)bk * DI + i] = to_tf32((s_v[i] - mu) * rs * w[i] + bi[i]);
    }
}

// ---------------- host launcher ----------------
extern "C" void kernel_launch(void* const* d_in, const int* in_sizes, int n_in,
                              void* d_out, int out_size)
{
    (void)in_sizes; (void)n_in; (void)out_size;
    const float* in_key      = (const float*)d_in[0];
    const float* in_query    = (const float*)d_in[1];
    const float* dist        = (const float*)d_in[2];
    const float* key_proj_w  = (const float*)d_in[4];
    const float* key_conv_w  = (const float*)d_in[5];
    const float* key_conv_b  = (const float*)d_in[6];
    const float* key_conv_bw = (const float*)d_in[7];
    const float* key_conv_bb = (const float*)d_in[8];
    const float* query_proj_w= (const float*)d_in[9];
    const float* bc_proj_w   = (const float*)d_in[10];
    const float* dt_proj_w   = (const float*)d_in[11];
    const float* dt_bias     = (const float*)d_in[12];
    const float* A_log       = (const float*)d_in[13];
    const float* D_param     = (const float*)d_in[14];
    const float* out_key_w   = (const float*)d_in[15];
    const float* out_query_w = (const float*)d_in[16];
    const float* key_norm_w  = (const float*)d_in[17];
    const float* q_ln_w      = (const float*)d_in[18];
    const float* q_ln_b      = (const float*)d_in[19];
    float* out = (float*)d_out;

    void *p_zx, *p_h0, *p_xg, *p_qn;
    void *p_rA1, *p_rW1, *p_rQ, *p_rWq, *p_rWo, *p_rWoq;
    cudaGetSymbolAddress(&p_zx, g_zx);
    cudaGetSymbolAddress(&p_h0, g_h0);
    cudaGetSymbolAddress(&p_xg, g_xg);
    cudaGetSymbolAddress(&p_qn, g_qn);
    cudaGetSymbolAddress(&p_rA1, g_rA1);
    cudaGetSymbolAddress(&p_rW1, g_rW1);
    cudaGetSymbolAddress(&p_rQ, g_rQ);
    cudaGetSymbolAddress(&p_rWq, g_rWq);
    cudaGetSymbolAddress(&p_rWo, g_rWo);
    cudaGetSymbolAddress(&p_rWoq, g_rWoq);

    cudaFuncSetAttribute(gemm_mma, cudaFuncAttributeMaxDynamicSharedMemorySize, DSMEM_G);
    cudaFuncSetAttribute(sgemm_s_kernel, cudaFuncAttributeMaxDynamicSharedMemorySize, DSMEM_SG);

    // #1: fused prerounds + zeros
    {
        size_t n = ((size_t)BLT * DM + (size_t)NZ * DM + (size_t)BB * NK * DM
                    + (size_t)DI * DM + 2ull * DM * DI
                    + (size_t)BB * NK * DI + (size_t)BB * NK * DM) / 4;
        prep_all_kernel<<<(int)((n + 255) / 256), 256>>>(
            in_key, key_proj_w, in_query, query_proj_w, out_key_w, out_query_w,
            out + (size_t)BLT * DM);
    }
    // #2: zxbcdt = in_key @ key_proj_w^T
    {
        dim3 grid((NZ + 127) / 128, BLT / 128, 1);
        gemm_mma<<<grid, 128, DSMEM_G>>>((const float*)p_rA1, (const float*)p_rW1,
                                         (float*)p_zx, BLT, NZ, DM);
    }
    // #3: fused conv + dtbc
    convdtbc_kernel<<<CONV_BLKS + DTBC_BLKS, 256>>>(
        key_conv_w, key_conv_b, key_conv_bw, key_conv_bb,
        dist, bc_proj_w, dt_proj_w, dt_bias, A_log);
    // #4 (profiled): w-prep
    wprep_kernel<<<512, 64>>>();
    // #5: x transpose (tf32)
    {
        dim3 grid(DI / 32, LL / 32, 2 * BB);
        xpose_kernel<<<grid, 256>>>();
    }
    // #6: S = w @ xT (tensor cores)
    sgemm_s_kernel<<<512, 128, DSMEM_SG>>>();
    // #7: h0 = in_query @ query_proj_w^T, split-K x4
    {
        dim3 grid(DI / 128, 1, 4);
        gemm_mma<<<grid, 128, DSMEM_G>>>((const float*)p_rQ, (const float*)p_rWq,
                                         (float*)p_h0, BB * NK, DI, DM);
    }
    // #8: scan P2
    scan_p2<<<128, 256>>>();
    // #9: scan P3
    scan_p3<<<512, 128>>>();
    // #10: combine + gate + RMSNorm
    gate_norm_key_kernel<<<BLT, 256>>>(D_param, key_norm_w);
    // #11: out_key = key_n @ out_key_w^T
    {
        dim3 grid(DM / 128, BLT / 128, 1);
        gemm_mma<<<grid, 128, DSMEM_G>>>((const float*)p_xg, (const float*)p_rWo,
                                         out, BLT, DM, DI);
    }
    // #12: query layer norm
    qnorm_kernel<<<BB * NK, 256>>>(q_ln_w, q_ln_b);
    // #13: out_query = qn @ out_query_w^T, split-K x8
    {
        dim3 grid(DM / 128, 1, 8);
        gemm_mma<<<grid, 128, DSMEM_G>>>((const float*)p_qn, (const float*)p_rWoq,
                                         out + (size_t)BLT * DM, BB * NK, DM, DI);
    }
}

// round 15
// speedup vs baseline: 1.4910x; 1.0018x over previous
#include <cuda_runtime.h>
#include <cuda_bf16.h>
#include <cstdint>

// ---------------- problem constants ----------------
#define BB 2
#define LL 2048
#define NK 64
#define DM 512
#define DI 1024
#define NH 8
#define PP 128
#define NZ 2058
#define CC 1026
#define BLT (BB*LL)
#define NCH 16
#define CHL 128

typedef unsigned long long ull;

// ---------------- scratch ----------------
__device__ float g_zx   [(size_t)BB*LL*NZ];
__device__ float g_convf[(size_t)BB*LL*CC];
__device__ float g_convb[(size_t)BB*LL*CC];
__device__ float g_dA   [(size_t)BB*NH*LL*NK];
__device__ float g_uf   [(size_t)BB*NH*LL*NK];
__device__ float g_ub   [(size_t)BB*NH*LL*NK];
__device__ float g_Cf   [(size_t)BB*LL*NK];
__device__ float g_Cb2  [(size_t)BB*LL*NK];
__device__ float g_h0   [(size_t)BB*NK*DI];
__device__ float g_yf   [(size_t)BB*LL*DI];
__device__ float g_yb   [(size_t)BB*LL*DI];
__device__ float g_hf   [(size_t)BB*NH*PP*NK];
__device__ float g_hb   [(size_t)BB*NH*PP*NK];
__device__ float g_xg   [(size_t)BB*LL*DI];
__device__ float g_qn   [(size_t)BB*NK*DI];
// chunked-scan intermediates
__device__ float g_Sf  [(size_t)16*NCH*NK*PP];   // [bh][c][n][p]
__device__ float g_Sb  [(size_t)16*NCH*NK*PP];
__device__ float g_P   [(size_t)16*NCH*NK];
__device__ float g_hsf [(size_t)16*NCH*PP*NK];   // [bh][c][p][n]
__device__ float g_hsb [(size_t)16*NCH*PP*NK];
__device__ float g_wf  [(size_t)16*NCH*NK*CHL];  // [bh][c][n][t], tf32
__device__ float g_wb  [(size_t)16*NCH*NK*CHL];
__device__ float g_xTf [(size_t)16*PP*LL];       // [bh][p][t], tf32
__device__ float g_xTb [(size_t)16*PP*LL];
// tf32-rounded copies of GEMM inputs
__device__ float g_rA1 [(size_t)BLT*DM];
__device__ float g_rW1 [(size_t)NZ*DM];
__device__ float g_rQ  [(size_t)BB*NK*DM];
__device__ float g_rWq [(size_t)DI*DM];
__device__ float g_rWo [(size_t)DM*DI];
__device__ float g_rWoq[(size_t)DM*DI];

// ---------------- helpers ----------------
__device__ __forceinline__ unsigned smem_u32(const void* p) {
    return (unsigned)__cvta_generic_to_shared(p);
}
__device__ __forceinline__ void cpasync16(unsigned s, const void* g) {
    asm volatile("cp.async.cg.shared.global [%0],[%1],16;\n" ::"r"(s), "l"(g));
}
__device__ __forceinline__ void cpasync16z(unsigned s, const void* g, unsigned srcsz) {
    asm volatile("cp.async.cg.shared.global [%0],[%1],16,%2;\n" ::"r"(s), "l"(g), "r"(srcsz));
}
__device__ __forceinline__ void cpasync8(unsigned s, const void* g) {
    asm volatile("cp.async.ca.shared.global [%0],[%1],8;\n" ::"r"(s), "l"(g));
}
__device__ __forceinline__ float to_tf32(float x) {
    float r; asm("cvt.rna.tf32.f32 %0,%1;" : "=f"(r) : "f"(x)); return r;
}
__device__ __forceinline__ void mma_tf32(float* c, const uint32_t* a, uint32_t b0, uint32_t b1) {
    asm volatile(
        "mma.sync.aligned.m16n8k8.row.col.f32.tf32.tf32.f32 "
        "{%0,%1,%2,%3}, {%4,%5,%6,%7}, {%8,%9}, {%0,%1,%2,%3};"
        : "+f"(c[0]), "+f"(c[1]), "+f"(c[2]), "+f"(c[3])
        : "r"(a[0]), "r"(a[1]), "r"(a[2]), "r"(a[3]), "r"(b0), "r"(b1));
}
__device__ __forceinline__ ull mul2(ull a, ull b) {
    ull d; asm("mul.rn.f32x2 %0,%1,%2;" : "=l"(d) : "l"(a), "l"(b)); return d;
}
__device__ __forceinline__ ull fma2(ull a, ull b, ull c) {
    ull d; asm("fma.rn.f32x2 %0,%1,%2,%3;" : "=l"(d) : "l"(a), "l"(b), "l"(c)); return d;
}
__device__ __forceinline__ ull pack2(float x, float y) {
    ull d; asm("mov.b64 %0,{%1,%2};" : "=l"(d) : "f"(x), "f"(y)); return d;
}
__device__ __forceinline__ void unpack2(ull v, float& x, float& y) {
    asm("mov.b64 {%0,%1},%2;" : "=f"(x), "=f"(y) : "l"(v));
}

// ---------------- #1: fused prerounds + zero accumulators ----------------
__global__ __launch_bounds__(256) void prep_all_kernel(
    const float* __restrict__ a1, const float* __restrict__ w1,
    const float* __restrict__ q,  const float* __restrict__ wq,
    const float* __restrict__ wo, const float* __restrict__ woq,
    float* __restrict__ outq)
{
    const size_t n1 = (size_t)BLT * DM / 4;
    const size_t n2 = n1 + (size_t)NZ * DM / 4;
    const size_t n3 = n2 + (size_t)BB * NK * DM / 4;
    const size_t n4 = n3 + (size_t)DI * DM / 4;
    const size_t n5 = n4 + (size_t)DM * DI / 4;
    const size_t n6 = n5 + (size_t)DM * DI / 4;
    const size_t n7 = n6 + (size_t)BB * NK * DI / 4;
    const size_t n8 = n7 + (size_t)BB * NK * DM / 4;
    size_t i = (size_t)blockIdx.x * 256 + threadIdx.x;
    if (i >= n8) return;
    if (i >= n6) {
        float4 z = make_float4(0.f, 0.f, 0.f, 0.f);
        if (i < n7) ((float4*)g_h0)[i - n6] = z;
        else        ((float4*)outq)[i - n7] = z;
        return;
    }
    const float* src; float* dst; size_t off;
    if      (i < n1) { src = a1;  dst = g_rA1;  off = i; }
    else if (i < n2) { src = w1;  dst = g_rW1;  off = i - n1; }
    else if (i < n3) { src = q;   dst = g_rQ;   off = i - n2; }
    else if (i < n4) { src = wq;  dst = g_rWq;  off = i - n3; }
    else if (i < n5) { src = wo;  dst = g_rWo;  off = i - n4; }
    else             { src = woq; dst = g_rWoq; off = i - n5; }
    float4 v = ((const float4*)src)[off];
    v.x = to_tf32(v.x); v.y = to_tf32(v.y); v.z = to_tf32(v.z); v.w = to_tf32(v.w);
    ((float4*)dst)[off] = v;
}

// ---------------- tensor-core tf32 GEMM (4 warps, 64x64 warp tile, 3-stage) ----------------
#define KC 16
#define PADK 20
#define STAGE_B (128*PADK*4)
#define CHUNK_B (2*STAGE_B)
#define DSMEM_G (3*CHUNK_B)

__global__ __launch_bounds__(128, 2) void gemm_mma(const float* __restrict__ A,
                                                   const float* __restrict__ W,
                                                   float* __restrict__ C,
                                                   int M, int N, int K)
{
    extern __shared__ __align__(16) char dsm[];
    const int tid = threadIdx.x;
    const int lid = tid & 31, wrp = tid >> 5;
    const int wm = wrp & 1, wn = wrp >> 1;
    const int gid = lid >> 2, tig = lid & 3;
    const int m0 = blockIdx.y * 128, n0 = blockIdx.x * 128;
    const unsigned sbase = smem_u32(dsm);

    const int totCh = K >> 4;
    const int per = totCh / gridDim.z;
    const int cbase = blockIdx.z * per;
    const bool split = gridDim.z > 1;

    auto load_chunk = [&](int st, int ch) {
        const float* Ap = A + (size_t)m0 * K + ch * KC;
        const float* Wp = W + (size_t)n0 * K + ch * KC;
        unsigned ao = (unsigned)st * CHUNK_B;
        unsigned bo = ao + STAGE_B;
#pragma unroll
        for (int i = 0; i < 4; i++) {
            int idx = tid + i * 128;
            int row = idx >> 2, kg = idx & 3;
            unsigned so = (unsigned)(row * PADK * 4 + kg * 16);
            cpasync16(sbase + ao + so, Ap + (size_t)row * K + kg * 4);
            int nrow = n0 + row;
            int cl = (nrow < N) ? nrow : (N - 1);
            cpasync16z(sbase + bo + so, Wp + (size_t)(cl - n0) * K + kg * 4,
                       (nrow < N) ? 16u : 0u);
        }
        asm volatile("cp.async.commit_group;\n" ::: "memory");
    };

    float acc[4][8][4];
#pragma unroll
    for (int mf = 0; mf < 4; mf++)
#pragma unroll
        for (int nf = 0; nf < 8; nf++)
#pragma unroll
            for (int i = 0; i < 4; i++) acc[mf][nf][i] = 0.f;

    load_chunk(0, cbase);
    if (per > 1) load_chunk(1, cbase + 1);

    int st = 0;
    for (int c = 0; c < per; c++) {
        if (c + 1 < per) asm volatile("cp.async.wait_group 1;\n" ::: "memory");
        else             asm volatile("cp.async.wait_group 0;\n" ::: "memory");
        __syncthreads();
        if (c + 2 < per) {
            int st2 = st + 2; if (st2 >= 3) st2 -= 3;
            load_chunk(st2, cbase + c + 2);
        }
        const float* as = (const float*)(dsm + st * CHUNK_B);
        const float* bs = (const float*)(dsm + st * CHUNK_B + STAGE_B);
#pragma unroll
        for (int ks = 0; ks < 2; ks++) {
            int k0 = ks * 8;
            uint32_t af[4][4];
#pragma unroll
            for (int mf = 0; mf < 4; mf++) {
                int r = wm * 64 + mf * 16 + gid;
                af[mf][0] = __float_as_uint(as[r * PADK + k0 + tig]);
                af[mf][1] = __float_as_uint(as[(r + 8) * PADK + k0 + tig]);
                af[mf][2] = __float_as_uint(as[r * PADK + k0 + tig + 4]);
                af[mf][3] = __float_as_uint(as[(r + 8) * PADK + k0 + tig + 4]);
            }
#pragma unroll
            for (int nf = 0; nf < 8; nf++) {
                int nr = wn * 64 + nf * 8 + gid;
                uint32_t b0 = __float_as_uint(bs[nr * PADK + k0 + tig]);
                uint32_t b1 = __float_as_uint(bs[nr * PADK + k0 + tig + 4]);
#pragma unroll
                for (int mf = 0; mf < 4; mf++)
                    mma_tf32(acc[mf][nf], af[mf], b0, b1);
            }
        }
        if (++st >= 3) st = 0;
    }

#pragma unroll
    for (int mf = 0; mf < 4; mf++) {
        int r0 = m0 + wm * 64 + mf * 16 + gid;
#pragma unroll
        for (int nf = 0; nf < 8; nf++) {
            int col = n0 + wn * 64 + nf * 8 + tig * 2;
            if (col < N) {
                float* p0 = &C[(size_t)r0 * N + col];
                float* p1 = &C[(size_t)(r0 + 8) * N + col];
                if (!split) {
                    *(float2*)p0 = make_float2(acc[mf][nf][0], acc[mf][nf][1]);
                    *(float2*)p1 = make_float2(acc[mf][nf][2], acc[mf][nf][3]);
                } else {
                    atomicAdd(p0,     acc[mf][nf][0]);
                    atomicAdd(p0 + 1, acc[mf][nf][1]);
                    atomicAdd(p1,     acc[mf][nf][2]);
                    atomicAdd(p1 + 1, acc[mf][nf][3]);
                }
            }
        }
    }
}

// ---------------- #3: fused conv + dtbc ----------------
#define CONV_BLKS (((CC + 255) / 256) * (LL / 8) * (2 * BB))
#define DTBC_BLKS (BLT / 4)

__global__ __launch_bounds__(256) void convdtbc_kernel(
    const float* __restrict__ cwf, const float* __restrict__ cbf,
    const float* __restrict__ cwb, const float* __restrict__ cbb,
    const float* __restrict__ dist, const float* __restrict__ bcw,
    const float* __restrict__ dtw, const float* __restrict__ dt_bias,
    const float* __restrict__ A_log)
{
    int bid = blockIdx.x;
    int tid = threadIdx.x;
    if (bid < CONV_BLKS) {
        int cblk = bid % 5;
        int rest = bid / 5;
        int l0 = (rest & 255) * 8;
        int db = rest >> 8;
        int dir = db >> 1, b = db & 1;
        int c = cblk * 256 + tid;
        if (c >= CC) return;

        const float* wsrc = (dir ? cwb : cwf) + c * 7;
        float wr[7];
#pragma unroll
        for (int t = 0; t < 7; t++) wr[t] = wsrc[t];
        float bias = (dir ? cbb : cbf)[c];

        const float* src = g_zx + (size_t)b * LL * NZ + DI + c;
        float win[14];
#pragma unroll
        for (int i = 0; i < 14; i++) {
            int l = l0 - 3 + i;
            win[i] = (0 <= l && l < LL) ? src[(size_t)l * NZ] : 0.f;
        }
        float* dst = (dir ? g_convb : g_convf) + ((size_t)b * LL + l0) * CC + c;
#pragma unroll
        for (int j = 0; j < 8; j++) {
            float acc = bias;
#pragma unroll
            for (int t = 0; t < 7; t++) acc = fmaf(wr[t], win[j + t], acc);
            float sig = 1.f / (1.f + __expf(-acc));
            dst[(size_t)j * CC] = acc * sig;
        }
        return;
    }
    {
        int bl = (bid - CONV_BLKS) * 4 + (tid >> 6);
        int b = bl / LL, l = bl % LL;
        int k = tid & 63;

        float resf[2], resb[2];
        const float* zsrc = g_zx + (size_t)b * LL * NZ + 2 * DI;
#pragma unroll
        for (int ch = 0; ch < 2; ch++) {
            float af = cbf[1024 + ch], ab = cbb[1024 + ch];
#pragma unroll
            for (int t = 0; t < 7; t++) {
                int l2 = l + t - 3;
                if (0 <= l2 && l2 < LL) {
                    float v = zsrc[(size_t)l2 * NZ + ch];
                    af = fmaf(cwf[(1024 + ch) * 7 + t], v, af);
                    ab = fmaf(cwb[(1024 + ch) * 7 + t], v, ab);
                }
            }
            resf[ch] = af * (1.f / (1.f + __expf(-af)));
            resb[ch] = ab * (1.f / (1.f + __expf(-ab)));
        }
        float bbf = resf[0], cbfv = resf[1], bbb = resb[0], cbbv = resb[1];

        float4 d4 = *(const float4*)&dist[((size_t)bl * NK + k) * 4];
        float bb = d4.x * bcw[0] + d4.y * bcw[1] + d4.z * bcw[2] + d4.w * bcw[3];
        float cb = d4.x * bcw[4] + d4.y * bcw[5] + d4.z * bcw[6] + d4.w * bcw[7];
        g_Cf [(size_t)bl * NK + k] = cb + cbfv;
        g_Cb2[(size_t)bl * NK + k] = cb + cbbv;
        float Bf = bb + bbf, Bbk = bb + bbb;
        size_t zoff = (size_t)bl * NZ + 2 * DI + 2;
#pragma unroll
        for (int h = 0; h < NH; h++) {
            float pre = d4.x * dtw[h * 4 + 0] + d4.y * dtw[h * 4 + 1]
                      + d4.z * dtw[h * 4 + 2] + d4.w * dtw[h * 4 + 3]
                      + g_zx[zoff + h] + dt_bias[h];
            float dt = (pre > 20.f) ? pre : log1pf(__expf(pre));
            float Ah = -__expf(A_log[h]);
            float dA = __expf(dt * Ah);
            size_t o = (((size_t)(b * NH + h) * LL) + l) * NK + k;
            g_dA[o] = dA;
            g_uf[o] = dt * Bf;
            g_ub[o] = dt * Bbk;
        }
    }
}

// ---------------- #4 (profiled): w-prep v2 — segment-parallel products ----------------
// 512 blocks: bh(16) x c(16) x dir(2); 256 threads = seg(4) x n(64).
__global__ __launch_bounds__(256) void wprep_kernel()
{
    __shared__ float sp[4][64];
    int bid = blockIdx.x;
    int dir = bid & 1;
    int c   = (bid >> 1) & 15;
    int bh  = bid >> 5;
    int n   = threadIdx.x & 63;
    int seg = threadIdx.x >> 6;
    const int t0 = seg * 32;

    const float* dA = g_dA + ((size_t)bh * LL + (size_t)c * CHL) * NK + n;
    const float* uu = (dir ? g_ub : g_uf) + ((size_t)bh * LL + (size_t)c * CHL) * NK + n;
    float* w = (dir ? g_wb : g_wf) + (((size_t)bh * NCH + c) * NK + n) * CHL;

    // pass 1: per-segment dA product
    float spv = 1.f;
#pragma unroll 8
    for (int t = 0; t < 32; t++) spv *= dA[(size_t)(t0 + t) * NK];
    sp[seg][n] = spv;
    __syncthreads();

    if (dir == 0) {
        // w[t] = (prod_{r>t} dA[r]) * u[t];  P = prod all
        float F = 1.f;
#pragma unroll
        for (int s = 1; s < 4; s++) if (s > seg) F *= sp[s][n];
        float run = F;
        float buf[4];
#pragma unroll 4
        for (int t = 31; t >= 0; t--) {
            int tt = t0 + t;
            buf[t & 3] = to_tf32(run * uu[(size_t)tt * NK]);
            run *= dA[(size_t)tt * NK];
            if ((t & 3) == 0)
                *(float4*)&w[tt] = make_float4(buf[0], buf[1], buf[2], buf[3]);
        }
        if (seg == 0)
            g_P[((size_t)bh * NCH + c) * NK + n] =
                sp[0][n] * sp[1][n] * sp[2][n] * sp[3][n];
    } else {
        // w[t] = (prod_{r<t} dA[r]) * u[t]
        float F = 1.f;
#pragma unroll
        for (int s = 0; s < 3; s++) if (s < seg) F *= sp[s][n];
        float run = F;
        float buf[4];
#pragma unroll 4
        for (int t = 0; t < 32; t++) {
            int tt = t0 + t;
            buf[t & 3] = to_tf32(run * uu[(size_t)tt * NK]);
            run *= dA[(size_t)tt * NK];
            if ((t & 3) == 3)
                *(float4*)&w[tt - 3] = make_float4(buf[0], buf[1], buf[2], buf[3]);
        }
    }
}

// ---------------- #5: transpose x (channels < 1024) to [bh][p][t], tf32 ----------------
__global__ __launch_bounds__(256) void xpose_kernel()
{
    __shared__ float tile[32][33];
    int db = blockIdx.z;
    int dir = db >> 1, b = db & 1;
    const float* src = (dir ? g_convb : g_convf) + (size_t)b * LL * CC;
    float* dst = dir ? g_xTb : g_xTf;
    int c0 = blockIdx.x * 32, l0 = blockIdx.y * 32;
    int tx = threadIdx.x & 31, ty = threadIdx.x >> 5;
#pragma unroll
    for (int i = 0; i < 4; i++) {
        int l = l0 + ty + i * 8;
        tile[ty + i * 8][tx] = src[(size_t)l * CC + c0 + tx];
    }
    __syncthreads();
#pragma unroll
    for (int i = 0; i < 4; i++) {
        int cc = c0 + ty + i * 8;
        int bh = b * 8 + (cc >> 7), p = cc & 127;
        dst[((size_t)bh * PP + p) * LL + l0 + tx] = to_tf32(tile[tx][ty + i * 8]);
    }
}

// ---------------- #6: S[n][p] = sum_t w[n][t] * xT[p][t] (tensor cores) ----------------
#define PADT 36
#define SGW_F (64*PADT)
#define SGX_F (128*PADT)
#define SGSTG_F (SGW_F + SGX_F)
#define DSMEM_SG (2*SGSTG_F*4)

__global__ __launch_bounds__(128, 4) void sgemm_s_kernel()
{
    extern __shared__ __align__(16) float sms[];
    int bid = blockIdx.x;
    int c   = bid & 15;
    int bh  = (bid >> 4) & 15;
    int dir = bid >> 8;
    int tid = threadIdx.x, lid = tid & 31, wp = tid >> 5;
    int gid = lid >> 2, tig = lid & 3;

    const float* wsrc = (dir ? g_wb : g_wf) + ((size_t)bh * NCH + c) * NK * CHL;
    const float* xT   = (dir ? g_xTb : g_xTf) + (size_t)bh * PP * LL + (size_t)c * CHL;
    float* S = (dir ? g_Sb : g_Sf) + ((size_t)bh * NCH + c) * NK * PP;

    auto load = [&](int st, int kt) {
        float* dw = sms + st * SGSTG_F;
        float* dx = dw + SGW_F;
#pragma unroll
        for (int i = 0; i < 4; i++) {
            int idx = tid + i * 128;
            int row = idx >> 3, kg = idx & 7;
            cpasync16(smem_u32(&dw[row * PADT + kg * 4]),
                      wsrc + (size_t)row * CHL + kt * 32 + kg * 4);
        }
#pragma unroll
        for (int i = 0; i < 8; i++) {
            int idx = tid + i * 128;
            int row = idx >> 3, kg = idx & 7;
            cpasync16(smem_u32(&dx[row * PADT + kg * 4]),
                      xT + (size_t)row * LL + kt * 32 + kg * 4);
        }
        asm volatile("cp.async.commit_group;\n" ::: "memory");
    };

    float acc[4][4][4];
#pragma unroll
    for (int mf = 0; mf < 4; mf++)
#pragma unroll
        for (int nf = 0; nf < 4; nf++)
#pragma unroll
            for (int i = 0; i < 4; i++) acc[mf][nf][i] = 0.f;

    load(0, 0);
    load(1, 1);
    for (int kt = 0; kt < 4; kt++) {
        if (kt + 1 < 4) asm volatile("cp.async.wait_group 1;\n" ::: "memory");
        else            asm volatile("cp.async.wait_group 0;\n" ::: "memory");
        __syncthreads();
        const float* dw = sms + (kt & 1) * SGSTG_F;
        const float* dx = dw + SGW_F;
#pragma unroll
        for (int kf = 0; kf < 4; kf++) {
            int k0 = kf * 8;
            uint32_t af[4][4];
#pragma unroll
            for (int mf = 0; mf < 4; mf++) {
                int r = mf * 16 + gid;
                af[mf][0] = __float_as_uint(dw[r * PADT + k0 + tig]);
                af[mf][1] = __float_as_uint(dw[(r + 8) * PADT + k0 + tig]);
                af[mf][2] = __float_as_uint(dw[r * PADT + k0 + tig + 4]);
                af[mf][3] = __float_as_uint(dw[(r + 8) * PADT + k0 + tig + 4]);
            }
#pragma unroll
            for (int nf = 0; nf < 4; nf++) {
                int pr = wp * 32 + nf * 8 + gid;
                uint32_t b0 = __float_as_uint(dx[pr * PADT + k0 + tig]);
                uint32_t b1 = __float_as_uint(dx[pr * PADT + k0 + tig + 4]);
#pragma unroll
                for (int mf = 0; mf < 4; mf++)
                    mma_tf32(acc[mf][nf], af[mf], b0, b1);
            }
        }
        __syncthreads();
        if (kt + 2 < 4) load(kt & 1, kt + 2);
    }

#pragma unroll
    for (int mf = 0; mf < 4; mf++) {
        int r0 = mf * 16 + gid;
#pragma unroll
        for (int nf = 0; nf < 4; nf++) {
            int col = wp * 32 + nf * 8 + tig * 2;
            *(float2*)&S[(size_t)r0 * PP + col] =
                make_float2(acc[mf][nf][0], acc[mf][nf][1]);
            *(float2*)&S[(size_t)(r0 + 8) * PP + col] =
                make_float2(acc[mf][nf][2], acc[mf][nf][3]);
        }
    }
}

// ---------------- P2: chunk combine (S in [n][p]) ----------------
__global__ __launch_bounds__(256) void scan_p2()
{
    int bid = blockIdx.x;
    int pblk = bid & 7, bh = bid >> 3;
    int b = bh >> 3, h = bh & 7;
    int tid = threadIdx.x;
    int q = tid & 15, pl = tid >> 4;
    int p = pblk * 16 + pl;

    ull h01, h23;
    {
        const float* hp = g_h0 + (size_t)b * NK * DI + h * PP + p;
        h01 = pack2(hp[(size_t)(4 * q + 0) * DI], hp[(size_t)(4 * q + 1) * DI]);
        h23 = pack2(hp[(size_t)(4 * q + 2) * DI], hp[(size_t)(4 * q + 3) * DI]);
    }
    {
        ull a01 = h01, a23 = h23;
        for (int c = 0; c < NCH; c++) {
            size_t ho = (((size_t)bh * NCH + c) * PP + p) * NK + 4 * q;
            *(ulonglong2*)&g_hsf[ho] = make_ulonglong2(a01, a23);
            ulonglong2 P2 = *(const ulonglong2*)&g_P[((size_t)bh * NCH + c) * NK + 4 * q];
            size_t sb = (((size_t)bh * NCH + c) * NK + 4 * q) * PP + p;
            ull S01 = pack2(g_Sf[sb], g_Sf[sb + PP]);
            ull S23 = pack2(g_Sf[sb + 2 * PP], g_Sf[sb + 3 * PP]);
            a01 = fma2(P2.x, a01, S01);
            a23 = fma2(P2.y, a23, S23);
        }
        float f0, f1, f2, f3;
        unpack2(a01, f0, f1); unpack2(a23, f2, f3);
        float* gh = g_hf + ((size_t)bh * PP + p) * NK + 4 * q;
        gh[0] = f0; gh[1] = f1; gh[2] = f2; gh[3] = f3;
    }
    {
        ull a01 = h01, a23 = h23;
        for (int c = NCH - 1; c >= 0; c--) {
            size_t ho = (((size_t)bh * NCH + c) * PP + p) * NK + 4 * q;
            *(ulonglong2*)&g_hsb[ho] = make_ulonglong2(a01, a23);
            ulonglong2 P2 = *(const ulonglong2*)&g_P[((size_t)bh * NCH + c) * NK + 4 * q];
            size_t sb = (((size_t)bh * NCH + c) * NK + 4 * q) * PP + p;
            ull S01 = pack2(g_Sb[sb], g_Sb[sb + PP]);
            ull S23 = pack2(g_Sb[sb + 2 * PP], g_Sb[sb + 3 * PP]);
            a01 = fma2(P2.x, a01, S01);
            a23 = fma2(P2.y, a23, S23);
        }
        float f0, f1, f2, f3;
        unpack2(a01, f0, f1); unpack2(a23, f2, f3);
        float* gh = g_hb + ((size_t)bh * PP + p) * NK + 4 * q;
        gh[0] = f0; gh[1] = f1; gh[2] = f2; gh[3] = f3;
    }
}

// ---------------- P3: within-chunk scan + y ----------------
#define T3_DA 0
#define T3_U  2048
#define T3_C  4096
#define T3_X  6144
__global__ __launch_bounds__(128, 4) void scan_p3()
{
    __shared__ __align__(16) float sm3[10240];
    int bid = blockIdx.x;
    int c   = bid & 15;
    int bh  = (bid >> 4) & 15;
    int dir = bid >> 8;
    int b = bh >> 3, h = bh & 7;
    int tid = threadIdx.x;

    const float* gdA = g_dA + ((size_t)bh * LL + (size_t)c * CHL) * NK;
    const float* gu  = (dir ? g_ub : g_uf) + ((size_t)bh * LL + (size_t)c * CHL) * NK;
    const float* gC  = (dir ? g_Cb2 : g_Cf) + ((size_t)b * LL + (size_t)c * CHL) * NK;
    const float* gx  = (dir ? g_convb : g_convf)
                     + ((size_t)b * LL + (size_t)c * CHL) * CC + h * PP;
    float* gy = (dir ? g_yb : g_yf)
              + ((size_t)b * LL + (size_t)c * CHL) * DI + h * PP + tid;

    ull hh[32];
    {
        const float* hs = (dir ? g_hsb : g_hsf)
                        + (((size_t)bh * NCH + c) * PP + tid) * NK;
#pragma unroll
        for (int i = 0; i < 16; i++) {
            ulonglong2 v = *(const ulonglong2*)&hs[i * 4];
            hh[2 * i] = v.x; hh[2 * i + 1] = v.y;
        }
    }

    auto load_tile = [&](int buf, int tile) {
        const float* da = gdA + (size_t)tile * 16 * NK;
        const float* uu = gu + (size_t)tile * 16 * NK;
        const float* cc = gC + (size_t)tile * 16 * NK;
        cpasync16(smem_u32(&sm3[T3_DA + buf * 1024 + tid * 8]),     da + tid * 8);
        cpasync16(smem_u32(&sm3[T3_DA + buf * 1024 + tid * 8 + 4]), da + tid * 8 + 4);
        cpasync16(smem_u32(&sm3[T3_U  + buf * 1024 + tid * 8]),     uu + tid * 8);
        cpasync16(smem_u32(&sm3[T3_U  + buf * 1024 + tid * 8 + 4]), uu + tid * 8 + 4);
        cpasync16(smem_u32(&sm3[T3_C  + buf * 1024 + tid * 8]),     cc + tid * 8);
        cpasync16(smem_u32(&sm3[T3_C  + buf * 1024 + tid * 8 + 4]), cc + tid * 8 + 4);
#pragma unroll
        for (int i = 0; i < 4; i++) {
            int idx = tid + i * 128;
            int row = idx >> 5, c4 = idx & 31;
            const float* xs = gx + (size_t)(tile * 16 + row) * CC + c4 * 4;
            unsigned sd = smem_u32(&sm3[T3_X + buf * 2048 + row * 128 + c4 * 4]);
            cpasync8(sd, xs);
            cpasync8(sd + 8, xs + 2);
        }
        asm volatile("cp.async.commit_group;\n");
    };

    load_tile(0, dir ? 7 : 0);
    for (int s = 0; s < 8; s++) {
        if (s + 1 < 8) {
            load_tile((s + 1) & 1, dir ? 6 - s : s + 1);
            asm volatile("cp.async.wait_group 1;\n");
        } else {
            asm volatile("cp.async.wait_group 0;\n");
        }
        __syncthreads();
        int buf = s & 1;
        int tile = dir ? 7 - s : s;
#pragma unroll 2
        for (int j = 0; j < 16; j++) {
            int tt = dir ? (15 - j) : j;
            float xp = sm3[T3_X + buf * 2048 + tt * 128 + tid];
            ull xx = pack2(xp, xp);
            const float* da = &sm3[T3_DA + buf * 1024 + tt * 64];
            const float* uu = &sm3[T3_U  + buf * 1024 + tt * 64];
            const float* cv = &sm3[T3_C  + buf * 1024 + tt * 64];
            ull acc0 = 0, acc1 = 0, acc2 = 0, acc3 = 0;
#pragma unroll
            for (int i = 0; i < 16; i++) {
                ulonglong2 av = *(const ulonglong2*)&da[i * 4];
                ulonglong2 uv = *(const ulonglong2*)&uu[i * 4];
                ulonglong2 c2 = *(const ulonglong2*)&cv[i * 4];
                hh[2 * i]     = fma2(av.x, hh[2 * i],     mul2(uv.x, xx));
                hh[2 * i + 1] = fma2(av.y, hh[2 * i + 1], mul2(uv.y, xx));
                if (i & 1) {
                    acc2 = fma2(c2.x, hh[2 * i], acc2);
                    acc3 = fma2(c2.y, hh[2 * i + 1], acc3);
                } else {
                    acc0 = fma2(c2.x, hh[2 * i], acc0);
                    acc1 = fma2(c2.y, hh[2 * i + 1], acc1);
                }
            }
            float a, bq, cq, d, e, f, g2, h2;
            unpack2(acc0, a, bq); unpack2(acc1, cq, d);
            unpack2(acc2, e, f);  unpack2(acc3, g2, h2);
            float y = ((a + bq) + (cq + d)) + ((e + f) + (g2 + h2));
            gy[(size_t)(tile * 16 + tt) * DI] = y;
        }
        __syncthreads();
    }
}

// ---------------- combine y, gate with silu(z), RMSNorm (tf32 out) ----------------
__global__ __launch_bounds__(256) void gate_norm_key_kernel(const float* __restrict__ Dp,
                                                            const float* __restrict__ normw)
{
    int bl = blockIdx.x;
    int tid = threadIdx.x;
    __shared__ float s_v[DI];
    __shared__ float sred[9];
    float ss = 0.f;
    size_t byDI = (size_t)bl * DI, byCC = (size_t)bl * CC, byNZ = (size_t)bl * NZ;
#pragma unroll
    for (int it = 0; it < 4; it++) {
        int i = tid + it * 256;
        int hh = i >> 7;
        float y = 0.5f * (g_yf[byDI + i] + g_yb[byDI + i])
                + 0.5f * Dp[hh] * (g_convf[byCC + i] + g_convb[byCC + i]);
        float z = g_zx[byNZ + i];
        float xg = y * z * (1.f / (1.f + __expf(-z)));
        s_v[i] = xg;
        ss += xg * xg;
    }
    for (int o = 16; o; o >>= 1) ss += __shfl_xor_sync(0xffffffffu, ss, o);
    if ((tid & 31) == 0) sred[tid >> 5] = ss;
    __syncthreads();
    if (tid == 0) {
        float t = 0.f;
        for (int w = 0; w < 8; w++) t += sred[w];
        sred[8] = rsqrtf(t * (1.f / DI) + 1e-5f);
    }
    __syncthreads();
    float sc = sred[8];
#pragma unroll
    for (int it = 0; it < 4; it++) {
        int i = tid + it * 256;
        g_xg[byDI + i] = to_tf32(s_v[i] * sc * normw[i]);
    }
}

// ---------------- query path: LayerNorm (tf32 out) ----------------
__global__ __launch_bounds__(256) void qnorm_kernel(const float* __restrict__ w,
                                                    const float* __restrict__ bi)
{
    int bk = blockIdx.x;
    int b = bk >> 6, k = bk & 63;
    int tid = threadIdx.x;
    __shared__ float s_v[DI];
    __shared__ float sred[18];
    float s1 = 0.f, s2 = 0.f;
#pragma unroll
    for (int it = 0; it < 4; it++) {
        int i = tid + it * 256;
        int hh = i >> 7, p = i & 127;
        size_t o = ((size_t)(b * NH + hh) * PP + p) * NK + k;
        float qv = 0.5f * (g_hf[o] + g_hb[o]);
        s_v[i] = qv;
        s1 += qv;
        s2 += qv * qv;
    }
    for (int o = 16; o; o >>= 1) {
        s1 += __shfl_xor_sync(0xffffffffu, s1, o);
        s2 += __shfl_xor_sync(0xffffffffu, s2, o);
    }
    if ((tid & 31) == 0) { sred[tid >> 5] = s1; sred[8 + (tid >> 5)] = s2; }
    __syncthreads();
    if (tid == 0) {
        float t1 = 0.f, t2 = 0.f;
        for (int wv = 0; wv < 8; wv++) { t1 += sred[wv]; t2 += sred[8 + wv]; }
        float mu = t1 * (1.f / DI);
        float var = t2 * (1.f / DI) - mu * mu;
        sred[16] = mu;
        sred[17] = rsqrtf(var + 1e-5f);
    }
    __syncthreads();
    float mu = sred[16], rs = sred[17];
#pragma unroll
    for (int it = 0; it < 4; it++) {
        int i = tid + it * 256;
        g_qn[(size_t)bk * DI + i] = to_tf32((s_v[i] - mu) * rs * w[i] + bi[i]);
    }
}

// ---------------- host launcher ----------------
extern "C" void kernel_launch(void* const* d_in, const int* in_sizes, int n_in,
                              void* d_out, int out_size)
{
    (void)in_sizes; (void)n_in; (void)out_size;
    const float* in_key      = (const float*)d_in[0];
    const float* in_query    = (const float*)d_in[1];
    const float* dist        = (const float*)d_in[2];
    const float* key_proj_w  = (const float*)d_in[4];
    const float* key_conv_w  = (const float*)d_in[5];
    const float* key_conv_b  = (const float*)d_in[6];
    const float* key_conv_bw = (const float*)d_in[7];
    const float* key_conv_bb = (const float*)d_in[8];
    const float* query_proj_w= (const float*)d_in[9];
    const float* bc_proj_w   = (const float*)d_in[10];
    const float* dt_proj_w   = (const float*)d_in[11];
    const float* dt_bias     = (const float*)d_in[12];
    const float* A_log       = (const float*)d_in[13];
    const float* D_param     = (const float*)d_in[14];
    const float* out_key_w   = (const float*)d_in[15];
    const float* out_query_w = (const float*)d_in[16];
    const float* key_norm_w  = (const float*)d_in[17];
    const float* q_ln_w      = (const float*)d_in[18];
    const float* q_ln_b      = (const float*)d_in[19];
    float* out = (float*)d_out;

    void *p_zx, *p_h0, *p_xg, *p_qn;
    void *p_rA1, *p_rW1, *p_rQ, *p_rWq, *p_rWo, *p_rWoq;
    cudaGetSymbolAddress(&p_zx, g_zx);
    cudaGetSymbolAddress(&p_h0, g_h0);
    cudaGetSymbolAddress(&p_xg, g_xg);
    cudaGetSymbolAddress(&p_qn, g_qn);
    cudaGetSymbolAddress(&p_rA1, g_rA1);
    cudaGetSymbolAddress(&p_rW1, g_rW1);
    cudaGetSymbolAddress(&p_rQ, g_rQ);
    cudaGetSymbolAddress(&p_rWq, g_rWq);
    cudaGetSymbolAddress(&p_rWo, g_rWo);
    cudaGetSymbolAddress(&p_rWoq, g_rWoq);

    cudaFuncSetAttribute(gemm_mma, cudaFuncAttributeMaxDynamicSharedMemorySize, DSMEM_G);
    cudaFuncSetAttribute(sgemm_s_kernel, cudaFuncAttributeMaxDynamicSharedMemorySize, DSMEM_SG);

    // #1: fused prerounds + zeros
    {
        size_t n = ((size_t)BLT * DM + (size_t)NZ * DM + (size_t)BB * NK * DM
                    + (size_t)DI * DM + 2ull * DM * DI
                    + (size_t)BB * NK * DI + (size_t)BB * NK * DM) / 4;
        prep_all_kernel<<<(int)((n + 255) / 256), 256>>>(
            in_key, key_proj_w, in_query, query_proj_w, out_key_w, out_query_w,
            out + (size_t)BLT * DM);
    }
    // #2: zxbcdt = in_key @ key_proj_w^T
    {
        dim3 grid((NZ + 127) / 128, BLT / 128, 1);
        gemm_mma<<<grid, 128, DSMEM_G>>>((const float*)p_rA1, (const float*)p_rW1,
                                         (float*)p_zx, BLT, NZ, DM);
    }
    // #3: fused conv + dtbc
    convdtbc_kernel<<<CONV_BLKS + DTBC_BLKS, 256>>>(
        key_conv_w, key_conv_b, key_conv_bw, key_conv_bb,
        dist, bc_proj_w, dt_proj_w, dt_bias, A_log);
    // #4 (profiled): w-prep v2 (segment-parallel)
    wprep_kernel<<<512, 256>>>();
    // #5: x transpose (tf32)
    {
        dim3 grid(DI / 32, LL / 32, 2 * BB);
        xpose_kernel<<<grid, 256>>>();
    }
    // #6: S = w @ xT (tensor cores)
    sgemm_s_kernel<<<512, 128, DSMEM_SG>>>();
    // #7: h0 = in_query @ query_proj_w^T, split-K x4
    {
        dim3 grid(DI / 128, 1, 4);
        gemm_mma<<<grid, 128, DSMEM_G>>>((const float*)p_rQ, (const float*)p_rWq,
                                         (float*)p_h0, BB * NK, DI, DM);
    }
    // #8: scan P2
    scan_p2<<<128, 256>>>();
    // #9: scan P3
    scan_p3<<<512, 128>>>();
    // #10: combine + gate + RMSNorm
    gate_norm_key_kernel<<<BLT, 256>>>(D_param, key_norm_w);
    // #11: out_key = key_n @ out_key_w^T
    {
        dim3 grid(DM / 128, BLT / 128, 1);
        gemm_mma<<<grid, 128, DSMEM_G>>>((const float*)p_xg, (const float*)p_rWo,
                                         out, BLT, DM, DI);
    }
    // #12: query layer norm
    qnorm_kernel<<<BB * NK, 256>>>(q_ln_w, q_ln_b);
    // #13: out_query = qn @ out_query_w^T, split-K x8
    {
        dim3 grid(DM / 128, 1, 8);
        gemm_mma<<<grid, 128, DSMEM_G>>>((const float*)p_qn, (const float*)p_rWoq,
                                         out + (size_t)BLT * DM, BB * NK, DM, DI);
    }
}

// round 16
// speedup vs baseline: 1.7717x; 1.1883x over previous
#include <cuda_runtime.h>
#include <cuda_bf16.h>
#include <cuda_fp16.h>
#include <cstdint>

// ---------------- problem constants ----------------
#define BB 2
#define LL 2048
#define NK 64
#define DM 512
#define DI 1024
#define NH 8
#define PP 128
#define NZ 2058
#define CC 1026
#define BLT (BB*LL)
#define NCH 16
#define CHL 128

typedef unsigned long long ull;

// ---------------- scratch ----------------
__device__ float g_zx   [(size_t)BB*LL*NZ];
__device__ float g_convf[(size_t)BB*LL*CC];
__device__ float g_convb[(size_t)BB*LL*CC];
__device__ float g_dA   [(size_t)BB*NH*LL*NK];
__device__ float g_uf   [(size_t)BB*NH*LL*NK];
__device__ float g_ub   [(size_t)BB*NH*LL*NK];
__device__ float g_Cf   [(size_t)BB*LL*NK];
__device__ float g_Cb2  [(size_t)BB*LL*NK];
__device__ float g_h0   [(size_t)BB*NK*DI];
__device__ float g_yf   [(size_t)BB*LL*DI];
__device__ float g_yb   [(size_t)BB*LL*DI];
__device__ float g_hf   [(size_t)BB*NH*PP*NK];
__device__ float g_hb   [(size_t)BB*NH*PP*NK];
__device__ float g_xg   [(size_t)BB*LL*DI];
__device__ float g_qn   [(size_t)BB*NK*DI];
// chunked-scan intermediates
__device__ float g_Sf  [(size_t)16*NCH*NK*PP];   // [bh][c][n][p]
__device__ float g_Sb  [(size_t)16*NCH*NK*PP];
__device__ float g_P   [(size_t)16*NCH*NK];
__device__ float g_hsf [(size_t)16*NCH*PP*NK];   // [bh][c][p][n]
__device__ float g_hsb [(size_t)16*NCH*PP*NK];
__device__ float g_wf  [(size_t)16*NCH*NK*CHL];  // [bh][c][n][t], tf32
__device__ float g_wb  [(size_t)16*NCH*NK*CHL];
__device__ float g_xTf [(size_t)16*PP*LL];       // [bh][p][t], tf32
__device__ float g_xTb [(size_t)16*PP*LL];
// fp16 copies of GEMM inputs
__device__ __half g_hA1 [(size_t)BLT*DM];
__device__ __half g_hW1 [(size_t)NZ*DM];
__device__ __half g_hQ  [(size_t)BB*NK*DM];
__device__ __half g_hWq [(size_t)DI*DM];
__device__ __half g_hWo [(size_t)DM*DI];
__device__ __half g_hWoq[(size_t)DM*DI];
__device__ __half g_hXg [(size_t)BB*LL*DI];
__device__ __half g_hQn [(size_t)BB*NK*DI];

// ---------------- helpers ----------------
__device__ __forceinline__ unsigned smem_u32(const void* p) {
    return (unsigned)__cvta_generic_to_shared(p);
}
__device__ __forceinline__ void cpasync16(unsigned s, const void* g) {
    asm volatile("cp.async.cg.shared.global [%0],[%1],16;\n" ::"r"(s), "l"(g));
}
__device__ __forceinline__ void cpasync16z(unsigned s, const void* g, unsigned srcsz) {
    asm volatile("cp.async.cg.shared.global [%0],[%1],16,%2;\n" ::"r"(s), "l"(g), "r"(srcsz));
}
__device__ __forceinline__ void cpasync8(unsigned s, const void* g) {
    asm volatile("cp.async.ca.shared.global [%0],[%1],8;\n" ::"r"(s), "l"(g));
}
__device__ __forceinline__ float to_tf32(float x) {
    float r; asm("cvt.rna.tf32.f32 %0,%1;" : "=f"(r) : "f"(x)); return r;
}
__device__ __forceinline__ void mma_tf32(float* c, const uint32_t* a, uint32_t b0, uint32_t b1) {
    asm volatile(
        "mma.sync.aligned.m16n8k8.row.col.f32.tf32.tf32.f32 "
        "{%0,%1,%2,%3}, {%4,%5,%6,%7}, {%8,%9}, {%0,%1,%2,%3};"
        : "+f"(c[0]), "+f"(c[1]), "+f"(c[2]), "+f"(c[3])
        : "r"(a[0]), "r"(a[1]), "r"(a[2]), "r"(a[3]), "r"(b0), "r"(b1));
}
__device__ __forceinline__ void mma_f16(float* c, const uint32_t* a, uint32_t b0, uint32_t b1) {
    asm volatile(
        "mma.sync.aligned.m16n8k16.row.col.f32.f16.f16.f32 "
        "{%0,%1,%2,%3}, {%4,%5,%6,%7}, {%8,%9}, {%0,%1,%2,%3};"
        : "+f"(c[0]), "+f"(c[1]), "+f"(c[2]), "+f"(c[3])
        : "r"(a[0]), "r"(a[1]), "r"(a[2]), "r"(a[3]), "r"(b0), "r"(b1));
}
__device__ __forceinline__ ull mul2(ull a, ull b) {
    ull d; asm("mul.rn.f32x2 %0,%1,%2;" : "=l"(d) : "l"(a), "l"(b)); return d;
}
__device__ __forceinline__ ull fma2(ull a, ull b, ull c) {
    ull d; asm("fma.rn.f32x2 %0,%1,%2,%3;" : "=l"(d) : "l"(a), "l"(b), "l"(c)); return d;
}
__device__ __forceinline__ ull pack2(float x, float y) {
    ull d; asm("mov.b64 %0,{%1,%2};" : "=l"(d) : "f"(x), "f"(y)); return d;
}
__device__ __forceinline__ void unpack2(ull v, float& x, float& y) {
    asm("mov.b64 {%0,%1},%2;" : "=f"(x), "=f"(y) : "l"(v));
}
__device__ __forceinline__ uint2 f4_to_h4(float4 v) {
    __half2 lo = __floats2half2_rn(v.x, v.y);
    __half2 hi = __floats2half2_rn(v.z, v.w);
    uint2 r;
    r.x = *(const unsigned*)&lo;
    r.y = *(const unsigned*)&hi;
    return r;
}

// ---------------- #1: fused fp16 conversions + zero accumulators ----------------
__global__ __launch_bounds__(256) void prep_all_kernel(
    const float* __restrict__ a1, const float* __restrict__ w1,
    const float* __restrict__ q,  const float* __restrict__ wq,
    const float* __restrict__ wo, const float* __restrict__ woq,
    float* __restrict__ outq)
{
    const size_t n1 = (size_t)BLT * DM / 4;
    const size_t n2 = n1 + (size_t)NZ * DM / 4;
    const size_t n3 = n2 + (size_t)BB * NK * DM / 4;
    const size_t n4 = n3 + (size_t)DI * DM / 4;
    const size_t n5 = n4 + (size_t)DM * DI / 4;
    const size_t n6 = n5 + (size_t)DM * DI / 4;
    const size_t n7 = n6 + (size_t)BB * NK * DI / 4;
    const size_t n8 = n7 + (size_t)BB * NK * DM / 4;
    size_t i = (size_t)blockIdx.x * 256 + threadIdx.x;
    if (i >= n8) return;
    if (i >= n6) {
        float4 z = make_float4(0.f, 0.f, 0.f, 0.f);
        if (i < n7) ((float4*)g_h0)[i - n6] = z;
        else        ((float4*)outq)[i - n7] = z;
        return;
    }
    const float* src; __half* dst; size_t off;
    if      (i < n1) { src = a1;  dst = g_hA1;  off = i; }
    else if (i < n2) { src = w1;  dst = g_hW1;  off = i - n1; }
    else if (i < n3) { src = q;   dst = g_hQ;   off = i - n2; }
    else if (i < n4) { src = wq;  dst = g_hWq;  off = i - n3; }
    else if (i < n5) { src = wo;  dst = g_hWo;  off = i - n4; }
    else             { src = woq; dst = g_hWoq; off = i - n5; }
    float4 v = ((const float4*)src)[off];
    ((uint2*)dst)[off] = f4_to_h4(v);
}

// ---------------- fp16 tensor-core GEMM: 4 warps, 64x64 warp tile, 3-stage ----------------
// A [M x K] half row-major (M % 128 == 0), W [N x K] half row-major, C [M x N] fp32.
// K % 32 == 0; K/32 % gridDim.z == 0. split-K (z>1) -> pre-zeroed C, atomicAdd.
#define KCH 32
#define PADKH 40
#define STAGE_BH (128*PADKH*2)     // 10240 B
#define CHUNK_BH (2*STAGE_BH)      // 20480 B
#define DSMEM_G (3*CHUNK_BH)       // 61440 B

__global__ __launch_bounds__(128, 2) void gemm_mma(const __half* __restrict__ A,
                                                   const __half* __restrict__ W,
                                                   float* __restrict__ C,
                                                   int M, int N, int K)
{
    extern __shared__ __align__(16) char dsm[];
    const int tid = threadIdx.x;
    const int lid = tid & 31, wrp = tid >> 5;
    const int wm = wrp & 1, wn = wrp >> 1;
    const int gid = lid >> 2, tig = lid & 3;
    const int m0 = blockIdx.y * 128, n0 = blockIdx.x * 128;
    const unsigned sbase = smem_u32(dsm);

    const int totCh = K >> 5;
    const int per = totCh / gridDim.z;
    const int cbase = blockIdx.z * per;
    const bool split = gridDim.z > 1;

    auto load_chunk = [&](int st, int ch) {
        const __half* Ap = A + (size_t)m0 * K + ch * KCH;
        const __half* Wp = W + (size_t)n0 * K + ch * KCH;
        unsigned ao = (unsigned)st * CHUNK_BH;
        unsigned bo = ao + STAGE_BH;
#pragma unroll
        for (int i = 0; i < 4; i++) {
            int idx = tid + i * 128;
            int row = idx >> 2, kg = idx & 3;     // 4 x 8 halfs = 32
            unsigned so = (unsigned)(row * PADKH * 2 + kg * 16);
            cpasync16(sbase + ao + so, Ap + (size_t)row * K + kg * 8);
            int nrow = n0 + row;
            int cl = (nrow < N) ? nrow : (N - 1);
            cpasync16z(sbase + bo + so, Wp + (size_t)(cl - n0) * K + kg * 8,
                       (nrow < N) ? 16u : 0u);
        }
        asm volatile("cp.async.commit_group;\n" ::: "memory");
    };

    float acc[4][8][4];
#pragma unroll
    for (int mf = 0; mf < 4; mf++)
#pragma unroll
        for (int nf = 0; nf < 8; nf++)
#pragma unroll
            for (int i = 0; i < 4; i++) acc[mf][nf][i] = 0.f;

    load_chunk(0, cbase);
    if (per > 1) load_chunk(1, cbase + 1);

    int st = 0;
    for (int c = 0; c < per; c++) {
        if (c + 1 < per) asm volatile("cp.async.wait_group 1;\n" ::: "memory");
        else             asm volatile("cp.async.wait_group 0;\n" ::: "memory");
        __syncthreads();
        if (c + 2 < per) {
            int st2 = st + 2; if (st2 >= 3) st2 -= 3;
            load_chunk(st2, cbase + c + 2);
        }
        const __half* as = (const __half*)(dsm + st * CHUNK_BH);
        const __half* bs = (const __half*)(dsm + st * CHUNK_BH + STAGE_BH);
#pragma unroll
        for (int ks = 0; ks < 2; ks++) {
            int k0 = ks * 16;
            uint32_t af[4][4];
#pragma unroll
            for (int mf = 0; mf < 4; mf++) {
                int r = wm * 64 + mf * 16 + gid;
                af[mf][0] = *(const uint32_t*)&as[r * PADKH + k0 + 2 * tig];
                af[mf][1] = *(const uint32_t*)&as[(r + 8) * PADKH + k0 + 2 * tig];
                af[mf][2] = *(const uint32_t*)&as[r * PADKH + k0 + 2 * tig + 8];
                af[mf][3] = *(const uint32_t*)&as[(r + 8) * PADKH + k0 + 2 * tig + 8];
            }
#pragma unroll
            for (int nf = 0; nf < 8; nf++) {
                int nr = wn * 64 + nf * 8 + gid;
                uint32_t b0 = *(const uint32_t*)&bs[nr * PADKH + k0 + 2 * tig];
                uint32_t b1 = *(const uint32_t*)&bs[nr * PADKH + k0 + 2 * tig + 8];
#pragma unroll
                for (int mf = 0; mf < 4; mf++)
                    mma_f16(acc[mf][nf], af[mf], b0, b1);
            }
        }
        if (++st >= 3) st = 0;
    }

#pragma unroll
    for (int mf = 0; mf < 4; mf++) {
        int r0 = m0 + wm * 64 + mf * 16 + gid;
#pragma unroll
        for (int nf = 0; nf < 8; nf++) {
            int col = n0 + wn * 64 + nf * 8 + tig * 2;
            if (col < N) {
                float* p0 = &C[(size_t)r0 * N + col];
                float* p1 = &C[(size_t)(r0 + 8) * N + col];
                if (!split) {
                    *(float2*)p0 = make_float2(acc[mf][nf][0], acc[mf][nf][1]);
                    *(float2*)p1 = make_float2(acc[mf][nf][2], acc[mf][nf][3]);
                } else {
                    atomicAdd(p0,     acc[mf][nf][0]);
                    atomicAdd(p0 + 1, acc[mf][nf][1]);
                    atomicAdd(p1,     acc[mf][nf][2]);
                    atomicAdd(p1 + 1, acc[mf][nf][3]);
                }
            }
        }
    }
}

// ---------------- #3: fused conv + dtbc ----------------
#define CONV_BLKS (((CC + 255) / 256) * (LL / 8) * (2 * BB))
#define DTBC_BLKS (BLT / 4)

__global__ __launch_bounds__(256) void convdtbc_kernel(
    const float* __restrict__ cwf, const float* __restrict__ cbf,
    const float* __restrict__ cwb, const float* __restrict__ cbb,
    const float* __restrict__ dist, const float* __restrict__ bcw,
    const float* __restrict__ dtw, const float* __restrict__ dt_bias,
    const float* __restrict__ A_log)
{
    int bid = blockIdx.x;
    int tid = threadIdx.x;
    if (bid < CONV_BLKS) {
        int cblk = bid % 5;
        int rest = bid / 5;
        int l0 = (rest & 255) * 8;
        int db = rest >> 8;
        int dir = db >> 1, b = db & 1;
        int c = cblk * 256 + tid;
        if (c >= CC) return;

        const float* wsrc = (dir ? cwb : cwf) + c * 7;
        float wr[7];
#pragma unroll
        for (int t = 0; t < 7; t++) wr[t] = wsrc[t];
        float bias = (dir ? cbb : cbf)[c];

        const float* src = g_zx + (size_t)b * LL * NZ + DI + c;
        float win[14];
#pragma unroll
        for (int i = 0; i < 14; i++) {
            int l = l0 - 3 + i;
            win[i] = (0 <= l && l < LL) ? src[(size_t)l * NZ] : 0.f;
        }
        float* dst = (dir ? g_convb : g_convf) + ((size_t)b * LL + l0) * CC + c;
#pragma unroll
        for (int j = 0; j < 8; j++) {
            float acc = bias;
#pragma unroll
            for (int t = 0; t < 7; t++) acc = fmaf(wr[t], win[j + t], acc);
            float sig = 1.f / (1.f + __expf(-acc));
            dst[(size_t)j * CC] = acc * sig;
        }
        return;
    }
    {
        int bl = (bid - CONV_BLKS) * 4 + (tid >> 6);
        int b = bl / LL, l = bl % LL;
        int k = tid & 63;

        float resf[2], resb[2];
        const float* zsrc = g_zx + (size_t)b * LL * NZ + 2 * DI;
#pragma unroll
        for (int ch = 0; ch < 2; ch++) {
            float af = cbf[1024 + ch], ab = cbb[1024 + ch];
#pragma unroll
            for (int t = 0; t < 7; t++) {
                int l2 = l + t - 3;
                if (0 <= l2 && l2 < LL) {
                    float v = zsrc[(size_t)l2 * NZ + ch];
                    af = fmaf(cwf[(1024 + ch) * 7 + t], v, af);
                    ab = fmaf(cwb[(1024 + ch) * 7 + t], v, ab);
                }
            }
            resf[ch] = af * (1.f / (1.f + __expf(-af)));
            resb[ch] = ab * (1.f / (1.f + __expf(-ab)));
        }
        float bbf = resf[0], cbfv = resf[1], bbb = resb[0], cbbv = resb[1];

        float4 d4 = *(const float4*)&dist[((size_t)bl * NK + k) * 4];
        float bb = d4.x * bcw[0] + d4.y * bcw[1] + d4.z * bcw[2] + d4.w * bcw[3];
        float cb = d4.x * bcw[4] + d4.y * bcw[5] + d4.z * bcw[6] + d4.w * bcw[7];
        g_Cf [(size_t)bl * NK + k] = cb + cbfv;
        g_Cb2[(size_t)bl * NK + k] = cb + cbbv;
        float Bf = bb + bbf, Bbk = bb + bbb;
        size_t zoff = (size_t)bl * NZ + 2 * DI + 2;
#pragma unroll
        for (int h = 0; h < NH; h++) {
            float pre = d4.x * dtw[h * 4 + 0] + d4.y * dtw[h * 4 + 1]
                      + d4.z * dtw[h * 4 + 2] + d4.w * dtw[h * 4 + 3]
                      + g_zx[zoff + h] + dt_bias[h];
            float dt = (pre > 20.f) ? pre : log1pf(__expf(pre));
            float Ah = -__expf(A_log[h]);
            float dA = __expf(dt * Ah);
            size_t o = (((size_t)(b * NH + h) * LL) + l) * NK + k;
            g_dA[o] = dA;
            g_uf[o] = dt * Bf;
            g_ub[o] = dt * Bbk;
        }
    }
}

// ---------------- #4: w-prep (segment-parallel) ----------------
__global__ __launch_bounds__(256) void wprep_kernel()
{
    __shared__ float sp[4][64];
    int bid = blockIdx.x;
    int dir = bid & 1;
    int c   = (bid >> 1) & 15;
    int bh  = bid >> 5;
    int n   = threadIdx.x & 63;
    int seg = threadIdx.x >> 6;
    const int t0 = seg * 32;

    const float* dA = g_dA + ((size_t)bh * LL + (size_t)c * CHL) * NK + n;
    const float* uu = (dir ? g_ub : g_uf) + ((size_t)bh * LL + (size_t)c * CHL) * NK + n;
    float* w = (dir ? g_wb : g_wf) + (((size_t)bh * NCH + c) * NK + n) * CHL;

    float spv = 1.f;
#pragma unroll 8
    for (int t = 0; t < 32; t++) spv *= dA[(size_t)(t0 + t) * NK];
    sp[seg][n] = spv;
    __syncthreads();

    if (dir == 0) {
        float F = 1.f;
#pragma unroll
        for (int s = 1; s < 4; s++) if (s > seg) F *= sp[s][n];
        float run = F;
        float buf[4];
#pragma unroll 4
        for (int t = 31; t >= 0; t--) {
            int tt = t0 + t;
            buf[t & 3] = to_tf32(run * uu[(size_t)tt * NK]);
            run *= dA[(size_t)tt * NK];
            if ((t & 3) == 0)
                *(float4*)&w[tt] = make_float4(buf[0], buf[1], buf[2], buf[3]);
        }
        if (seg == 0)
            g_P[((size_t)bh * NCH + c) * NK + n] =
                sp[0][n] * sp[1][n] * sp[2][n] * sp[3][n];
    } else {
        float F = 1.f;
#pragma unroll
        for (int s = 0; s < 3; s++) if (s < seg) F *= sp[s][n];
        float run = F;
        float buf[4];
#pragma unroll 4
        for (int t = 0; t < 32; t++) {
            int tt = t0 + t;
            buf[t & 3] = to_tf32(run * uu[(size_t)tt * NK]);
            run *= dA[(size_t)tt * NK];
            if ((t & 3) == 3)
                *(float4*)&w[tt - 3] = make_float4(buf[0], buf[1], buf[2], buf[3]);
        }
    }
}

// ---------------- #5: transpose x to [bh][p][t], tf32 ----------------
__global__ __launch_bounds__(256) void xpose_kernel()
{
    __shared__ float tile[32][33];
    int db = blockIdx.z;
    int dir = db >> 1, b = db & 1;
    const float* src = (dir ? g_convb : g_convf) + (size_t)b * LL * CC;
    float* dst = dir ? g_xTb : g_xTf;
    int c0 = blockIdx.x * 32, l0 = blockIdx.y * 32;
    int tx = threadIdx.x & 31, ty = threadIdx.x >> 5;
#pragma unroll
    for (int i = 0; i < 4; i++) {
        int l = l0 + ty + i * 8;
        tile[ty + i * 8][tx] = src[(size_t)l * CC + c0 + tx];
    }
    __syncthreads();
#pragma unroll
    for (int i = 0; i < 4; i++) {
        int cc = c0 + ty + i * 8;
        int bh = b * 8 + (cc >> 7), p = cc & 127;
        dst[((size_t)bh * PP + p) * LL + l0 + tx] = to_tf32(tile[tx][ty + i * 8]);
    }
}

// ---------------- #6: S[n][p] = sum_t w[n][t] * xT[p][t] (tf32 MMA) ----------------
#define PADT 36
#define SGW_F (64*PADT)
#define SGX_F (128*PADT)
#define SGSTG_F (SGW_F + SGX_F)
#define DSMEM_SG (2*SGSTG_F*4)

__global__ __launch_bounds__(128, 4) void sgemm_s_kernel()
{
    extern __shared__ __align__(16) float sms[];
    int bid = blockIdx.x;
    int c   = bid & 15;
    int bh  = (bid >> 4) & 15;
    int dir = bid >> 8;
    int tid = threadIdx.x, lid = tid & 31, wp = tid >> 5;
    int gid = lid >> 2, tig = lid & 3;

    const float* wsrc = (dir ? g_wb : g_wf) + ((size_t)bh * NCH + c) * NK * CHL;
    const float* xT   = (dir ? g_xTb : g_xTf) + (size_t)bh * PP * LL + (size_t)c * CHL;
    float* S = (dir ? g_Sb : g_Sf) + ((size_t)bh * NCH + c) * NK * PP;

    auto load = [&](int st, int kt) {
        float* dw = sms + st * SGSTG_F;
        float* dx = dw + SGW_F;
#pragma unroll
        for (int i = 0; i < 4; i++) {
            int idx = tid + i * 128;
            int row = idx >> 3, kg = idx & 7;
            cpasync16(smem_u32(&dw[row * PADT + kg * 4]),
                      wsrc + (size_t)row * CHL + kt * 32 + kg * 4);
        }
#pragma unroll
        for (int i = 0; i < 8; i++) {
            int idx = tid + i * 128;
            int row = idx >> 3, kg = idx & 7;
            cpasync16(smem_u32(&dx[row * PADT + kg * 4]),
                      xT + (size_t)row * LL + kt * 32 + kg * 4);
        }
        asm volatile("cp.async.commit_group;\n" ::: "memory");
    };

    float acc[4][4][4];
#pragma unroll
    for (int mf = 0; mf < 4; mf++)
#pragma unroll
        for (int nf = 0; nf < 4; nf++)
#pragma unroll
            for (int i = 0; i < 4; i++) acc[mf][nf][i] = 0.f;

    load(0, 0);
    load(1, 1);
    for (int kt = 0; kt < 4; kt++) {
        if (kt + 1 < 4) asm volatile("cp.async.wait_group 1;\n" ::: "memory");
        else            asm volatile("cp.async.wait_group 0;\n" ::: "memory");
        __syncthreads();
        const float* dw = sms + (kt & 1) * SGSTG_F;
        const float* dx = dw + SGW_F;
#pragma unroll
        for (int kf = 0; kf < 4; kf++) {
            int k0 = kf * 8;
            uint32_t af[4][4];
#pragma unroll
            for (int mf = 0; mf < 4; mf++) {
                int r = mf * 16 + gid;
                af[mf][0] = __float_as_uint(dw[r * PADT + k0 + tig]);
                af[mf][1] = __float_as_uint(dw[(r + 8) * PADT + k0 + tig]);
                af[mf][2] = __float_as_uint(dw[r * PADT + k0 + tig + 4]);
                af[mf][3] = __float_as_uint(dw[(r + 8) * PADT + k0 + tig + 4]);
            }
#pragma unroll
            for (int nf = 0; nf < 4; nf++) {
                int pr = wp * 32 + nf * 8 + gid;
                uint32_t b0 = __float_as_uint(dx[pr * PADT + k0 + tig]);
                uint32_t b1 = __float_as_uint(dx[pr * PADT + k0 + tig + 4]);
#pragma unroll
                for (int mf = 0; mf < 4; mf++)
                    mma_tf32(acc[mf][nf], af[mf], b0, b1);
            }
        }
        __syncthreads();
        if (kt + 2 < 4) load(kt & 1, kt + 2);
    }

#pragma unroll
    for (int mf = 0; mf < 4; mf++) {
        int r0 = mf * 16 + gid;
#pragma unroll
        for (int nf = 0; nf < 4; nf++) {
            int col = wp * 32 + nf * 8 + tig * 2;
            *(float2*)&S[(size_t)r0 * PP + col] =
                make_float2(acc[mf][nf][0], acc[mf][nf][1]);
            *(float2*)&S[(size_t)(r0 + 8) * PP + col] =
                make_float2(acc[mf][nf][2], acc[mf][nf][3]);
        }
    }
}

// ---------------- P2: chunk combine (S in [n][p]) ----------------
__global__ __launch_bounds__(256) void scan_p2()
{
    int bid = blockIdx.x;
    int pblk = bid & 7, bh = bid >> 3;
    int b = bh >> 3, h = bh & 7;
    int tid = threadIdx.x;
    int q = tid & 15, pl = tid >> 4;
    int p = pblk * 16 + pl;

    ull h01, h23;
    {
        const float* hp = g_h0 + (size_t)b * NK * DI + h * PP + p;
        h01 = pack2(hp[(size_t)(4 * q + 0) * DI], hp[(size_t)(4 * q + 1) * DI]);
        h23 = pack2(hp[(size_t)(4 * q + 2) * DI], hp[(size_t)(4 * q + 3) * DI]);
    }
    {
        ull a01 = h01, a23 = h23;
        for (int c = 0; c < NCH; c++) {
            size_t ho = (((size_t)bh * NCH + c) * PP + p) * NK + 4 * q;
            *(ulonglong2*)&g_hsf[ho] = make_ulonglong2(a01, a23);
            ulonglong2 P2 = *(const ulonglong2*)&g_P[((size_t)bh * NCH + c) * NK + 4 * q];
            size_t sb = (((size_t)bh * NCH + c) * NK + 4 * q) * PP + p;
            ull S01 = pack2(g_Sf[sb], g_Sf[sb + PP]);
            ull S23 = pack2(g_Sf[sb + 2 * PP], g_Sf[sb + 3 * PP]);
            a01 = fma2(P2.x, a01, S01);
            a23 = fma2(P2.y, a23, S23);
        }
        float f0, f1, f2, f3;
        unpack2(a01, f0, f1); unpack2(a23, f2, f3);
        float* gh = g_hf + ((size_t)bh * PP + p) * NK + 4 * q;
        gh[0] = f0; gh[1] = f1; gh[2] = f2; gh[3] = f3;
    }
    {
        ull a01 = h01, a23 = h23;
        for (int c = NCH - 1; c >= 0; c--) {
            size_t ho = (((size_t)bh * NCH + c) * PP + p) * NK + 4 * q;
            *(ulonglong2*)&g_hsb[ho] = make_ulonglong2(a01, a23);
            ulonglong2 P2 = *(const ulonglong2*)&g_P[((size_t)bh * NCH + c) * NK + 4 * q];
            size_t sb = (((size_t)bh * NCH + c) * NK + 4 * q) * PP + p;
            ull S01 = pack2(g_Sb[sb], g_Sb[sb + PP]);
            ull S23 = pack2(g_Sb[sb + 2 * PP], g_Sb[sb + 3 * PP]);
            a01 = fma2(P2.x, a01, S01);
            a23 = fma2(P2.y, a23, S23);
        }
        float f0, f1, f2, f3;
        unpack2(a01, f0, f1); unpack2(a23, f2, f3);
        float* gh = g_hb + ((size_t)bh * PP + p) * NK + 4 * q;
        gh[0] = f0; gh[1] = f1; gh[2] = f2; gh[3] = f3;
    }
}

// ---------------- P3: within-chunk scan + y ----------------
#define T3_DA 0
#define T3_U  2048
#define T3_C  4096
#define T3_X  6144
__global__ __launch_bounds__(128, 4) void scan_p3()
{
    __shared__ __align__(16) float sm3[10240];
    int bid = blockIdx.x;
    int c   = bid & 15;
    int bh  = (bid >> 4) & 15;
    int dir = bid >> 8;
    int b = bh >> 3, h = bh & 7;
    int tid = threadIdx.x;

    const float* gdA = g_dA + ((size_t)bh * LL + (size_t)c * CHL) * NK;
    const float* gu  = (dir ? g_ub : g_uf) + ((size_t)bh * LL + (size_t)c * CHL) * NK;
    const float* gC  = (dir ? g_Cb2 : g_Cf) + ((size_t)b * LL + (size_t)c * CHL) * NK;
    const float* gx  = (dir ? g_convb : g_convf)
                     + ((size_t)b * LL + (size_t)c * CHL) * CC + h * PP;
    float* gy = (dir ? g_yb : g_yf)
              + ((size_t)b * LL + (size_t)c * CHL) * DI + h * PP + tid;

    ull hh[32];
    {
        const float* hs = (dir ? g_hsb : g_hsf)
                        + (((size_t)bh * NCH + c) * PP + tid) * NK;
#pragma unroll
        for (int i = 0; i < 16; i++) {
            ulonglong2 v = *(const ulonglong2*)&hs[i * 4];
            hh[2 * i] = v.x; hh[2 * i + 1] = v.y;
        }
    }

    auto load_tile = [&](int buf, int tile) {
        const float* da = gdA + (size_t)tile * 16 * NK;
        const float* uu = gu + (size_t)tile * 16 * NK;
        const float* cc = gC + (size_t)tile * 16 * NK;
        cpasync16(smem_u32(&sm3[T3_DA + buf * 1024 + tid * 8]),     da + tid * 8);
        cpasync16(smem_u32(&sm3[T3_DA + buf * 1024 + tid * 8 + 4]), da + tid * 8 + 4);
        cpasync16(smem_u32(&sm3[T3_U  + buf * 1024 + tid * 8]),     uu + tid * 8);
        cpasync16(smem_u32(&sm3[T3_U  + buf * 1024 + tid * 8 + 4]), uu + tid * 8 + 4);
        cpasync16(smem_u32(&sm3[T3_C  + buf * 1024 + tid * 8]),     cc + tid * 8);
        cpasync16(smem_u32(&sm3[T3_C  + buf * 1024 + tid * 8 + 4]), cc + tid * 8 + 4);
#pragma unroll
        for (int i = 0; i < 4; i++) {
            int idx = tid + i * 128;
            int row = idx >> 5, c4 = idx & 31;
            const float* xs = gx + (size_t)(tile * 16 + row) * CC + c4 * 4;
            unsigned sd = smem_u32(&sm3[T3_X + buf * 2048 + row * 128 + c4 * 4]);
            cpasync8(sd, xs);
            cpasync8(sd + 8, xs + 2);
        }
        asm volatile("cp.async.commit_group;\n");
    };

    load_tile(0, dir ? 7 : 0);
    for (int s = 0; s < 8; s++) {
        if (s + 1 < 8) {
            load_tile((s + 1) & 1, dir ? 6 - s : s + 1);
            asm volatile("cp.async.wait_group 1;\n");
        } else {
            asm volatile("cp.async.wait_group 0;\n");
        }
        __syncthreads();
        int buf = s & 1;
        int tile = dir ? 7 - s : s;
#pragma unroll 2
        for (int j = 0; j < 16; j++) {
            int tt = dir ? (15 - j) : j;
            float xp = sm3[T3_X + buf * 2048 + tt * 128 + tid];
            ull xx = pack2(xp, xp);
            const float* da = &sm3[T3_DA + buf * 1024 + tt * 64];
            const float* uu = &sm3[T3_U  + buf * 1024 + tt * 64];
            const float* cv = &sm3[T3_C  + buf * 1024 + tt * 64];
            ull acc0 = 0, acc1 = 0, acc2 = 0, acc3 = 0;
#pragma unroll
            for (int i = 0; i < 16; i++) {
                ulonglong2 av = *(const ulonglong2*)&da[i * 4];
                ulonglong2 uv = *(const ulonglong2*)&uu[i * 4];
                ulonglong2 c2 = *(const ulonglong2*)&cv[i * 4];
                hh[2 * i]     = fma2(av.x, hh[2 * i],     mul2(uv.x, xx));
                hh[2 * i + 1] = fma2(av.y, hh[2 * i + 1], mul2(uv.y, xx));
                if (i & 1) {
                    acc2 = fma2(c2.x, hh[2 * i], acc2);
                    acc3 = fma2(c2.y, hh[2 * i + 1], acc3);
                } else {
                    acc0 = fma2(c2.x, hh[2 * i], acc0);
                    acc1 = fma2(c2.y, hh[2 * i + 1], acc1);
                }
            }
            float a, bq, cq, d, e, f, g2, h2;
            unpack2(acc0, a, bq); unpack2(acc1, cq, d);
            unpack2(acc2, e, f);  unpack2(acc3, g2, h2);
            float y = ((a + bq) + (cq + d)) + ((e + f) + (g2 + h2));
            gy[(size_t)(tile * 16 + tt) * DI] = y;
        }
        __syncthreads();
    }
}

// ---------------- combine y, gate with silu(z), RMSNorm (fp16 out) ----------------
__global__ __launch_bounds__(256) void gate_norm_key_kernel(const float* __restrict__ Dp,
                                                            const float* __restrict__ normw)
{
    int bl = blockIdx.x;
    int tid = threadIdx.x;
    __shared__ float s_v[DI];
    __shared__ float sred[9];
    float ss = 0.f;
    size_t byDI = (size_t)bl * DI, byCC = (size_t)bl * CC, byNZ = (size_t)bl * NZ;
#pragma unroll
    for (int it = 0; it < 4; it++) {
        int i = tid + it * 256;
        int hh = i >> 7;
        float y = 0.5f * (g_yf[byDI + i] + g_yb[byDI + i])
                + 0.5f * Dp[hh] * (g_convf[byCC + i] + g_convb[byCC + i]);
        float z = g_zx[byNZ + i];
        float xg = y * z * (1.f / (1.f + __expf(-z)));
        s_v[i] = xg;
        ss += xg * xg;
    }
    for (int o = 16; o; o >>= 1) ss += __shfl_xor_sync(0xffffffffu, ss, o);
    if ((tid & 31) == 0) sred[tid >> 5] = ss;
    __syncthreads();
    if (tid == 0) {
        float t = 0.f;
        for (int w = 0; w < 8; w++) t += sred[w];
        sred[8] = rsqrtf(t * (1.f / DI) + 1e-5f);
    }
    __syncthreads();
    float sc = sred[8];
#pragma unroll
    for (int it = 0; it < 2; it++) {
        int i = tid * 2 + it * 512;
        __half2 hv = __floats2half2_rn(s_v[i] * sc * normw[i],
                                       s_v[i + 1] * sc * normw[i + 1]);
        *(__half2*)&g_hXg[byDI + i] = hv;
    }
}

// ---------------- query path: LayerNorm (fp16 out) ----------------
__global__ __launch_bounds__(256) void qnorm_kernel(const float* __restrict__ w,
                                                    const float* __restrict__ bi)
{
    int bk = blockIdx.x;
    int b = bk >> 6, k = bk & 63;
    int tid = threadIdx.x;
    __shared__ float s_v[DI];
    __shared__ float sred[18];
    float s1 = 0.f, s2 = 0.f;
#pragma unroll
    for (int it = 0; it < 4; it++) {
        int i = tid + it * 256;
        int hh = i >> 7, p = i & 127;
        size_t o = ((size_t)(b * NH + hh) * PP + p) * NK + k;
        float qv = 0.5f * (g_hf[o] + g_hb[o]);
        s_v[i] = qv;
        s1 += qv;
        s2 += qv * qv;
    }
    for (int o = 16; o; o >>= 1) {
        s1 += __shfl_xor_sync(0xffffffffu, s1, o);
        s2 += __shfl_xor_sync(0xffffffffu, s2, o);
    }
    if ((tid & 31) == 0) { sred[tid >> 5] = s1; sred[8 + (tid >> 5)] = s2; }
    __syncthreads();
    if (tid == 0) {
        float t1 = 0.f, t2 = 0.f;
        for (int wv = 0; wv < 8; wv++) { t1 += sred[wv]; t2 += sred[8 + wv]; }
        float mu = t1 * (1.f / DI);
        float var = t2 * (1.f / DI) - mu * mu;
        sred[16] = mu;
        sred[17] = rsqrtf(var + 1e-5f);
    }
    __syncthreads();
    float mu = sred[16], rs = sred[17];
#pragma unroll
    for (int it = 0; it < 2; it++) {
        int i = tid * 2 + it * 512;
        __half2 hv = __floats2half2_rn((s_v[i] - mu) * rs * w[i] + bi[i],
                                       (s_v[i + 1] - mu) * rs * w[i + 1] + bi[i + 1]);
        *(__half2*)&g_hQn[(size_t)bk * DI + i] = hv;
    }
}

// ---------------- host launcher ----------------
extern "C" void kernel_launch(void* const* d_in, const int* in_sizes, int n_in,
                              void* d_out, int out_size)
{
    (void)in_sizes; (void)n_in; (void)out_size;
    const float* in_key      = (const float*)d_in[0];
    const float* in_query    = (const float*)d_in[1];
    const float* dist        = (const float*)d_in[2];
    const float* key_proj_w  = (const float*)d_in[4];
    const float* key_conv_w  = (const float*)d_in[5];
    const float* key_conv_b  = (const float*)d_in[6];
    const float* key_conv_bw = (const float*)d_in[7];
    const float* key_conv_bb = (const float*)d_in[8];
    const float* query_proj_w= (const float*)d_in[9];
    const float* bc_proj_w   = (const float*)d_in[10];
    const float* dt_proj_w   = (const float*)d_in[11];
    const float* dt_bias     = (const float*)d_in[12];
    const float* A_log       = (const float*)d_in[13];
    const float* D_param     = (const float*)d_in[14];
    const float* out_key_w   = (const float*)d_in[15];
    const float* out_query_w = (const float*)d_in[16];
    const float* key_norm_w  = (const float*)d_in[17];
    const float* q_ln_w      = (const float*)d_in[18];
    const float* q_ln_b      = (const float*)d_in[19];
    float* out = (float*)d_out;

    void *p_zx, *p_h0;
    void *p_hA1, *p_hW1, *p_hQ, *p_hWq, *p_hWo, *p_hWoq, *p_hXg, *p_hQn;
    cudaGetSymbolAddress(&p_zx, g_zx);
    cudaGetSymbolAddress(&p_h0, g_h0);
    cudaGetSymbolAddress(&p_hA1, g_hA1);
    cudaGetSymbolAddress(&p_hW1, g_hW1);
    cudaGetSymbolAddress(&p_hQ, g_hQ);
    cudaGetSymbolAddress(&p_hWq, g_hWq);
    cudaGetSymbolAddress(&p_hWo, g_hWo);
    cudaGetSymbolAddress(&p_hWoq, g_hWoq);
    cudaGetSymbolAddress(&p_hXg, g_hXg);
    cudaGetSymbolAddress(&p_hQn, g_hQn);

    cudaFuncSetAttribute(gemm_mma, cudaFuncAttributeMaxDynamicSharedMemorySize, DSMEM_G);
    cudaFuncSetAttribute(sgemm_s_kernel, cudaFuncAttributeMaxDynamicSharedMemorySize, DSMEM_SG);

    // #1: fused fp16 conversions + zeros
    {
        size_t n = ((size_t)BLT * DM + (size_t)NZ * DM + (size_t)BB * NK * DM
                    + (size_t)DI * DM + 2ull * DM * DI
                    + (size_t)BB * NK * DI + (size_t)BB * NK * DM) / 4;
        prep_all_kernel<<<(int)((n + 255) / 256), 256>>>(
            in_key, key_proj_w, in_query, query_proj_w, out_key_w, out_query_w,
            out + (size_t)BLT * DM);
    }
    // #2: zxbcdt = in_key @ key_proj_w^T  (fp16 MMA)
    {
        dim3 grid((NZ + 127) / 128, BLT / 128, 1);
        gemm_mma<<<grid, 128, DSMEM_G>>>((const __half*)p_hA1, (const __half*)p_hW1,
                                         (float*)p_zx, BLT, NZ, DM);
    }
    // #3: fused conv + dtbc
    convdtbc_kernel<<<CONV_BLKS + DTBC_BLKS, 256>>>(
        key_conv_w, key_conv_b, key_conv_bw, key_conv_bb,
        dist, bc_proj_w, dt_proj_w, dt_bias, A_log);
    // #4: w-prep (segment-parallel)
    wprep_kernel<<<512, 256>>>();
    // #5: x transpose (tf32)
    {
        dim3 grid(DI / 32, LL / 32, 2 * BB);
        xpose_kernel<<<grid, 256>>>();
    }
    // #6: S = w @ xT
    sgemm_s_kernel<<<512, 128, DSMEM_SG>>>();
    // #7: h0 = in_query @ query_proj_w^T, split-K x4 (fp16 MMA)
    {
        dim3 grid(DI / 128, 1, 4);
        gemm_mma<<<grid, 128, DSMEM_G>>>((const __half*)p_hQ, (const __half*)p_hWq,
                                         (float*)p_h0, BB * NK, DI, DM);
    }
    // #8: scan P2
    scan_p2<<<128, 256>>>();
    // #9: scan P3
    scan_p3<<<512, 128>>>();
    // #10: combine + gate + RMSNorm (fp16 out)
    gate_norm_key_kernel<<<BLT, 256>>>(D_param, key_norm_w);
    // #11: out_key = key_n @ out_key_w^T (fp16 MMA)
    {
        dim3 grid(DM / 128, BLT / 128, 1);
        gemm_mma<<<grid, 128, DSMEM_G>>>((const __half*)p_hXg, (const __half*)p_hWo,
                                         out, BLT, DM, DI);
    }
    // #12: query layer norm (fp16 out)
    qnorm_kernel<<<BB * NK, 256>>>(q_ln_w, q_ln_b);
    // #13: out_query = qn @ out_query_w^T, split-K x8 (fp16 MMA)
    {
        dim3 grid(DM / 128, 1, 8);
        gemm_mma<<<grid, 128, DSMEM_G>>>((const __half*)p_hQn, (const __half*)p_hWoq,
                                         out + (size_t)BLT * DM, BB * NK, DM, DI);
    }
}

// round 17
// speedup vs baseline: 1.7831x; 1.0064x over previous
#include <cuda_runtime.h>
#include <cuda_bf16.h>
#include <cuda_fp16.h>
#include <cstdint>

// ---------------- problem constants ----------------
#define BB 2
#define LL 2048
#define NK 64
#define DM 512
#define DI 1024
#define NH 8
#define PP 128
#define NZ 2058
#define CC 1026
#define BLT (BB*LL)
#define NCH 32
#define CHL 64
#define SEGL (CHL/4)

typedef unsigned long long ull;

// ---------------- scratch ----------------
__device__ float g_zx   [(size_t)BB*LL*NZ];
__device__ float g_convf[(size_t)BB*LL*CC];
__device__ float g_convb[(size_t)BB*LL*CC];
__device__ float g_dA   [(size_t)BB*NH*LL*NK];
__device__ float g_uf   [(size_t)BB*NH*LL*NK];
__device__ float g_ub   [(size_t)BB*NH*LL*NK];
__device__ float g_Cf   [(size_t)BB*LL*NK];
__device__ float g_Cb2  [(size_t)BB*LL*NK];
__device__ float g_h0   [(size_t)BB*NK*DI];
__device__ float g_yf   [(size_t)BB*LL*DI];
__device__ float g_yb   [(size_t)BB*LL*DI];
__device__ float g_hf   [(size_t)BB*NH*PP*NK];
__device__ float g_hb   [(size_t)BB*NH*PP*NK];
// chunked-scan intermediates
__device__ float g_Sf  [(size_t)16*NCH*NK*PP];   // [bh][c][n][p]
__device__ float g_Sb  [(size_t)16*NCH*NK*PP];
__device__ float g_P   [(size_t)16*NCH*NK];
__device__ float g_hsf [(size_t)16*NCH*PP*NK];   // [bh][c][p][n]
__device__ float g_hsb [(size_t)16*NCH*PP*NK];
__device__ float g_wf  [(size_t)16*NCH*NK*CHL];  // [bh][c][n][t], tf32
__device__ float g_wb  [(size_t)16*NCH*NK*CHL];
// fp16 copies of GEMM inputs
__device__ __half g_hA1 [(size_t)BLT*DM];
__device__ __half g_hW1 [(size_t)NZ*DM];
__device__ __half g_hQ  [(size_t)BB*NK*DM];
__device__ __half g_hWq [(size_t)DI*DM];
__device__ __half g_hWo [(size_t)DM*DI];
__device__ __half g_hWoq[(size_t)DM*DI];
__device__ __half g_hXg [(size_t)BB*LL*DI];
__device__ __half g_hQn [(size_t)BB*NK*DI];

// ---------------- helpers ----------------
__device__ __forceinline__ unsigned smem_u32(const void* p) {
    return (unsigned)__cvta_generic_to_shared(p);
}
__device__ __forceinline__ void cpasync16(unsigned s, const void* g) {
    asm volatile("cp.async.cg.shared.global [%0],[%1],16;\n" ::"r"(s), "l"(g));
}
__device__ __forceinline__ void cpasync16z(unsigned s, const void* g, unsigned srcsz) {
    asm volatile("cp.async.cg.shared.global [%0],[%1],16,%2;\n" ::"r"(s), "l"(g), "r"(srcsz));
}
__device__ __forceinline__ void cpasync8(unsigned s, const void* g) {
    asm volatile("cp.async.ca.shared.global [%0],[%1],8;\n" ::"r"(s), "l"(g));
}
__device__ __forceinline__ float to_tf32(float x) {
    float r; asm("cvt.rna.tf32.f32 %0,%1;" : "=f"(r) : "f"(x)); return r;
}
__device__ __forceinline__ uint32_t tf32b(float v) {
    uint32_t u; asm("cvt.rna.tf32.f32 %0,%1;" : "=r"(u) : "f"(v)); return u;
}
__device__ __forceinline__ void mma_tf32(float* c, const uint32_t* a, uint32_t b0, uint32_t b1) {
    asm volatile(
        "mma.sync.aligned.m16n8k8.row.col.f32.tf32.tf32.f32 "
        "{%0,%1,%2,%3}, {%4,%5,%6,%7}, {%8,%9}, {%0,%1,%2,%3};"
        : "+f"(c[0]), "+f"(c[1]), "+f"(c[2]), "+f"(c[3])
        : "r"(a[0]), "r"(a[1]), "r"(a[2]), "r"(a[3]), "r"(b0), "r"(b1));
}
__device__ __forceinline__ void mma_f16(float* c, const uint32_t* a, uint32_t b0, uint32_t b1) {
    asm volatile(
        "mma.sync.aligned.m16n8k16.row.col.f32.f16.f16.f32 "
        "{%0,%1,%2,%3}, {%4,%5,%6,%7}, {%8,%9}, {%0,%1,%2,%3};"
        : "+f"(c[0]), "+f"(c[1]), "+f"(c[2]), "+f"(c[3])
        : "r"(a[0]), "r"(a[1]), "r"(a[2]), "r"(a[3]), "r"(b0), "r"(b1));
}
__device__ __forceinline__ ull mul2(ull a, ull b) {
    ull d; asm("mul.rn.f32x2 %0,%1,%2;" : "=l"(d) : "l"(a), "l"(b)); return d;
}
__device__ __forceinline__ ull fma2(ull a, ull b, ull c) {
    ull d; asm("fma.rn.f32x2 %0,%1,%2,%3;" : "=l"(d) : "l"(a), "l"(b), "l"(c)); return d;
}
__device__ __forceinline__ ull pack2(float x, float y) {
    ull d; asm("mov.b64 %0,{%1,%2};" : "=l"(d) : "f"(x), "f"(y)); return d;
}
__device__ __forceinline__ void unpack2(ull v, float& x, float& y) {
    asm("mov.b64 {%0,%1},%2;" : "=f"(x), "=f"(y) : "l"(v));
}
__device__ __forceinline__ uint2 f4_to_h4(float4 v) {
    __half2 lo = __floats2half2_rn(v.x, v.y);
    __half2 hi = __floats2half2_rn(v.z, v.w);
    uint2 r;
    r.x = *(const unsigned*)&lo;
    r.y = *(const unsigned*)&hi;
    return r;
}

// ---------------- #1: fused fp16 conversions + zero accumulators ----------------
__global__ __launch_bounds__(256) void prep_all_kernel(
    const float* __restrict__ a1, const float* __restrict__ w1,
    const float* __restrict__ q,  const float* __restrict__ wq,
    const float* __restrict__ wo, const float* __restrict__ woq,
    float* __restrict__ outq)
{
    const size_t n1 = (size_t)BLT * DM / 4;
    const size_t n2 = n1 + (size_t)NZ * DM / 4;
    const size_t n3 = n2 + (size_t)BB * NK * DM / 4;
    const size_t n4 = n3 + (size_t)DI * DM / 4;
    const size_t n5 = n4 + (size_t)DM * DI / 4;
    const size_t n6 = n5 + (size_t)DM * DI / 4;
    const size_t n7 = n6 + (size_t)BB * NK * DI / 4;
    const size_t n8 = n7 + (size_t)BB * NK * DM / 4;
    size_t i = (size_t)blockIdx.x * 256 + threadIdx.x;
    if (i >= n8) return;
    if (i >= n6) {
        float4 z = make_float4(0.f, 0.f, 0.f, 0.f);
        if (i < n7) ((float4*)g_h0)[i - n6] = z;
        else        ((float4*)outq)[i - n7] = z;
        return;
    }
    const float* src; __half* dst; size_t off;
    if      (i < n1) { src = a1;  dst = g_hA1;  off = i; }
    else if (i < n2) { src = w1;  dst = g_hW1;  off = i - n1; }
    else if (i < n3) { src = q;   dst = g_hQ;   off = i - n2; }
    else if (i < n4) { src = wq;  dst = g_hWq;  off = i - n3; }
    else if (i < n5) { src = wo;  dst = g_hWo;  off = i - n4; }
    else             { src = woq; dst = g_hWoq; off = i - n5; }
    float4 v = ((const float4*)src)[off];
    ((uint2*)dst)[off] = f4_to_h4(v);
}

// ---------------- fp16 tensor-core GEMM (4 warps, 64x64 warp tile, 3-stage) ----------------
#define KCH 32
#define PADKH 40
#define STAGE_BH (128*PADKH*2)
#define CHUNK_BH (2*STAGE_BH)
#define DSMEM_G (3*CHUNK_BH)

__global__ __launch_bounds__(128, 2) void gemm_mma(const __half* __restrict__ A,
                                                   const __half* __restrict__ W,
                                                   float* __restrict__ C,
                                                   int M, int N, int K)
{
    extern __shared__ __align__(16) char dsm[];
    const int tid = threadIdx.x;
    const int lid = tid & 31, wrp = tid >> 5;
    const int wm = wrp & 1, wn = wrp >> 1;
    const int gid = lid >> 2, tig = lid & 3;
    const int m0 = blockIdx.y * 128, n0 = blockIdx.x * 128;
    const unsigned sbase = smem_u32(dsm);

    const int totCh = K >> 5;
    const int per = totCh / gridDim.z;
    const int cbase = blockIdx.z * per;
    const bool split = gridDim.z > 1;

    auto load_chunk = [&](int st, int ch) {
        const __half* Ap = A + (size_t)m0 * K + ch * KCH;
        const __half* Wp = W + (size_t)n0 * K + ch * KCH;
        unsigned ao = (unsigned)st * CHUNK_BH;
        unsigned bo = ao + STAGE_BH;
#pragma unroll
        for (int i = 0; i < 4; i++) {
            int idx = tid + i * 128;
            int row = idx >> 2, kg = idx & 3;
            unsigned so = (unsigned)(row * PADKH * 2 + kg * 16);
            cpasync16(sbase + ao + so, Ap + (size_t)row * K + kg * 8);
            int nrow = n0 + row;
            int cl = (nrow < N) ? nrow : (N - 1);
            cpasync16z(sbase + bo + so, Wp + (size_t)(cl - n0) * K + kg * 8,
                       (nrow < N) ? 16u : 0u);
        }
        asm volatile("cp.async.commit_group;\n" ::: "memory");
    };

    float acc[4][8][4];
#pragma unroll
    for (int mf = 0; mf < 4; mf++)
#pragma unroll
        for (int nf = 0; nf < 8; nf++)
#pragma unroll
            for (int i = 0; i < 4; i++) acc[mf][nf][i] = 0.f;

    load_chunk(0, cbase);
    if (per > 1) load_chunk(1, cbase + 1);

    int st = 0;
    for (int c = 0; c < per; c++) {
        if (c + 1 < per) asm volatile("cp.async.wait_group 1;\n" ::: "memory");
        else             asm volatile("cp.async.wait_group 0;\n" ::: "memory");
        __syncthreads();
        if (c + 2 < per) {
            int st2 = st + 2; if (st2 >= 3) st2 -= 3;
            load_chunk(st2, cbase + c + 2);
        }
        const __half* as = (const __half*)(dsm + st * CHUNK_BH);
        const __half* bs = (const __half*)(dsm + st * CHUNK_BH + STAGE_BH);
#pragma unroll
        for (int ks = 0; ks < 2; ks++) {
            int k0 = ks * 16;
            uint32_t af[4][4];
#pragma unroll
            for (int mf = 0; mf < 4; mf++) {
                int r = wm * 64 + mf * 16 + gid;
                af[mf][0] = *(const uint32_t*)&as[r * PADKH + k0 + 2 * tig];
                af[mf][1] = *(const uint32_t*)&as[(r + 8) * PADKH + k0 + 2 * tig];
                af[mf][2] = *(const uint32_t*)&as[r * PADKH + k0 + 2 * tig + 8];
                af[mf][3] = *(const uint32_t*)&as[(r + 8) * PADKH + k0 + 2 * tig + 8];
            }
#pragma unroll
            for (int nf = 0; nf < 8; nf++) {
                int nr = wn * 64 + nf * 8 + gid;
                uint32_t b0 = *(const uint32_t*)&bs[nr * PADKH + k0 + 2 * tig];
                uint32_t b1 = *(const uint32_t*)&bs[nr * PADKH + k0 + 2 * tig + 8];
#pragma unroll
                for (int mf = 0; mf < 4; mf++)
                    mma_f16(acc[mf][nf], af[mf], b0, b1);
            }
        }
        if (++st >= 3) st = 0;
    }

#pragma unroll
    for (int mf = 0; mf < 4; mf++) {
        int r0 = m0 + wm * 64 + mf * 16 + gid;
#pragma unroll
        for (int nf = 0; nf < 8; nf++) {
            int col = n0 + wn * 64 + nf * 8 + tig * 2;
            if (col < N) {
                float* p0 = &C[(size_t)r0 * N + col];
                float* p1 = &C[(size_t)(r0 + 8) * N + col];
                if (!split) {
                    *(float2*)p0 = make_float2(acc[mf][nf][0], acc[mf][nf][1]);
                    *(float2*)p1 = make_float2(acc[mf][nf][2], acc[mf][nf][3]);
                } else {
                    atomicAdd(p0,     acc[mf][nf][0]);
                    atomicAdd(p0 + 1, acc[mf][nf][1]);
                    atomicAdd(p1,     acc[mf][nf][2]);
                    atomicAdd(p1 + 1, acc[mf][nf][3]);
                }
            }
        }
    }
}

// ---------------- #3: fused conv + dtbc ----------------
#define CONV_BLKS (((CC + 255) / 256) * (LL / 8) * (2 * BB))
#define DTBC_BLKS (BLT / 4)

__global__ __launch_bounds__(256) void convdtbc_kernel(
    const float* __restrict__ cwf, const float* __restrict__ cbf,
    const float* __restrict__ cwb, const float* __restrict__ cbb,
    const float* __restrict__ dist, const float* __restrict__ bcw,
    const float* __restrict__ dtw, const float* __restrict__ dt_bias,
    const float* __restrict__ A_log)
{
    int bid = blockIdx.x;
    int tid = threadIdx.x;
    if (bid < CONV_BLKS) {
        int cblk = bid % 5;
        int rest = bid / 5;
        int l0 = (rest & 255) * 8;
        int db = rest >> 8;
        int dir = db >> 1, b = db & 1;
        int c = cblk * 256 + tid;
        if (c >= CC) return;

        const float* wsrc = (dir ? cwb : cwf) + c * 7;
        float wr[7];
#pragma unroll
        for (int t = 0; t < 7; t++) wr[t] = wsrc[t];
        float bias = (dir ? cbb : cbf)[c];

        const float* src = g_zx + (size_t)b * LL * NZ + DI + c;
        float win[14];
#pragma unroll
        for (int i = 0; i < 14; i++) {
            int l = l0 - 3 + i;
            win[i] = (0 <= l && l < LL) ? src[(size_t)l * NZ] : 0.f;
        }
        float* dst = (dir ? g_convb : g_convf) + ((size_t)b * LL + l0) * CC + c;
#pragma unroll
        for (int j = 0; j < 8; j++) {
            float acc = bias;
#pragma unroll
            for (int t = 0; t < 7; t++) acc = fmaf(wr[t], win[j + t], acc);
            float sig = 1.f / (1.f + __expf(-acc));
            dst[(size_t)j * CC] = acc * sig;
        }
        return;
    }
    {
        int bl = (bid - CONV_BLKS) * 4 + (tid >> 6);
        int b = bl / LL, l = bl % LL;
        int k = tid & 63;

        float resf[2], resb[2];
        const float* zsrc = g_zx + (size_t)b * LL * NZ + 2 * DI;
#pragma unroll
        for (int ch = 0; ch < 2; ch++) {
            float af = cbf[1024 + ch], ab = cbb[1024 + ch];
#pragma unroll
            for (int t = 0; t < 7; t++) {
                int l2 = l + t - 3;
                if (0 <= l2 && l2 < LL) {
                    float v = zsrc[(size_t)l2 * NZ + ch];
                    af = fmaf(cwf[(1024 + ch) * 7 + t], v, af);
                    ab = fmaf(cwb[(1024 + ch) * 7 + t], v, ab);
                }
            }
            resf[ch] = af * (1.f / (1.f + __expf(-af)));
            resb[ch] = ab * (1.f / (1.f + __expf(-ab)));
        }
        float bbf = resf[0], cbfv = resf[1], bbb = resb[0], cbbv = resb[1];

        float4 d4 = *(const float4*)&dist[((size_t)bl * NK + k) * 4];
        float bb = d4.x * bcw[0] + d4.y * bcw[1] + d4.z * bcw[2] + d4.w * bcw[3];
        float cb = d4.x * bcw[4] + d4.y * bcw[5] + d4.z * bcw[6] + d4.w * bcw[7];
        g_Cf [(size_t)bl * NK + k] = cb + cbfv;
        g_Cb2[(size_t)bl * NK + k] = cb + cbbv;
        float Bf = bb + bbf, Bbk = bb + bbb;
        size_t zoff = (size_t)bl * NZ + 2 * DI + 2;
#pragma unroll
        for (int h = 0; h < NH; h++) {
            float pre = d4.x * dtw[h * 4 + 0] + d4.y * dtw[h * 4 + 1]
                      + d4.z * dtw[h * 4 + 2] + d4.w * dtw[h * 4 + 3]
                      + g_zx[zoff + h] + dt_bias[h];
            float dt = (pre > 20.f) ? pre : log1pf(__expf(pre));
            float Ah = -__expf(A_log[h]);
            float dA = __expf(dt * Ah);
            size_t o = (((size_t)(b * NH + h) * LL) + l) * NK + k;
            g_dA[o] = dA;
            g_uf[o] = dt * Bf;
            g_ub[o] = dt * Bbk;
        }
    }
}

// ---------------- #4: w-prep (segment-parallel, CHL=64, SEGL=16) ----------------
// 1024 blocks: bh(16) x c(32) x dir(2); 256 threads = seg(4) x n(64).
__global__ __launch_bounds__(256) void wprep_kernel()
{
    __shared__ float sp[4][64];
    int bid = blockIdx.x;
    int dir = bid & 1;
    int c   = (bid >> 1) & (NCH - 1);
    int bh  = bid >> 6;
    int n   = threadIdx.x & 63;
    int seg = threadIdx.x >> 6;
    const int t0 = seg * SEGL;

    const float* dA = g_dA + ((size_t)bh * LL + (size_t)c * CHL) * NK + n;
    const float* uu = (dir ? g_ub : g_uf) + ((size_t)bh * LL + (size_t)c * CHL) * NK + n;
    float* w = (dir ? g_wb : g_wf) + (((size_t)bh * NCH + c) * NK + n) * CHL;

    float spv = 1.f;
#pragma unroll 8
    for (int t = 0; t < SEGL; t++) spv *= dA[(size_t)(t0 + t) * NK];
    sp[seg][n] = spv;
    __syncthreads();

    if (dir == 0) {
        float F = 1.f;
#pragma unroll
        for (int s = 1; s < 4; s++) if (s > seg) F *= sp[s][n];
        float run = F;
        float buf[4];
#pragma unroll 4
        for (int t = SEGL - 1; t >= 0; t--) {
            int tt = t0 + t;
            buf[t & 3] = to_tf32(run * uu[(size_t)tt * NK]);
            run *= dA[(size_t)tt * NK];
            if ((t & 3) == 0)
                *(float4*)&w[tt] = make_float4(buf[0], buf[1], buf[2], buf[3]);
        }
        if (seg == 0)
            g_P[((size_t)bh * NCH + c) * NK + n] =
                sp[0][n] * sp[1][n] * sp[2][n] * sp[3][n];
    } else {
        float F = 1.f;
#pragma unroll
        for (int s = 0; s < 3; s++) if (s < seg) F *= sp[s][n];
        float run = F;
        float buf[4];
#pragma unroll 4
        for (int t = 0; t < SEGL; t++) {
            int tt = t0 + t;
            buf[t & 3] = to_tf32(run * uu[(size_t)tt * NK]);
            run *= dA[(size_t)tt * NK];
            if ((t & 3) == 3)
                *(float4*)&w[tt - 3] = make_float4(buf[0], buf[1], buf[2], buf[3]);
        }
    }
}

// ---------------- #5: S[n][p] = sum_t w[n][t] * x[t][p], x read直 from g_conv ----------------
#define PADT 36
#define PADP 132
#define SGW_F (64*PADT)       // 2304 floats
#define SGX_F (32*PADP)       // 4224 floats
#define SGSTG_F (SGW_F + SGX_F)
#define DSMEM_SG (2*SGSTG_F*4)     // 52224 B

__global__ __launch_bounds__(128, 4) void sgemm_s_kernel()
{
    extern __shared__ __align__(16) float sms[];
    int bid = blockIdx.x;            // c(32) x bh(16) x dir(2)
    int c   = bid & (NCH - 1);
    int bh  = (bid >> 5) & 15;
    int dir = bid >> 9;
    int b = bh >> 3, h = bh & 7;
    int tid = threadIdx.x, lid = tid & 31, wp = tid >> 5;
    int gid = lid >> 2, tig = lid & 3;

    const float* wsrc = (dir ? g_wb : g_wf) + ((size_t)bh * NCH + c) * NK * CHL;
    const float* gx = (dir ? g_convb : g_convf)
                    + ((size_t)b * LL + (size_t)c * CHL) * CC + h * PP;
    float* S = (dir ? g_Sb : g_Sf) + ((size_t)bh * NCH + c) * NK * PP;

    const int NKT = CHL / 32;   // 2 stages of 32 t

    auto load = [&](int st, int kt) {
        float* dw = sms + st * SGSTG_F;
        float* dx = dw + SGW_F;
#pragma unroll
        for (int i = 0; i < 4; i++) {          // w: 64 n-rows x 8 float4 (32 t)
            int idx = tid + i * 128;
            int row = idx >> 3, kg = idx & 7;
            cpasync16(smem_u32(&dw[row * PADT + kg * 4]),
                      wsrc + (size_t)row * CHL + kt * 32 + kg * 4);
        }
        // x: 32 t-rows x 128 p; global rows only 8B-aligned -> cpasync8
#pragma unroll
        for (int i = 0; i < 16; i++) {
            int idx = tid + i * 128;
            int row = idx >> 6, c8 = idx & 63;
            cpasync8(smem_u32(&dx[row * PADP + c8 * 2]),
                     gx + (size_t)(kt * 32 + row) * CC + c8 * 2);
        }
        asm volatile("cp.async.commit_group;\n" ::: "memory");
    };

    float acc[4][4][4];
#pragma unroll
    for (int mf = 0; mf < 4; mf++)
#pragma unroll
        for (int nf = 0; nf < 4; nf++)
#pragma unroll
            for (int i = 0; i < 4; i++) acc[mf][nf][i] = 0.f;

    load(0, 0);
    load(1, 1);
    for (int kt = 0; kt < NKT; kt++) {
        if (kt + 1 < NKT) asm volatile("cp.async.wait_group 1;\n" ::: "memory");
        else              asm volatile("cp.async.wait_group 0;\n" ::: "memory");
        __syncthreads();
        const float* dw = sms + (kt & 1) * SGSTG_F;
        const float* dx = dw + SGW_F;
#pragma unroll
        for (int kf = 0; kf < 4; kf++) {
            int k0 = kf * 8;
            uint32_t af[4][4];
#pragma unroll
            for (int mf = 0; mf < 4; mf++) {
                int r = mf * 16 + gid;
                af[mf][0] = __float_as_uint(dw[r * PADT + k0 + tig]);
                af[mf][1] = __float_as_uint(dw[(r + 8) * PADT + k0 + tig]);
                af[mf][2] = __float_as_uint(dw[r * PADT + k0 + tig + 4]);
                af[mf][3] = __float_as_uint(dw[(r + 8) * PADT + k0 + tig + 4]);
            }
#pragma unroll
            for (int nf = 0; nf < 4; nf++) {
                int pr = wp * 32 + nf * 8 + gid;
                uint32_t b0 = tf32b(dx[(k0 + tig) * PADP + pr]);
                uint32_t b1 = tf32b(dx[(k0 + tig + 4) * PADP + pr]);
#pragma unroll
                for (int mf = 0; mf < 4; mf++)
                    mma_tf32(acc[mf][nf], af[mf], b0, b1);
            }
        }
        __syncthreads();
        if (kt + 2 < NKT) load(kt & 1, kt + 2);
    }

#pragma unroll
    for (int mf = 0; mf < 4; mf++) {
        int r0 = mf * 16 + gid;
#pragma unroll
        for (int nf = 0; nf < 4; nf++) {
            int col = wp * 32 + nf * 8 + tig * 2;
            *(float2*)&S[(size_t)r0 * PP + col] =
                make_float2(acc[mf][nf][0], acc[mf][nf][1]);
            *(float2*)&S[(size_t)(r0 + 8) * PP + col] =
                make_float2(acc[mf][nf][2], acc[mf][nf][3]);
        }
    }
}

// ---------------- P2: chunk combine (S in [n][p], NCH=32) ----------------
__global__ __launch_bounds__(256) void scan_p2()
{
    int bid = blockIdx.x;
    int pblk = bid & 7, bh = bid >> 3;
    int b = bh >> 3, h = bh & 7;
    int tid = threadIdx.x;
    int q = tid & 15, pl = tid >> 4;
    int p = pblk * 16 + pl;

    ull h01, h23;
    {
        const float* hp = g_h0 + (size_t)b * NK * DI + h * PP + p;
        h01 = pack2(hp[(size_t)(4 * q + 0) * DI], hp[(size_t)(4 * q + 1) * DI]);
        h23 = pack2(hp[(size_t)(4 * q + 2) * DI], hp[(size_t)(4 * q + 3) * DI]);
    }
    {
        ull a01 = h01, a23 = h23;
        for (int c = 0; c < NCH; c++) {
            size_t ho = (((size_t)bh * NCH + c) * PP + p) * NK + 4 * q;
            *(ulonglong2*)&g_hsf[ho] = make_ulonglong2(a01, a23);
            ulonglong2 P2 = *(const ulonglong2*)&g_P[((size_t)bh * NCH + c) * NK + 4 * q];
            size_t sb = (((size_t)bh * NCH + c) * NK + 4 * q) * PP + p;
            ull S01 = pack2(g_Sf[sb], g_Sf[sb + PP]);
            ull S23 = pack2(g_Sf[sb + 2 * PP], g_Sf[sb + 3 * PP]);
            a01 = fma2(P2.x, a01, S01);
            a23 = fma2(P2.y, a23, S23);
        }
        float f0, f1, f2, f3;
        unpack2(a01, f0, f1); unpack2(a23, f2, f3);
        float* gh = g_hf + ((size_t)bh * PP + p) * NK + 4 * q;
        gh[0] = f0; gh[1] = f1; gh[2] = f2; gh[3] = f3;
    }
    {
        ull a01 = h01, a23 = h23;
        for (int c = NCH - 1; c >= 0; c--) {
            size_t ho = (((size_t)bh * NCH + c) * PP + p) * NK + 4 * q;
            *(ulonglong2*)&g_hsb[ho] = make_ulonglong2(a01, a23);
            ulonglong2 P2 = *(const ulonglong2*)&g_P[((size_t)bh * NCH + c) * NK + 4 * q];
            size_t sb = (((size_t)bh * NCH + c) * NK + 4 * q) * PP + p;
            ull S01 = pack2(g_Sb[sb], g_Sb[sb + PP]);
            ull S23 = pack2(g_Sb[sb + 2 * PP], g_Sb[sb + 3 * PP]);
            a01 = fma2(P2.x, a01, S01);
            a23 = fma2(P2.y, a23, S23);
        }
        float f0, f1, f2, f3;
        unpack2(a01, f0, f1); unpack2(a23, f2, f3);
        float* gh = g_hb + ((size_t)bh * PP + p) * NK + 4 * q;
        gh[0] = f0; gh[1] = f1; gh[2] = f2; gh[3] = f3;
    }
}

// ---------------- P3: within-chunk scan + y (CHL=64: 4 tiles of 16) ----------------
#define T3_DA 0
#define T3_U  2048
#define T3_C  4096
#define T3_X  6144
__global__ __launch_bounds__(128, 4) void scan_p3()
{
    __shared__ __align__(16) float sm3[10240];
    int bid = blockIdx.x;            // c(32) x bh(16) x dir(2)
    int c   = bid & (NCH - 1);
    int bh  = (bid >> 5) & 15;
    int dir = bid >> 9;
    int b = bh >> 3, h = bh & 7;
    int tid = threadIdx.x;

    const float* gdA = g_dA + ((size_t)bh * LL + (size_t)c * CHL) * NK;
    const float* gu  = (dir ? g_ub : g_uf) + ((size_t)bh * LL + (size_t)c * CHL) * NK;
    const float* gC  = (dir ? g_Cb2 : g_Cf) + ((size_t)b * LL + (size_t)c * CHL) * NK;
    const float* gx  = (dir ? g_convb : g_convf)
                     + ((size_t)b * LL + (size_t)c * CHL) * CC + h * PP;
    float* gy = (dir ? g_yb : g_yf)
              + ((size_t)b * LL + (size_t)c * CHL) * DI + h * PP + tid;

    ull hh[32];
    {
        const float* hs = (dir ? g_hsb : g_hsf)
                        + (((size_t)bh * NCH + c) * PP + tid) * NK;
#pragma unroll
        for (int i = 0; i < 16; i++) {
            ulonglong2 v = *(const ulonglong2*)&hs[i * 4];
            hh[2 * i] = v.x; hh[2 * i + 1] = v.y;
        }
    }

    const int NT = CHL / 16;   // 4 tiles

    auto load_tile = [&](int buf, int tile) {
        const float* da = gdA + (size_t)tile * 16 * NK;
        const float* uu = gu + (size_t)tile * 16 * NK;
        const float* cc = gC + (size_t)tile * 16 * NK;
        cpasync16(smem_u32(&sm3[T3_DA + buf * 1024 + tid * 8]),     da + tid * 8);
        cpasync16(smem_u32(&sm3[T3_DA + buf * 1024 + tid * 8 + 4]), da + tid * 8 + 4);
        cpasync16(smem_u32(&sm3[T3_U  + buf * 1024 + tid * 8]),     uu + tid * 8);
        cpasync16(smem_u32(&sm3[T3_U  + buf * 1024 + tid * 8 + 4]), uu + tid * 8 + 4);
        cpasync16(smem_u32(&sm3[T3_C  + buf * 1024 + tid * 8]),     cc + tid * 8);
        cpasync16(smem_u32(&sm3[T3_C  + buf * 1024 + tid * 8 + 4]), cc + tid * 8 + 4);
#pragma unroll
        for (int i = 0; i < 4; i++) {
            int idx = tid + i * 128;
            int row = idx >> 5, c4 = idx & 31;
            const float* xs = gx + (size_t)(tile * 16 + row) * CC + c4 * 4;
            unsigned sd = smem_u32(&sm3[T3_X + buf * 2048 + row * 128 + c4 * 4]);
            cpasync8(sd, xs);
            cpasync8(sd + 8, xs + 2);
        }
        asm volatile("cp.async.commit_group;\n");
    };

    load_tile(0, dir ? NT - 1 : 0);
    for (int s = 0; s < NT; s++) {
        if (s + 1 < NT) {
            load_tile((s + 1) & 1, dir ? NT - 2 - s : s + 1);
            asm volatile("cp.async.wait_group 1;\n");
        } else {
            asm volatile("cp.async.wait_group 0;\n");
        }
        __syncthreads();
        int buf = s & 1;
        int tile = dir ? NT - 1 - s : s;
#pragma unroll 2
        for (int j = 0; j < 16; j++) {
            int tt = dir ? (15 - j) : j;
            float xp = sm3[T3_X + buf * 2048 + tt * 128 + tid];
            ull xx = pack2(xp, xp);
            const float* da = &sm3[T3_DA + buf * 1024 + tt * 64];
            const float* uu = &sm3[T3_U  + buf * 1024 + tt * 64];
            const float* cv = &sm3[T3_C  + buf * 1024 + tt * 64];
            ull acc0 = 0, acc1 = 0, acc2 = 0, acc3 = 0;
#pragma unroll
            for (int i = 0; i < 16; i++) {
                ulonglong2 av = *(const ulonglong2*)&da[i * 4];
                ulonglong2 uv = *(const ulonglong2*)&uu[i * 4];
                ulonglong2 c2 = *(const ulonglong2*)&cv[i * 4];
                hh[2 * i]     = fma2(av.x, hh[2 * i],     mul2(uv.x, xx));
                hh[2 * i + 1] = fma2(av.y, hh[2 * i + 1], mul2(uv.y, xx));
                if (i & 1) {
                    acc2 = fma2(c2.x, hh[2 * i], acc2);
                    acc3 = fma2(c2.y, hh[2 * i + 1], acc3);
                } else {
                    acc0 = fma2(c2.x, hh[2 * i], acc0);
                    acc1 = fma2(c2.y, hh[2 * i + 1], acc1);
                }
            }
            float a, bq, cq, d, e, f, g2, h2;
            unpack2(acc0, a, bq); unpack2(acc1, cq, d);
            unpack2(acc2, e, f);  unpack2(acc3, g2, h2);
            float y = ((a + bq) + (cq + d)) + ((e + f) + (g2 + h2));
            gy[(size_t)(tile * 16 + tt) * DI] = y;
        }
        __syncthreads();
    }
}

// ---------------- combine y, gate with silu(z), RMSNorm (fp16 out) ----------------
__global__ __launch_bounds__(256) void gate_norm_key_kernel(const float* __restrict__ Dp,
                                                            const float* __restrict__ normw)
{
    int bl = blockIdx.x;
    int tid = threadIdx.x;
    __shared__ float s_v[DI];
    __shared__ float sred[9];
    float ss = 0.f;
    size_t byDI = (size_t)bl * DI, byCC = (size_t)bl * CC, byNZ = (size_t)bl * NZ;
#pragma unroll
    for (int it = 0; it < 4; it++) {
        int i = tid + it * 256;
        int hh = i >> 7;
        float y = 0.5f * (g_yf[byDI + i] + g_yb[byDI + i])
                + 0.5f * Dp[hh] * (g_convf[byCC + i] + g_convb[byCC + i]);
        float z = g_zx[byNZ + i];
        float xg = y * z * (1.f / (1.f + __expf(-z)));
        s_v[i] = xg;
        ss += xg * xg;
    }
    for (int o = 16; o; o >>= 1) ss += __shfl_xor_sync(0xffffffffu, ss, o);
    if ((tid & 31) == 0) sred[tid >> 5] = ss;
    __syncthreads();
    if (tid == 0) {
        float t = 0.f;
        for (int w = 0; w < 8; w++) t += sred[w];
        sred[8] = rsqrtf(t * (1.f / DI) + 1e-5f);
    }
    __syncthreads();
    float sc = sred[8];
#pragma unroll
    for (int it = 0; it < 2; it++) {
        int i = tid * 2 + it * 512;
        __half2 hv = __floats2half2_rn(s_v[i] * sc * normw[i],
                                       s_v[i + 1] * sc * normw[i + 1]);
        *(__half2*)&g_hXg[byDI + i] = hv;
    }
}

// ---------------- query path: LayerNorm (fp16 out) ----------------
__global__ __launch_bounds__(256) void qnorm_kernel(const float* __restrict__ w,
                                                    const float* __restrict__ bi)
{
    int bk = blockIdx.x;
    int b = bk >> 6, k = bk & 63;
    int tid = threadIdx.x;
    __shared__ float s_v[DI];
    __shared__ float sred[18];
    float s1 = 0.f, s2 = 0.f;
#pragma unroll
    for (int it = 0; it < 4; it++) {
        int i = tid + it * 256;
        int hh = i >> 7, p = i & 127;
        size_t o = ((size_t)(b * NH + hh) * PP + p) * NK + k;
        float qv = 0.5f * (g_hf[o] + g_hb[o]);
        s_v[i] = qv;
        s1 += qv;
        s2 += qv * qv;
    }
    for (int o = 16; o; o >>= 1) {
        s1 += __shfl_xor_sync(0xffffffffu, s1, o);
        s2 += __shfl_xor_sync(0xffffffffu, s2, o);
    }
    if ((tid & 31) == 0) { sred[tid >> 5] = s1; sred[8 + (tid >> 5)] = s2; }
    __syncthreads();
    if (tid == 0) {
        float t1 = 0.f, t2 = 0.f;
        for (int wv = 0; wv < 8; wv++) { t1 += sred[wv]; t2 += sred[8 + wv]; }
        float mu = t1 * (1.f / DI);
        float var = t2 * (1.f / DI) - mu * mu;
        sred[16] = mu;
        sred[17] = rsqrtf(var + 1e-5f);
    }
    __syncthreads();
    float mu = sred[16], rs = sred[17];
#pragma unroll
    for (int it = 0; it < 2; it++) {
        int i = tid * 2 + it * 512;
        __half2 hv = __floats2half2_rn((s_v[i] - mu) * rs * w[i] + bi[i],
                                       (s_v[i + 1] - mu) * rs * w[i + 1] + bi[i + 1]);
        *(__half2*)&g_hQn[(size_t)bk * DI + i] = hv;
    }
}

// ---------------- host launcher ----------------
extern "C" void kernel_launch(void* const* d_in, const int* in_sizes, int n_in,
                              void* d_out, int out_size)
{
    (void)in_sizes; (void)n_in; (void)out_size;
    const float* in_key      = (const float*)d_in[0];
    const float* in_query    = (const float*)d_in[1];
    const float* dist        = (const float*)d_in[2];
    const float* key_proj_w  = (const float*)d_in[4];
    const float* key_conv_w  = (const float*)d_in[5];
    const float* key_conv_b  = (const float*)d_in[6];
    const float* key_conv_bw = (const float*)d_in[7];
    const float* key_conv_bb = (const float*)d_in[8];
    const float* query_proj_w= (const float*)d_in[9];
    const float* bc_proj_w   = (const float*)d_in[10];
    const float* dt_proj_w   = (const float*)d_in[11];
    const float* dt_bias     = (const float*)d_in[12];
    const float* A_log       = (const float*)d_in[13];
    const float* D_param     = (const float*)d_in[14];
    const float* out_key_w   = (const float*)d_in[15];
    const float* out_query_w = (const float*)d_in[16];
    const float* key_norm_w  = (const float*)d_in[17];
    const float* q_ln_w      = (const float*)d_in[18];
    const float* q_ln_b      = (const float*)d_in[19];
    float* out = (float*)d_out;

    void *p_zx, *p_h0;
    void *p_hA1, *p_hW1, *p_hQ, *p_hWq, *p_hWo, *p_hWoq, *p_hXg, *p_hQn;
    cudaGetSymbolAddress(&p_zx, g_zx);
    cudaGetSymbolAddress(&p_h0, g_h0);
    cudaGetSymbolAddress(&p_hA1, g_hA1);
    cudaGetSymbolAddress(&p_hW1, g_hW1);
    cudaGetSymbolAddress(&p_hQ, g_hQ);
    cudaGetSymbolAddress(&p_hWq, g_hWq);
    cudaGetSymbolAddress(&p_hWo, g_hWo);
    cudaGetSymbolAddress(&p_hWoq, g_hWoq);
    cudaGetSymbolAddress(&p_hXg, g_hXg);
    cudaGetSymbolAddress(&p_hQn, g_hQn);

    cudaFuncSetAttribute(gemm_mma, cudaFuncAttributeMaxDynamicSharedMemorySize, DSMEM_G);
    cudaFuncSetAttribute(sgemm_s_kernel, cudaFuncAttributeMaxDynamicSharedMemorySize, DSMEM_SG);

    // #1: fused fp16 conversions + zeros
    {
        size_t n = ((size_t)BLT * DM + (size_t)NZ * DM + (size_t)BB * NK * DM
                    + (size_t)DI * DM + 2ull * DM * DI
                    + (size_t)BB * NK * DI + (size_t)BB * NK * DM) / 4;
        prep_all_kernel<<<(int)((n + 255) / 256), 256>>>(
            in_key, key_proj_w, in_query, query_proj_w, out_key_w, out_query_w,
            out + (size_t)BLT * DM);
    }
    // #2: zxbcdt = in_key @ key_proj_w^T  (fp16 MMA)
    {
        dim3 grid((NZ + 127) / 128, BLT / 128, 1);
        gemm_mma<<<grid, 128, DSMEM_G>>>((const __half*)p_hA1, (const __half*)p_hW1,
                                         (float*)p_zx, BLT, NZ, DM);
    }
    // #3: fused conv + dtbc
    convdtbc_kernel<<<CONV_BLKS + DTBC_BLKS, 256>>>(
        key_conv_w, key_conv_b, key_conv_bw, key_conv_bb,
        dist, bc_proj_w, dt_proj_w, dt_bias, A_log);
    // #4: w-prep
    wprep_kernel<<<16 * NCH * 2, 256>>>();
    // #5: S = w @ x (x direct from g_conv)
    sgemm_s_kernel<<<16 * NCH * 2, 128, DSMEM_SG>>>();
    // #6: h0 = in_query @ query_proj_w^T, split-K x4 (fp16 MMA)
    {
        dim3 grid(DI / 128, 1, 4);
        gemm_mma<<<grid, 128, DSMEM_G>>>((const __half*)p_hQ, (const __half*)p_hWq,
                                         (float*)p_h0, BB * NK, DI, DM);
    }
    // #7: scan P2
    scan_p2<<<128, 256>>>();
    // #8: scan P3
    scan_p3<<<16 * NCH * 2, 128>>>();
    // #9: combine + gate + RMSNorm (fp16 out)
    gate_norm_key_kernel<<<BLT, 256>>>(D_param, key_norm_w);
    // #10: out_key = key_n @ out_key_w^T (fp16 MMA)
    {
        dim3 grid(DM / 128, BLT / 128, 1);
        gemm_mma<<<grid, 128, DSMEM_G>>>((const __half*)p_hXg, (const __half*)p_hWo,
                                         out, BLT, DM, DI);
    }
    // #11: query layer norm (fp16 out)
    qnorm_kernel<<<BB * NK, 256>>>(q_ln_w, q_ln_b);
    // #12: out_query = qn @ out_query_w^T, split-K x8 (fp16 MMA)
    {
        dim3 grid(DM / 128, 1, 8);
        gemm_mma<<<grid, 128, DSMEM_G>>>((const __half*)p_hQn, (const __half*)p_hWoq,
                                         out + (size_t)BLT * DM, BB * NK, DM, DI);
    }
}